// round 4
// baseline (speedup 1.0000x reference)
#include <cuda_runtime.h>
#include <cuda_bf16.h>
#include <cstdint>

#define NS   524288
#define DIM  128
#define BG   128
#define HH   64
#define KK_  4
#define BH   (BG * HH)
#define NK   (NS * KK_)
#define HUBF_ELEMS (BH * DIM)

#define TILES_PER_CTA 4
#define FFN_GRID (NS / 64 / TILES_PER_CTA)   /* 2048 */

// fixed activation quant scales (clamp >=10 sigma, never hit)
#define XQ_SCALE   4000.0f          /* q = x * 4000, |x|<=8  */
#define XQ_INV     (8.0f / 32000.0f)
#define HQ_SCALE   (32000.0f / 6.0f)
#define HQ_INV     (6.0f / 32000.0f)

// FFN output scratch
__device__ float g_hbuf[(size_t)NS * DIM];

// int8 weights, transposed [n][k], hi/lo split, XOR-swizzled
__device__ signed char gW1q[2 * 256 * 128];           // [split][n256][k128] 64KB
__device__ signed char gW2q[4 * 2 * 128 * 64];        // [slab][split][n128][k64] 64KB
__device__ float g_sw1[256];
__device__ float g_sw2[128];

// SMEM layout (112KB -> 2 CTAs/SM)
#define OFF_W1H 0
#define OFF_W1L 32768
#define OFF_XH  65536      /* [64][128]B  */
#define OFF_XL  73728
#define OFF_W2H 65536      /* slab reuses x region after GEMM1 */
#define OFF_W2L 73728
#define OFF_H1H 81920      /* [64][256]B  */
#define OFF_H1L 98304
#define FFN_SMEM 114688

// ---------------------------------------------------------------------------
__device__ __forceinline__ uint32_t smem_u32(const void* p) {
    uint32_t a;
    asm("{ .reg .u64 t; cvta.to.shared.u64 t, %1; cvt.u32.u64 %0, t; }" : "=r"(a) : "l"(p));
    return a;
}
__device__ __forceinline__ void ldsm4(uint32_t addr, uint32_t r[4]) {
    asm volatile("ldmatrix.sync.aligned.m8n8.x4.shared.b16 {%0,%1,%2,%3}, [%4];"
                 : "=r"(r[0]), "=r"(r[1]), "=r"(r[2]), "=r"(r[3]) : "r"(addr));
}
__device__ __forceinline__ void imma(int c[4], const uint32_t a[4], uint32_t b0, uint32_t b1) {
    asm volatile("mma.sync.aligned.m16n8k32.row.col.s32.s8.s8.s32 "
                 "{%0,%1,%2,%3}, {%4,%5,%6,%7}, {%8,%9}, {%0,%1,%2,%3};"
                 : "+r"(c[0]), "+r"(c[1]), "+r"(c[2]), "+r"(c[3])
                 : "r"(a[0]), "r"(a[1]), "r"(a[2]), "r"(a[3]), "r"(b0), "r"(b1));
}
// A ldmatrix address: 16 rows x 32 k-bytes at (m0, kb); row-major, swizzle mask 7
__device__ __forceinline__ uint32_t a_addr(uint32_t base, int stride, int m0, int kb, int lane) {
    int row = m0 + (lane & 15);
    int k = kb + ((lane >> 4) << 4);
    return base + row * stride + (uint32_t)(k ^ ((row & 7) << 4));
}
// B ldmatrix address: 16 n-rows x 32 k-bytes at (n0, kb); swizzle mask param
__device__ __forceinline__ uint32_t b_addr(uint32_t base, int stride, int n0, int kb, int lane, int msk) {
    int row = n0 + (lane & 7) + ((lane & 16) >> 1);
    int k = kb + (((lane >> 3) & 1) << 4);
    return base + row * stride + (uint32_t)(k ^ ((row & msk) << 4));
}
__device__ __forceinline__ float gelu_exact(float v) {
    return 0.5f * v * (1.0f + erff(v * 0.7071067811865476f));
}
// split integer-valued float q into qh*256+ql, ql in [-128,127]
__device__ __forceinline__ void split16(float q, int& ih, int& il) {
    float qh = floorf(q * (1.0f / 256.0f) + 0.5f);
    ih = (int)qh;
    il = (int)(q - qh * 256.0f);
}
__device__ __forceinline__ uint32_t pack4(int b0, int b1, int b2, int b3) {
    return (uint32_t)(b0 & 255) | ((uint32_t)(b1 & 255) << 8) |
           ((uint32_t)(b2 & 255) << 16) | ((uint32_t)(b3 & 255) << 24);
}

// ---------------------------------------------------------------------------
// prep 1: per-column scales
// ---------------------------------------------------------------------------
__global__ void prep_scales(const float* __restrict__ W1, const float* __restrict__ W2) {
    int t = threadIdx.x;
    if (t < 256) {
        float m = 0.f;
        for (int k = 0; k < 128; k++) m = fmaxf(m, fabsf(W1[k * 256 + t]));
        g_sw1[t] = (m > 0.f ? m : 1.f) / 32000.f;
    } else {
        int n = t - 256;
        float m = 0.f;
        for (int k = 0; k < 256; k++) m = fmaxf(m, fabsf(W2[k * 128 + n]));
        g_sw2[n] = (m > 0.f ? m : 1.f) / 32000.f;
    }
}

// ---------------------------------------------------------------------------
// prep 2: quantize + transpose + split + swizzle weights
// ---------------------------------------------------------------------------
__global__ void prep_quant(const float* __restrict__ W1, const float* __restrict__ W2) {
    int tid = threadIdx.x + blockIdx.x * blockDim.x;
    int stride = blockDim.x * gridDim.x;
    for (int i = tid; i < 32768; i += stride) {        // W1: n=256, k=128
        int n = i >> 7, k = i & 127;
        float q = rintf(W1[k * 256 + n] / g_sw1[n]);
        int ih, il; split16(q, ih, il);
        uint32_t off = (uint32_t)(n * 128) + (uint32_t)(k ^ ((n & 7) << 4));
        gW1q[off] = (signed char)ih;
        gW1q[32768 + off] = (signed char)il;
    }
    for (int i = tid; i < 32768; i += stride) {        // W2: slab s, n=128, k=64
        int s = i >> 13, r = i & 8191, n = r >> 6, k = r & 63;
        float q = rintf(W2[(s * 64 + k) * 128 + n] / g_sw2[n]);
        int ih, il; split16(q, ih, il);
        uint32_t off = (uint32_t)(s * 16384) + (uint32_t)(n * 64) + (uint32_t)(k ^ ((n & 3) << 4));
        gW2q[off] = (signed char)ih;
        gW2q[off + 8192] = (signed char)il;
    }
}

// ---------------------------------------------------------------------------
// K1: FFN via int8 mma.m16n8k32 with 16-bit split (3 terms, drop lo*lo).
// 64 rows/tile, 4 tiles/CTA, 8 warps (2m x 4n), W1 resident, W2 slab-streamed.
// GEMM1 in 2 N-passes of 128 cols (register budget).
// ---------------------------------------------------------------------------
__global__ void __launch_bounds__(256, 2)
ffn_imma(const float* __restrict__ x,
         const float* __restrict__ b1, const float* __restrict__ b2) {
    extern __shared__ char sm[];
    const uint32_t sb = smem_u32(sm);
    const int tid = threadIdx.x;
    const int wid = tid >> 5;
    const int lane = tid & 31;
    const int wm = wid & 1;        // 0-1
    const int wn = wid >> 1;       // 0-3

    // W1 (hi+lo) resident: 64KB = 4096 uint4
    {
        const uint4* src = (const uint4*)gW1q;
        uint4* dst = (uint4*)(sm + OFF_W1H);
#pragma unroll 4
        for (int i = tid; i < 4096; i += 256) dst[i] = src[i];
    }

    for (int t = 0; t < TILES_PER_CTA; t++) {
        const size_t rowbase = (size_t)(blockIdx.x * TILES_PER_CTA + t) * 64;

        __syncthreads();   // protect x/W2 region + h1 from previous tile

        // ---- load + quantize x tile [64,128]: 4 threads per row ----
        {
            const int row = tid >> 2;
            const int kq = (tid & 3) * 32;
            const float4* xr = (const float4*)(x + (rowbase + row) * DIM + kq);
#pragma unroll
            for (int c = 0; c < 2; c++) {
                int hb[16], lb[16];
#pragma unroll
                for (int j = 0; j < 4; j++) {
                    float4 v = xr[c * 4 + j];
                    float q0 = rintf(fminf(fmaxf(v.x * XQ_SCALE, -32000.f), 32000.f));
                    float q1 = rintf(fminf(fmaxf(v.y * XQ_SCALE, -32000.f), 32000.f));
                    float q2 = rintf(fminf(fmaxf(v.z * XQ_SCALE, -32000.f), 32000.f));
                    float q3 = rintf(fminf(fmaxf(v.w * XQ_SCALE, -32000.f), 32000.f));
                    split16(q0, hb[j * 4 + 0], lb[j * 4 + 0]);
                    split16(q1, hb[j * 4 + 1], lb[j * 4 + 1]);
                    split16(q2, hb[j * 4 + 2], lb[j * 4 + 2]);
                    split16(q3, hb[j * 4 + 3], lb[j * 4 + 3]);
                }
                uint4 hp = make_uint4(pack4(hb[0], hb[1], hb[2], hb[3]), pack4(hb[4], hb[5], hb[6], hb[7]),
                                      pack4(hb[8], hb[9], hb[10], hb[11]), pack4(hb[12], hb[13], hb[14], hb[15]));
                uint4 lp = make_uint4(pack4(lb[0], lb[1], lb[2], lb[3]), pack4(lb[4], lb[5], lb[6], lb[7]),
                                      pack4(lb[8], lb[9], lb[10], lb[11]), pack4(lb[12], lb[13], lb[14], lb[15]));
                uint32_t off = (uint32_t)(row * 128) + (uint32_t)((kq + c * 16) ^ ((row & 7) << 4));
                *(uint4*)(sm + OFF_XH + off) = hp;
                *(uint4*)(sm + OFF_XL + off) = lp;
            }
        }
        __syncthreads();

        // ---- GEMM1: [64,128] @ [128,256] in 2 N-passes of 128 ----
#pragma unroll
        for (int pass = 0; pass < 2; pass++) {
            int p1[2][4][4], p23[2][4][4];
#pragma unroll
            for (int a = 0; a < 2; a++)
#pragma unroll
                for (int b = 0; b < 4; b++)
#pragma unroll
                    for (int c = 0; c < 4; c++) { p1[a][b][c] = 0; p23[a][b][c] = 0; }

#pragma unroll
            for (int ks = 0; ks < 4; ks++) {
                const int kb = ks * 32;
                uint32_t ah[2][4], al[2][4];
#pragma unroll
                for (int mt = 0; mt < 2; mt++) {
                    ldsm4(a_addr(sb + OFF_XH, 128, wm * 32 + mt * 16, kb, lane), ah[mt]);
                    ldsm4(a_addr(sb + OFF_XL, 128, wm * 32 + mt * 16, kb, lane), al[mt]);
                }
#pragma unroll
                for (int nt = 0; nt < 2; nt++) {
                    const int n0 = pass * 128 + wn * 32 + nt * 16;
                    uint32_t bh[4], bl[4];
                    ldsm4(b_addr(sb + OFF_W1H, 128, n0, kb, lane, 7), bh);
                    ldsm4(b_addr(sb + OFF_W1L, 128, n0, kb, lane, 7), bl);
#pragma unroll
                    for (int mt = 0; mt < 2; mt++) {
#pragma unroll
                        for (int h = 0; h < 2; h++) {
                            imma(p1[mt][nt * 2 + h], ah[mt], bh[h * 2], bh[h * 2 + 1]);
                            imma(p23[mt][nt * 2 + h], ah[mt], bl[h * 2], bl[h * 2 + 1]);
                            imma(p23[mt][nt * 2 + h], al[mt], bh[h * 2], bh[h * 2 + 1]);
                        }
                    }
                }
            }

            // ---- Epilogue 1: dequant, +b1, GELU, requant -> h1q (smem) ----
#pragma unroll
            for (int n8 = 0; n8 < 4; n8++) {
                const int c0 = pass * 128 + wn * 32 + n8 * 8 + (lane & 3) * 2;
                const float s0 = XQ_INV * __ldg(&g_sw1[c0]);
                const float s1 = XQ_INV * __ldg(&g_sw1[c0 + 1]);
                const float bb0 = __ldg(&b1[c0]), bb1 = __ldg(&b1[c0 + 1]);
#pragma unroll
                for (int mt = 0; mt < 2; mt++) {
                    const int r = wm * 32 + mt * 16 + (lane >> 2);
#pragma unroll
                    for (int h = 0; h < 2; h++) {
                        const int rr = r + h * 8;
                        float v0 = (65536.f * (float)p1[mt][n8][h * 2] + 256.f * (float)p23[mt][n8][h * 2]) * s0 + bb0;
                        float v1 = (65536.f * (float)p1[mt][n8][h * 2 + 1] + 256.f * (float)p23[mt][n8][h * 2 + 1]) * s1 + bb1;
                        float q0 = rintf(fminf(fmaxf(gelu_exact(v0) * HQ_SCALE, -32000.f), 32000.f));
                        float q1 = rintf(fminf(fmaxf(gelu_exact(v1) * HQ_SCALE, -32000.f), 32000.f));
                        int ih0, il0, ih1, il1;
                        split16(q0, ih0, il0);
                        split16(q1, ih1, il1);
                        uint32_t off = (uint32_t)(rr * 256) + (uint32_t)(c0 ^ ((rr & 7) << 4));
                        *(short*)(sm + OFF_H1H + off) = (short)((ih0 & 255) | ((ih1 & 255) << 8));
                        *(short*)(sm + OFF_H1L + off) = (short)((il0 & 255) | ((il1 & 255) << 8));
                    }
                }
            }
        }
        __syncthreads();   // h1q complete; x reads done -> W2 slabs may overwrite

        // ---- GEMM2: [64,256] @ [256,128], W2 streamed in 4 k-slabs of 64 ----
        int q1[2][4][4], q23[2][4][4];
#pragma unroll
        for (int a = 0; a < 2; a++)
#pragma unroll
            for (int b = 0; b < 4; b++)
#pragma unroll
                for (int c = 0; c < 4; c++) { q1[a][b][c] = 0; q23[a][b][c] = 0; }

        for (int s = 0; s < 4; s++) {
            {
                const uint4* src = (const uint4*)(gW2q + (size_t)s * 16384);
                uint4* dst = (uint4*)(sm + OFF_W2H);
#pragma unroll
                for (int i = tid; i < 1024; i += 256) dst[i] = src[i];
            }
            __syncthreads();
#pragma unroll
            for (int ks = 0; ks < 2; ks++) {
                const int kb = ks * 32;          // within slab
                const int akb = s * 64 + kb;     // within h1q
                uint32_t ah[2][4], al[2][4];
#pragma unroll
                for (int mt = 0; mt < 2; mt++) {
                    ldsm4(a_addr(sb + OFF_H1H, 256, wm * 32 + mt * 16, akb, lane), ah[mt]);
                    ldsm4(a_addr(sb + OFF_H1L, 256, wm * 32 + mt * 16, akb, lane), al[mt]);
                }
#pragma unroll
                for (int nt = 0; nt < 2; nt++) {
                    const int n0 = wn * 32 + nt * 16;
                    uint32_t bh[4], bl[4];
                    ldsm4(b_addr(sb + OFF_W2H, 64, n0, kb, lane, 3), bh);
                    ldsm4(b_addr(sb + OFF_W2L, 64, n0, kb, lane, 3), bl);
#pragma unroll
                    for (int mt = 0; mt < 2; mt++) {
#pragma unroll
                        for (int h = 0; h < 2; h++) {
                            imma(q1[mt][nt * 2 + h], ah[mt], bh[h * 2], bh[h * 2 + 1]);
                            imma(q23[mt][nt * 2 + h], ah[mt], bl[h * 2], bl[h * 2 + 1]);
                            imma(q23[mt][nt * 2 + h], al[mt], bh[h * 2], bh[h * 2 + 1]);
                        }
                    }
                }
            }
            __syncthreads();   // slab reads done before overwrite
        }

        // ---- Epilogue 2: dequant, +b2 -> g_hbuf ----
#pragma unroll
        for (int n8 = 0; n8 < 4; n8++) {
            const int c0 = wn * 32 + n8 * 8 + (lane & 3) * 2;
            const float s0 = HQ_INV * __ldg(&g_sw2[c0]);
            const float s1 = HQ_INV * __ldg(&g_sw2[c0 + 1]);
            const float bb0 = __ldg(&b2[c0]), bb1 = __ldg(&b2[c0 + 1]);
#pragma unroll
            for (int mt = 0; mt < 2; mt++) {
                const int r = wm * 32 + mt * 16 + (lane >> 2);
#pragma unroll
                for (int h = 0; h < 2; h++) {
                    const int rr = r + h * 8;
                    float2 v;
                    v.x = (65536.f * (float)q1[mt][n8][h * 2] + 256.f * (float)q23[mt][n8][h * 2]) * s0 + bb0;
                    v.y = (65536.f * (float)q1[mt][n8][h * 2 + 1] + 256.f * (float)q23[mt][n8][h * 2 + 1]) * s1 + bb1;
                    *(float2*)&g_hbuf[(rowbase + rr) * DIM + c0] = v;
                }
            }
        }
    }
}

// ---------------------------------------------------------------------------
// K2: scatter-mean per graph (batch_idx sorted, one block per graph)
// ---------------------------------------------------------------------------
__global__ void scatter_kernel(const int* __restrict__ hub_idx,
                               const int* __restrict__ batch_idx,
                               float* __restrict__ hubf_out) {
    __shared__ float acc[HH][DIM];
    __shared__ int   cnt[HH];
    __shared__ int   srange[2];

    const int b = blockIdx.x;
    const int tid = threadIdx.x;   // 128 threads; tid == dim

    for (int i = tid; i < HH * DIM; i += 128) ((float*)acc)[i] = 0.f;
    if (tid < HH) cnt[tid] = 0;
    if (tid < 2) {
        int target = b + tid, lo = 0, hi = NS;
        while (lo < hi) { int mid = (lo + hi) >> 1; if (batch_idx[mid] < target) lo = mid + 1; else hi = mid; }
        srange[tid] = lo;
    }
    __syncthreads();

    const int s0 = srange[0], s1 = srange[1];
    for (int s = s0 + tid; s < s1; s += 128) atomicAdd(&cnt[hub_idx[s]], 1);
    for (int s = s0; s < s1; s++) {
        int hu = hub_idx[s];
        acc[hu][tid] += g_hbuf[(size_t)s * DIM + tid];
    }
    __syncthreads();

    for (int h = 0; h < HH; h++) {
        float c = cnt[h] > 0 ? (float)cnt[h] : 1.0f;
        hubf_out[((size_t)b * HH + h) * DIM + tid] = acc[h][tid] / c;
    }
}

// ---------------------------------------------------------------------------
// K3: per-graph 64x64 kNN (top-4 min d2, tie-break lower index) + edge emit
// ---------------------------------------------------------------------------
__global__ void knn_edge_kernel(const int* __restrict__ hub_idx,
                                const int* __restrict__ batch_idx,
                                const float* __restrict__ hubf,
                                float* __restrict__ e0,
                                float* __restrict__ e1) {
    __shared__ float hf[HH][DIM + 1];
    __shared__ float d2row[8][HH];
    __shared__ int   knn[HH][KK_];
    __shared__ int   srange[2];

    const int b = blockIdx.x;
    const int tid = threadIdx.x;   // 256
    const int warp = tid >> 5, lane = tid & 31;

    for (int i = tid; i < HH * DIM; i += 256) {
        int h = i >> 7, d = i & 127;
        hf[h][d] = hubf[((size_t)b * HH + h) * DIM + d];
    }
    if (tid < 2) {
        int target = b + tid, lo = 0, hi = NS;
        while (lo < hi) { int mid = (lo + hi) >> 1; if (batch_idx[mid] < target) lo = mid + 1; else hi = mid; }
        srange[tid] = lo;
    }
    __syncthreads();

    for (int i = warp; i < HH; i += 8) {
        for (int jj = 0; jj < HH; jj += 32) {
            int j = jj + lane;
            float s = 0.f;
#pragma unroll
            for (int d = 0; d < DIM; d++) {
                float diff = hf[i][d] - hf[j][d];
                s = fmaf(diff, diff, s);
            }
            d2row[warp][j] = s;
        }
        float v0 = d2row[warp][lane], v1 = d2row[warp][lane + 32];
        int   i0 = lane,              i1 = lane + 32;
#pragma unroll
        for (int k = 0; k < KK_; k++) {
            float bv; int bi;
            if (v0 < v1 || (v0 == v1 && i0 < i1)) { bv = v0; bi = i0; }
            else                                   { bv = v1; bi = i1; }
#pragma unroll
            for (int off = 16; off; off >>= 1) {
                float ov = __shfl_xor_sync(0xffffffffu, bv, off);
                int   oi = __shfl_xor_sync(0xffffffffu, bi, off);
                if (ov < bv || (ov == bv && oi < bi)) { bv = ov; bi = oi; }
            }
            if (lane == 0) knn[i][k] = bi;
            if (i0 == bi) v0 = 3.4e38f;
            if (i1 == bi) v1 = 3.4e38f;
        }
    }
    __syncthreads();

    const int s0 = srange[0], s1 = srange[1];
    const int boff = b * HH;
    for (long idx = (long)s0 * KK_ + tid; idx < (long)s1 * KK_; idx += 256) {
        int s = (int)(idx >> 2);
        int k = (int)(idx & 3);
        int sh = hub_idx[s];
        e0[idx] = (float)s;
        e1[idx] = (float)(knn[sh][k] + boff);
    }
}

// ---------------------------------------------------------------------------
extern "C" void kernel_launch(void* const* d_in, const int* in_sizes, int n_in,
                              void* d_out, int out_size) {
    const float* x   = (const float*)d_in[0];
    const int*   hub = (const int*)d_in[1];
    const int*   bix = (const int*)d_in[2];
    const float* W1  = (const float*)d_in[3];
    const float* b1  = (const float*)d_in[4];
    const float* W2  = (const float*)d_in[5];
    const float* b2  = (const float*)d_in[6];

    float* out  = (float*)d_out;
    float* hubf = out;
    float* e0   = out + HUBF_ELEMS;
    float* e1   = out + HUBF_ELEMS + NK;

    cudaFuncSetAttribute(ffn_imma, cudaFuncAttributeMaxDynamicSharedMemorySize, FFN_SMEM);

    prep_scales<<<1, 384>>>(W1, W2);
    prep_quant<<<64, 256>>>(W1, W2);
    ffn_imma<<<FFN_GRID, 256, FFN_SMEM>>>(x, b1, b2);
    scatter_kernel<<<BG, 128>>>(hub, bix, hubf);
    knn_edge_kernel<<<BG, 256>>>(hub, bix, hubf, e0, e1);
}

// round 5
// speedup vs baseline: 1.8942x; 1.8942x over previous
#include <cuda_runtime.h>
#include <cuda_bf16.h>
#include <cstdint>

#define NS   524288
#define DIM  128
#define BG   128
#define HH   64
#define KK_  4
#define BH   (BG * HH)
#define NK   (NS * KK_)
#define HUBF_ELEMS (BH * DIM)

#define TILES_PER_CTA 4
#define FFN_GRID (NS / 64 / TILES_PER_CTA)   /* 2048 */

#define SPLITS 8
#define SCAT_GRID (BG * SPLITS)              /* 1024 */

// FFN output scratch
__device__ float g_hbuf[(size_t)NS * DIM];
// scatter partials: [graph*8+p][64 hubs][128 dims], and counts
__device__ float g_part[(size_t)SCAT_GRID * HH * DIM];
__device__ int   g_cntp[SCAT_GRID * HH];

// Prepped weights: bf16, transposed to [n][k], hi/lo split, XOR-swizzled.
__device__ __nv_bfloat16 gW1[65536];   // [split 2][n 256][k 128]
__device__ __nv_bfloat16 gW2[65536];   // [slab 4][split 2][n 128][k 64]

// SMEM byte offsets (ffn kernel)
#define OFF_W1H 0
#define OFF_W1L 65536
#define OFF_XH  131072
#define OFF_XL  147456
#define OFF_W2H 131072   /* reuses x region after GEMM1 */
#define OFF_W2L 147456
#define OFF_H1H 163840
#define OFF_H1L 196608
#define FFN_SMEM 229376

// ---------------------------------------------------------------------------
__device__ __forceinline__ uint32_t smem_u32(const void* p) {
    uint32_t a;
    asm("{ .reg .u64 t; cvta.to.shared.u64 t, %1; cvt.u32.u64 %0, t; }" : "=r"(a) : "l"(p));
    return a;
}
__device__ __forceinline__ void ldsm4(uint32_t addr, uint32_t r[4]) {
    asm volatile("ldmatrix.sync.aligned.m8n8.x4.shared.b16 {%0,%1,%2,%3}, [%4];"
                 : "=r"(r[0]), "=r"(r[1]), "=r"(r[2]), "=r"(r[3]) : "r"(addr));
}
__device__ __forceinline__ void mma16816(float c[4], const uint32_t a[4], uint32_t b0, uint32_t b1) {
    asm volatile("mma.sync.aligned.m16n8k16.row.col.f32.bf16.bf16.f32 "
                 "{%0,%1,%2,%3}, {%4,%5,%6,%7}, {%8,%9}, {%0,%1,%2,%3};"
                 : "+f"(c[0]), "+f"(c[1]), "+f"(c[2]), "+f"(c[3])
                 : "r"(a[0]), "r"(a[1]), "r"(a[2]), "r"(a[3]), "r"(b0), "r"(b1));
}
__device__ __forceinline__ uint32_t a_addr(uint32_t base, int stride, int m0, int kb, int lane) {
    int row = m0 + (lane & 15);
    int k = kb + ((lane >> 4) << 4);
    return base + row * stride + (uint32_t)(k ^ ((row & 7) << 4));
}
__device__ __forceinline__ uint32_t b_addr(uint32_t base, int stride, int n0, int kb, int lane) {
    int row = n0 + (lane & 7) + ((lane & 16) >> 1);
    int k = kb + (((lane >> 3) & 1) << 4);
    return base + row * stride + (uint32_t)(k ^ ((row & 7) << 4));
}
__device__ __forceinline__ float gelu_exact(float v) {
    return 0.5f * v * (1.0f + erff(v * 0.7071067811865476f));
}
__device__ __forceinline__ uint32_t pack_bf2(__nv_bfloat16 a, __nv_bfloat16 b) {
    __nv_bfloat162 t; t.x = a; t.y = b;
    return *(uint32_t*)&t;
}

// ---------------------------------------------------------------------------
// K0: weight prep — transpose, hi/lo split, XOR swizzle
// ---------------------------------------------------------------------------
__global__ void prep_weights(const float* __restrict__ W1, const float* __restrict__ W2) {
    int tid = threadIdx.x + blockIdx.x * blockDim.x;
    int stride = blockDim.x * gridDim.x;
    for (int i = tid; i < 65536; i += stride) {
        int split = i >> 15, r = i & 32767, n = r >> 7, k = r & 127;
        float v = W1[k * 256 + n];
        __nv_bfloat16 hi = __float2bfloat16(v);
        __nv_bfloat16 val = split ? __float2bfloat16(v - __bfloat162float(hi)) : hi;
        uint32_t off = (uint32_t)(n * 256) + (uint32_t)((k * 2) ^ ((n & 7) << 4));
        *(__nv_bfloat16*)((char*)gW1 + (size_t)split * 65536 + off) = val;
    }
    for (int i = tid; i < 65536; i += stride) {
        int s = i >> 14, r = i & 16383, split = r >> 13, rr = r & 8191, n = rr >> 6, k = rr & 63;
        float v = W2[(s * 64 + k) * 128 + n];
        __nv_bfloat16 hi = __float2bfloat16(v);
        __nv_bfloat16 val = split ? __float2bfloat16(v - __bfloat162float(hi)) : hi;
        uint32_t off = (uint32_t)(n * 128) + (uint32_t)((k * 2) ^ ((n & 7) << 4));
        *(__nv_bfloat16*)((char*)gW2 + (size_t)s * 32768 + (size_t)split * 16384 + off) = val;
    }
}

// ---------------------------------------------------------------------------
// K1: FFN via mma.sync bf16 (hi/lo split, 3 terms). Same as R3 (795us).
// ---------------------------------------------------------------------------
__global__ void __launch_bounds__(256)
ffn_mma(const float* __restrict__ x,
        const float* __restrict__ b1, const float* __restrict__ b2) {
    extern __shared__ char sm[];
    const uint32_t sb = smem_u32(sm);
    const int tid = threadIdx.x;
    const int wid = tid >> 5;
    const int lane = tid & 31;
    const int wm = wid & 1;
    const int wn = wid >> 1;

    // load W1 (hi+lo) once: 131072 B = 8192 uint4
    {
        const uint4* src = (const uint4*)gW1;
        uint4* dst = (uint4*)(sm + OFF_W1H);
#pragma unroll 8
        for (int i = tid; i < 8192; i += 256) dst[i] = src[i];
    }

    for (int t = 0; t < TILES_PER_CTA; t++) {
        const int tile = blockIdx.x * TILES_PER_CTA + t;
        const size_t rowbase = (size_t)tile * 64;

        __syncthreads();

        // ---- load x tile [64,128] f32 -> bf16 hi/lo, swizzled ----
        {
            const float4* xg = (const float4*)(x + rowbase * DIM);
#pragma unroll
            for (int ii = 0; ii < 8; ii++) {
                int i = tid + ii * 256;
                float4 v = xg[i];
                int row = i >> 5, k = (i & 31) * 4;
                __nv_bfloat16 h0 = __float2bfloat16(v.x), h1v = __float2bfloat16(v.y);
                __nv_bfloat16 h2 = __float2bfloat16(v.z), h3 = __float2bfloat16(v.w);
                __nv_bfloat16 l0 = __float2bfloat16(v.x - __bfloat162float(h0));
                __nv_bfloat16 l1 = __float2bfloat16(v.y - __bfloat162float(h1v));
                __nv_bfloat16 l2 = __float2bfloat16(v.z - __bfloat162float(h2));
                __nv_bfloat16 l3 = __float2bfloat16(v.w - __bfloat162float(h3));
                uint32_t off = (uint32_t)((k * 2) ^ ((row & 7) << 4)) + row * 256;
                *(uint2*)(sm + OFF_XH + off) = make_uint2(pack_bf2(h0, h1v), pack_bf2(h2, h3));
                *(uint2*)(sm + OFF_XL + off) = make_uint2(pack_bf2(l0, l1), pack_bf2(l2, l3));
            }
        }
        __syncthreads();

        // ---- GEMM1: [64,128] x [128,256] ----
        float acc[2][8][4];
#pragma unroll
        for (int a = 0; a < 2; a++)
#pragma unroll
            for (int b = 0; b < 8; b++)
#pragma unroll
                for (int c = 0; c < 4; c++) acc[a][b][c] = 0.f;

#pragma unroll
        for (int ks = 0; ks < 8; ks++) {
            const int kb = ks * 32;
            uint32_t ah[2][4], al[2][4];
#pragma unroll
            for (int mt = 0; mt < 2; mt++) {
                ldsm4(a_addr(sb + OFF_XH, 256, wm * 32 + mt * 16, kb, lane), ah[mt]);
                ldsm4(a_addr(sb + OFF_XL, 256, wm * 32 + mt * 16, kb, lane), al[mt]);
            }
#pragma unroll
            for (int ntp = 0; ntp < 4; ntp++) {
                const int n0 = wn * 64 + ntp * 16;
                uint32_t bh[4], bl[4];
                ldsm4(b_addr(sb + OFF_W1H, 256, n0, kb, lane), bh);
                ldsm4(b_addr(sb + OFF_W1L, 256, n0, kb, lane), bl);
#pragma unroll
                for (int mt = 0; mt < 2; mt++) {
                    mma16816(acc[mt][ntp * 2],     ah[mt], bh[0], bh[1]);
                    mma16816(acc[mt][ntp * 2],     al[mt], bh[0], bh[1]);
                    mma16816(acc[mt][ntp * 2],     ah[mt], bl[0], bl[1]);
                    mma16816(acc[mt][ntp * 2 + 1], ah[mt], bh[2], bh[3]);
                    mma16816(acc[mt][ntp * 2 + 1], al[mt], bh[2], bh[3]);
                    mma16816(acc[mt][ntp * 2 + 1], ah[mt], bl[2], bl[3]);
                }
            }
        }

        // ---- Epilogue 1: +b1, GELU, split -> h1 (smem) ----
#pragma unroll
        for (int nt = 0; nt < 8; nt++) {
            const int col = wn * 64 + nt * 8 + (lane & 3) * 2;
            const float2 bb = *(const float2*)&b1[col];
#pragma unroll
            for (int mt = 0; mt < 2; mt++) {
                const int r = wm * 32 + mt * 16 + (lane >> 2);
#pragma unroll
                for (int h = 0; h < 2; h++) {
                    const int rr = r + h * 8;
                    float v0 = gelu_exact(acc[mt][nt][h * 2]     + bb.x);
                    float v1 = gelu_exact(acc[mt][nt][h * 2 + 1] + bb.y);
                    __nv_bfloat16 h0 = __float2bfloat16(v0), h1v = __float2bfloat16(v1);
                    __nv_bfloat16 l0 = __float2bfloat16(v0 - __bfloat162float(h0));
                    __nv_bfloat16 l1 = __float2bfloat16(v1 - __bfloat162float(h1v));
                    uint32_t off = rr * 512 + (uint32_t)((col * 2) ^ ((rr & 7) << 4));
                    *(uint32_t*)(sm + OFF_H1H + off) = pack_bf2(h0, h1v);
                    *(uint32_t*)(sm + OFF_H1L + off) = pack_bf2(l0, l1);
                }
            }
        }
        __syncthreads();

        // ---- GEMM2: [64,256] x [256,128], W2 in 4 k-slabs of 64 ----
        float acc2[2][4][4];
#pragma unroll
        for (int a = 0; a < 2; a++)
#pragma unroll
            for (int b = 0; b < 4; b++)
#pragma unroll
                for (int c = 0; c < 4; c++) acc2[a][b][c] = 0.f;

        for (int s = 0; s < 4; s++) {
            {
                const uint4* src = (const uint4*)((const char*)gW2 + (size_t)s * 32768);
                uint4* dst = (uint4*)(sm + OFF_W2H);
#pragma unroll
                for (int i = tid; i < 2048; i += 256) dst[i] = src[i];
            }
            __syncthreads();
#pragma unroll
            for (int ks = 0; ks < 4; ks++) {
                const int kb = ks * 32;
                const int akb = s * 128 + kb;
                uint32_t ah[2][4], al[2][4];
#pragma unroll
                for (int mt = 0; mt < 2; mt++) {
                    ldsm4(a_addr(sb + OFF_H1H, 512, wm * 32 + mt * 16, akb, lane), ah[mt]);
                    ldsm4(a_addr(sb + OFF_H1L, 512, wm * 32 + mt * 16, akb, lane), al[mt]);
                }
#pragma unroll
                for (int ntp = 0; ntp < 2; ntp++) {
                    const int n0 = wn * 32 + ntp * 16;
                    uint32_t bh[4], bl[4];
                    ldsm4(b_addr(sb + OFF_W2H, 128, n0, kb, lane), bh);
                    ldsm4(b_addr(sb + OFF_W2L, 128, n0, kb, lane), bl);
#pragma unroll
                    for (int mt = 0; mt < 2; mt++) {
                        mma16816(acc2[mt][ntp * 2],     ah[mt], bh[0], bh[1]);
                        mma16816(acc2[mt][ntp * 2],     al[mt], bh[0], bh[1]);
                        mma16816(acc2[mt][ntp * 2],     ah[mt], bl[0], bl[1]);
                        mma16816(acc2[mt][ntp * 2 + 1], ah[mt], bh[2], bh[3]);
                        mma16816(acc2[mt][ntp * 2 + 1], al[mt], bh[2], bh[3]);
                        mma16816(acc2[mt][ntp * 2 + 1], ah[mt], bl[2], bl[3]);
                    }
                }
            }
            __syncthreads();
        }

        // ---- Epilogue 2: +b2 -> g_hbuf ----
#pragma unroll
        for (int nt = 0; nt < 4; nt++) {
            const int col = wn * 32 + nt * 8 + (lane & 3) * 2;
            const float2 bb = *(const float2*)&b2[col];
#pragma unroll
            for (int mt = 0; mt < 2; mt++) {
                const int r = wm * 32 + mt * 16 + (lane >> 2);
#pragma unroll
                for (int h = 0; h < 2; h++) {
                    const int rr = r + h * 8;
                    float2 v = make_float2(acc2[mt][nt][h * 2] + bb.x,
                                           acc2[mt][nt][h * 2 + 1] + bb.y);
                    *(float2*)&g_hbuf[(rowbase + rr) * DIM + col] = v;
                }
            }
        }
    }
}

// ---------------------------------------------------------------------------
// K2a: partial scatter. 8 blocks per graph; block accumulates its slice in
// smem (thread d owns dim d -> no float atomics) and writes a dense partial.
// Deterministic.
// ---------------------------------------------------------------------------
__global__ void __launch_bounds__(128)
scatter_partial(const int* __restrict__ hub_idx,
                const int* __restrict__ batch_idx) {
    __shared__ float acc[HH][DIM];   // 32KB
    __shared__ int   cnt[HH];
    __shared__ int   srange[2];

    const int b = blockIdx.x >> 3;
    const int p = blockIdx.x & 7;
    const int tid = threadIdx.x;     // 128; tid == dim

    for (int i = tid; i < HH * DIM; i += 128) ((float*)acc)[i] = 0.f;
    if (tid < HH) cnt[tid] = 0;
    if (tid < 2) {
        int target = b + tid, lo = 0, hi = NS;
        while (lo < hi) { int mid = (lo + hi) >> 1; if (batch_idx[mid] < target) lo = mid + 1; else hi = mid; }
        srange[tid] = lo;
    }
    __syncthreads();

    const int s0 = srange[0], s1 = srange[1];
    const int chunk = (s1 - s0 + SPLITS - 1) >> 3;
    const int cs = s0 + p * chunk;
    const int ce = min(cs + chunk, s1);

    for (int s = cs + tid; s < ce; s += 128) atomicAdd(&cnt[hub_idx[s]], 1);

    if (cs < ce) {
        int   hu_n = hub_idx[cs];
        float v_n  = g_hbuf[(size_t)cs * DIM + tid];
        for (int s = cs; s < ce; s++) {
            int hu = hu_n;
            float v = v_n;
            if (s + 1 < ce) {                      // prefetch next spoke
                hu_n = hub_idx[s + 1];
                v_n  = g_hbuf[(size_t)(s + 1) * DIM + tid];
            }
            acc[hu][tid] += v;
        }
    }
    __syncthreads();

    float* part = g_part + (size_t)blockIdx.x * (HH * DIM);
    for (int h = 0; h < HH; h++) part[h * DIM + tid] = acc[h][tid];
    if (tid < HH) g_cntp[blockIdx.x * HH + tid] = cnt[tid];
}

// ---------------------------------------------------------------------------
// K2b: finalize — sum 8 partials + counts, divide, write hub_features.
// ---------------------------------------------------------------------------
__global__ void __launch_bounds__(128)
scatter_finalize(float* __restrict__ hubf_out) {
    __shared__ float inv[HH];
    const int b = blockIdx.x;
    const int tid = threadIdx.x;

    if (tid < HH) {
        int c = 0;
#pragma unroll
        for (int p = 0; p < SPLITS; p++) c += g_cntp[(b * SPLITS + p) * HH + tid];
        inv[tid] = 1.0f / (float)max(c, 1);
    }
    __syncthreads();

    const float* part = g_part + (size_t)b * SPLITS * (HH * DIM);
    for (int h = 0; h < HH; h++) {
        float s = 0.f;
#pragma unroll
        for (int p = 0; p < SPLITS; p++) s += part[(size_t)p * (HH * DIM) + h * DIM + tid];
        hubf_out[((size_t)b * HH + h) * DIM + tid] = s * inv[h];
    }
}

// ---------------------------------------------------------------------------
// K3: per-graph 64x64 kNN (top-4 min d2, tie-break lower index) + edge emit
// ---------------------------------------------------------------------------
__global__ void knn_edge_kernel(const int* __restrict__ hub_idx,
                                const int* __restrict__ batch_idx,
                                const float* __restrict__ hubf,
                                float* __restrict__ e0,
                                float* __restrict__ e1) {
    __shared__ float hf[HH][DIM + 1];
    __shared__ float d2row[8][HH];
    __shared__ int   knn[HH][KK_];
    __shared__ int   srange[2];

    const int b = blockIdx.x;
    const int tid = threadIdx.x;   // 256
    const int warp = tid >> 5, lane = tid & 31;

    for (int i = tid; i < HH * DIM; i += 256) {
        int h = i >> 7, d = i & 127;
        hf[h][d] = hubf[((size_t)b * HH + h) * DIM + d];
    }
    if (tid < 2) {
        int target = b + tid, lo = 0, hi = NS;
        while (lo < hi) { int mid = (lo + hi) >> 1; if (batch_idx[mid] < target) lo = mid + 1; else hi = mid; }
        srange[tid] = lo;
    }
    __syncthreads();

    for (int i = warp; i < HH; i += 8) {
        for (int jj = 0; jj < HH; jj += 32) {
            int j = jj + lane;
            float s = 0.f;
#pragma unroll
            for (int d = 0; d < DIM; d++) {
                float diff = hf[i][d] - hf[j][d];
                s = fmaf(diff, diff, s);
            }
            d2row[warp][j] = s;
        }
        float v0 = d2row[warp][lane], v1 = d2row[warp][lane + 32];
        int   i0 = lane,              i1 = lane + 32;
#pragma unroll
        for (int k = 0; k < KK_; k++) {
            float bv; int bi;
            if (v0 < v1 || (v0 == v1 && i0 < i1)) { bv = v0; bi = i0; }
            else                                   { bv = v1; bi = i1; }
#pragma unroll
            for (int off = 16; off; off >>= 1) {
                float ov = __shfl_xor_sync(0xffffffffu, bv, off);
                int   oi = __shfl_xor_sync(0xffffffffu, bi, off);
                if (ov < bv || (ov == bv && oi < bi)) { bv = ov; bi = oi; }
            }
            if (lane == 0) knn[i][k] = bi;
            if (i0 == bi) v0 = 3.4e38f;
            if (i1 == bi) v1 = 3.4e38f;
        }
    }
    __syncthreads();

    const int s0 = srange[0], s1 = srange[1];
    const int boff = b * HH;
    for (long idx = (long)s0 * KK_ + tid; idx < (long)s1 * KK_; idx += 256) {
        int s = (int)(idx >> 2);
        int k = (int)(idx & 3);
        int sh = hub_idx[s];
        e0[idx] = (float)s;
        e1[idx] = (float)(knn[sh][k] + boff);
    }
}

// ---------------------------------------------------------------------------
extern "C" void kernel_launch(void* const* d_in, const int* in_sizes, int n_in,
                              void* d_out, int out_size) {
    const float* x   = (const float*)d_in[0];
    const int*   hub = (const int*)d_in[1];
    const int*   bix = (const int*)d_in[2];
    const float* W1  = (const float*)d_in[3];
    const float* b1  = (const float*)d_in[4];
    const float* W2  = (const float*)d_in[5];
    const float* b2  = (const float*)d_in[6];

    float* out  = (float*)d_out;
    float* hubf = out;
    float* e0   = out + HUBF_ELEMS;
    float* e1   = out + HUBF_ELEMS + NK;

    cudaFuncSetAttribute(ffn_mma, cudaFuncAttributeMaxDynamicSharedMemorySize, FFN_SMEM);

    prep_weights<<<64, 256>>>(W1, W2);
    ffn_mma<<<FFN_GRID, 256, FFN_SMEM>>>(x, b1, b2);
    scatter_partial<<<SCAT_GRID, 128>>>(hub, bix);
    scatter_finalize<<<BG, 128>>>(hubf);
    knn_edge_kernel<<<BG, 256>>>(hub, bix, hubf, e0, e1);
}

// round 6
// speedup vs baseline: 2.5104x; 1.3253x over previous
#include <cuda_runtime.h>
#include <cuda_fp16.h>
#include <cstdint>

#define NS   524288
#define DIM  128
#define BG   128
#define HH   64
#define KK_  4
#define BH   (BG * HH)
#define NK   (NS * KK_)
#define HUBF_ELEMS (BH * DIM)

#define TILES_PER_CTA 4
#define FFN_GRID (NS / 64 / TILES_PER_CTA)   /* 2048 */

#define SPLITS 8
#define SCAT_GRID (BG * SPLITS)              /* 1024 */

// FFN output scratch
__device__ float g_hbuf[(size_t)NS * DIM];
// scatter partials + counts
__device__ float g_part[(size_t)SCAT_GRID * HH * DIM];
__device__ int   g_cntp[SCAT_GRID * HH];
// knn table: [B*H][4] local hub ids
__device__ int   g_knn[BH * KK_];

// Prepped fp16 weights, transposed [n][k], XOR-swizzled
__device__ __half gW1[256 * 128];   // 64KB, row stride 256B
__device__ __half gW2[128 * 256];   // 64KB, row stride 512B

// SMEM layout (ffn): 224KB
#define OFF_W1  0         /* [256][128] fp16, stride 256B */
#define OFF_W2  65536     /* [128][256] fp16, stride 512B */
#define OFF_XH  131072    /* [64][128] fp16 */
#define OFF_XL  147456
#define OFF_H1H 163840    /* [64][256] fp16 */
#define OFF_H1L 196608
#define FFN_SMEM 229376

// ---------------------------------------------------------------------------
__device__ __forceinline__ uint32_t smem_u32(const void* p) {
    uint32_t a;
    asm("{ .reg .u64 t; cvta.to.shared.u64 t, %1; cvt.u32.u64 %0, t; }" : "=r"(a) : "l"(p));
    return a;
}
__device__ __forceinline__ void ldsm4(uint32_t addr, uint32_t r[4]) {
    asm volatile("ldmatrix.sync.aligned.m8n8.x4.shared.b16 {%0,%1,%2,%3}, [%4];"
                 : "=r"(r[0]), "=r"(r[1]), "=r"(r[2]), "=r"(r[3]) : "r"(addr));
}
__device__ __forceinline__ void mma16816(float c[4], const uint32_t a[4], uint32_t b0, uint32_t b1) {
    asm volatile("mma.sync.aligned.m16n8k16.row.col.f32.f16.f16.f32 "
                 "{%0,%1,%2,%3}, {%4,%5,%6,%7}, {%8,%9}, {%0,%1,%2,%3};"
                 : "+f"(c[0]), "+f"(c[1]), "+f"(c[2]), "+f"(c[3])
                 : "r"(a[0]), "r"(a[1]), "r"(a[2]), "r"(a[3]), "r"(b0), "r"(b1));
}
__device__ __forceinline__ uint32_t a_addr(uint32_t base, int stride, int m0, int kb, int lane) {
    int row = m0 + (lane & 15);
    int k = kb + ((lane >> 4) << 4);
    return base + row * stride + (uint32_t)(k ^ ((row & 7) << 4));
}
__device__ __forceinline__ uint32_t b_addr(uint32_t base, int stride, int n0, int kb, int lane) {
    int row = n0 + (lane & 7) + ((lane & 16) >> 1);
    int k = kb + (((lane >> 3) & 1) << 4);
    return base + row * stride + (uint32_t)(k ^ ((row & 7) << 4));
}
__device__ __forceinline__ float gelu_exact(float v) {
    return 0.5f * v * (1.0f + erff(v * 0.7071067811865476f));
}
__device__ __forceinline__ uint32_t pack_h2(__half a, __half b) {
    __half2 t; t.x = a; t.y = b;
    return *(uint32_t*)&t;
}

// ---------------------------------------------------------------------------
// K0: weight prep — fp16 quantize + transpose + XOR swizzle
// ---------------------------------------------------------------------------
__global__ void prep_weights(const float* __restrict__ W1, const float* __restrict__ W2) {
    int tid = threadIdx.x + blockIdx.x * blockDim.x;
    int stride = blockDim.x * gridDim.x;
    for (int i = tid; i < 32768; i += stride) {          // W1: n 256, k 128
        int n = i >> 7, k = i & 127;
        uint32_t off = (uint32_t)(n * 256) + (uint32_t)((k * 2) ^ ((n & 7) << 4));
        *(__half*)((char*)gW1 + off) = __float2half_rn(W1[k * 256 + n]);
    }
    for (int i = tid; i < 32768; i += stride) {          // W2: n 128, k 256
        int n = i >> 8, k = i & 255;
        uint32_t off = (uint32_t)(n * 512) + (uint32_t)((k * 2) ^ ((n & 7) << 4));
        *(__half*)((char*)gW2 + off) = __float2half_rn(W2[k * 128 + n]);
    }
}

// ---------------------------------------------------------------------------
// K1: FFN via mma.sync fp16 (x split hi/lo, W single plane, 2 terms).
// W1+W2 resident in SMEM. 64 rows/tile, 4 tiles/CTA, 8 warps (2m x 4n).
// ---------------------------------------------------------------------------
__global__ void __launch_bounds__(256)
ffn_mma(const float* __restrict__ x,
        const float* __restrict__ b1, const float* __restrict__ b2) {
    extern __shared__ char sm[];
    const uint32_t sb = smem_u32(sm);
    const int tid = threadIdx.x;
    const int wid = tid >> 5;
    const int lane = tid & 31;
    const int wm = wid & 1;
    const int wn = wid >> 1;

    // load W1+W2 once: 131072 B = 8192 uint4
    {
        const uint4* s1 = (const uint4*)gW1;
        const uint4* s2 = (const uint4*)gW2;
        uint4* d1 = (uint4*)(sm + OFF_W1);
        uint4* d2 = (uint4*)(sm + OFF_W2);
#pragma unroll 4
        for (int i = tid; i < 4096; i += 256) { d1[i] = s1[i]; d2[i] = s2[i]; }
    }

    for (int t = 0; t < TILES_PER_CTA; t++) {
        const size_t rowbase = (size_t)(blockIdx.x * TILES_PER_CTA + t) * 64;

        __syncthreads();   // W ready / previous tile's H1 reads done

        // ---- load x tile [64,128] f32 -> fp16 hi/lo, swizzled ----
        {
            const float4* xg = (const float4*)(x + rowbase * DIM);
#pragma unroll
            for (int ii = 0; ii < 8; ii++) {
                int i = tid + ii * 256;
                float4 v = xg[i];
                int row = i >> 5, k = (i & 31) * 4;
                __half h0 = __float2half_rn(v.x), h1v = __float2half_rn(v.y);
                __half h2 = __float2half_rn(v.z), h3 = __float2half_rn(v.w);
                __half l0 = __float2half_rn(v.x - __half2float(h0));
                __half l1 = __float2half_rn(v.y - __half2float(h1v));
                __half l2 = __float2half_rn(v.z - __half2float(h2));
                __half l3 = __float2half_rn(v.w - __half2float(h3));
                uint32_t off = (uint32_t)((k * 2) ^ ((row & 7) << 4)) + row * 256;
                *(uint2*)(sm + OFF_XH + off) = make_uint2(pack_h2(h0, h1v), pack_h2(h2, h3));
                *(uint2*)(sm + OFF_XL + off) = make_uint2(pack_h2(l0, l1), pack_h2(l2, l3));
            }
        }
        __syncthreads();

        // ---- GEMM1: [64,128] x [128,256], warp tile 32x64 ----
        float acc[2][8][4];
#pragma unroll
        for (int a = 0; a < 2; a++)
#pragma unroll
            for (int b = 0; b < 8; b++)
#pragma unroll
                for (int c = 0; c < 4; c++) acc[a][b][c] = 0.f;

#pragma unroll
        for (int ks = 0; ks < 8; ks++) {
            const int kb = ks * 32;
            uint32_t ah[2][4], al[2][4];
#pragma unroll
            for (int mt = 0; mt < 2; mt++) {
                ldsm4(a_addr(sb + OFF_XH, 256, wm * 32 + mt * 16, kb, lane), ah[mt]);
                ldsm4(a_addr(sb + OFF_XL, 256, wm * 32 + mt * 16, kb, lane), al[mt]);
            }
#pragma unroll
            for (int ntp = 0; ntp < 4; ntp++) {
                const int n0 = wn * 64 + ntp * 16;
                uint32_t bw[4];
                ldsm4(b_addr(sb + OFF_W1, 256, n0, kb, lane), bw);
#pragma unroll
                for (int mt = 0; mt < 2; mt++) {
                    mma16816(acc[mt][ntp * 2],     ah[mt], bw[0], bw[1]);
                    mma16816(acc[mt][ntp * 2],     al[mt], bw[0], bw[1]);
                    mma16816(acc[mt][ntp * 2 + 1], ah[mt], bw[2], bw[3]);
                    mma16816(acc[mt][ntp * 2 + 1], al[mt], bw[2], bw[3]);
                }
            }
        }

        // ---- Epilogue 1: +b1, GELU, fp16 split -> h1 (smem) ----
#pragma unroll
        for (int nt = 0; nt < 8; nt++) {
            const int col = wn * 64 + nt * 8 + (lane & 3) * 2;
            const float2 bb = *(const float2*)&b1[col];
#pragma unroll
            for (int mt = 0; mt < 2; mt++) {
                const int r = wm * 32 + mt * 16 + (lane >> 2);
#pragma unroll
                for (int h = 0; h < 2; h++) {
                    const int rr = r + h * 8;
                    float v0 = gelu_exact(acc[mt][nt][h * 2]     + bb.x);
                    float v1 = gelu_exact(acc[mt][nt][h * 2 + 1] + bb.y);
                    __half h0 = __float2half_rn(v0), h1v = __float2half_rn(v1);
                    __half l0 = __float2half_rn(v0 - __half2float(h0));
                    __half l1 = __float2half_rn(v1 - __half2float(h1v));
                    uint32_t off = rr * 512 + (uint32_t)((col * 2) ^ ((rr & 7) << 4));
                    *(uint32_t*)(sm + OFF_H1H + off) = pack_h2(h0, h1v);
                    *(uint32_t*)(sm + OFF_H1L + off) = pack_h2(l0, l1);
                }
            }
        }
        __syncthreads();

        // ---- GEMM2: [64,256] x [256,128], W2 resident, warp tile 32x32 ----
        float acc2[2][4][4];
#pragma unroll
        for (int a = 0; a < 2; a++)
#pragma unroll
            for (int b = 0; b < 4; b++)
#pragma unroll
                for (int c = 0; c < 4; c++) acc2[a][b][c] = 0.f;

#pragma unroll
        for (int ks = 0; ks < 16; ks++) {
            const int kb = ks * 32;
            uint32_t ah[2][4], al[2][4];
#pragma unroll
            for (int mt = 0; mt < 2; mt++) {
                ldsm4(a_addr(sb + OFF_H1H, 512, wm * 32 + mt * 16, kb, lane), ah[mt]);
                ldsm4(a_addr(sb + OFF_H1L, 512, wm * 32 + mt * 16, kb, lane), al[mt]);
            }
#pragma unroll
            for (int ntp = 0; ntp < 2; ntp++) {
                const int n0 = wn * 32 + ntp * 16;
                uint32_t bw[4];
                ldsm4(b_addr(sb + OFF_W2, 512, n0, kb, lane), bw);
#pragma unroll
                for (int mt = 0; mt < 2; mt++) {
                    mma16816(acc2[mt][ntp * 2],     ah[mt], bw[0], bw[1]);
                    mma16816(acc2[mt][ntp * 2],     al[mt], bw[0], bw[1]);
                    mma16816(acc2[mt][ntp * 2 + 1], ah[mt], bw[2], bw[3]);
                    mma16816(acc2[mt][ntp * 2 + 1], al[mt], bw[2], bw[3]);
                }
            }
        }

        // ---- Epilogue 2: +b2 -> g_hbuf ----
#pragma unroll
        for (int nt = 0; nt < 4; nt++) {
            const int col = wn * 32 + nt * 8 + (lane & 3) * 2;
            const float2 bb = *(const float2*)&b2[col];
#pragma unroll
            for (int mt = 0; mt < 2; mt++) {
                const int r = wm * 32 + mt * 16 + (lane >> 2);
#pragma unroll
                for (int h = 0; h < 2; h++) {
                    const int rr = r + h * 8;
                    float2 v = make_float2(acc2[mt][nt][h * 2] + bb.x,
                                           acc2[mt][nt][h * 2 + 1] + bb.y);
                    *(float2*)&g_hbuf[(rowbase + rr) * DIM + col] = v;
                }
            }
        }
    }
}

// ---------------------------------------------------------------------------
// K2a: partial scatter, batch-8 pipelined (MLP=8). Deterministic.
// ---------------------------------------------------------------------------
__global__ void __launch_bounds__(128)
scatter_partial(const int* __restrict__ hub_idx,
                const int* __restrict__ batch_idx) {
    __shared__ float acc[HH][DIM];
    __shared__ int   cnt[HH];
    __shared__ int   srange[2];

    const int b = blockIdx.x >> 3;
    const int p = blockIdx.x & 7;
    const int tid = threadIdx.x;     // tid == dim

    for (int i = tid; i < HH * DIM; i += 128) ((float*)acc)[i] = 0.f;
    if (tid < HH) cnt[tid] = 0;
    if (tid < 2) {
        int target = b + tid, lo = 0, hi = NS;
        while (lo < hi) { int mid = (lo + hi) >> 1; if (batch_idx[mid] < target) lo = mid + 1; else hi = mid; }
        srange[tid] = lo;
    }
    __syncthreads();

    const int s0 = srange[0], s1 = srange[1];
    const int chunk = (s1 - s0 + SPLITS - 1) >> 3;
    const int cs = s0 + p * chunk;
    const int ce = min(cs + chunk, s1);

    for (int s = cs + tid; s < ce; s += 128) atomicAdd(&cnt[hub_idx[s]], 1);

    int s = cs;
    for (; s + 8 <= ce; s += 8) {
        int hu[8]; float v[8];
#pragma unroll
        for (int j = 0; j < 8; j++) hu[j] = __ldg(&hub_idx[s + j]);
#pragma unroll
        for (int j = 0; j < 8; j++) v[j] = g_hbuf[(size_t)(s + j) * DIM + tid];
#pragma unroll
        for (int j = 0; j < 8; j++) acc[hu[j]][tid] += v[j];
    }
    for (; s < ce; s++) acc[hub_idx[s]][tid] += g_hbuf[(size_t)s * DIM + tid];
    __syncthreads();

    float* part = g_part + (size_t)blockIdx.x * (HH * DIM);
    for (int h = 0; h < HH; h++) part[h * DIM + tid] = acc[h][tid];
    if (tid < HH) g_cntp[blockIdx.x * HH + tid] = cnt[tid];
}

// ---------------------------------------------------------------------------
// K2b: finalize — flat parallel, 1 output element per thread (MLP=16)
// ---------------------------------------------------------------------------
__global__ void __launch_bounds__(256)
scatter_finalize(float* __restrict__ hubf_out) {
    const int idx = blockIdx.x * 256 + threadIdx.x;   // 0 .. 1048575
    const int d = idx & 127;
    const int row = idx >> 7;          // b*64 + h
    const int h = row & 63;
    const int b = row >> 6;

    int c = 0;
    float s = 0.f;
#pragma unroll
    for (int p = 0; p < SPLITS; p++) {
        c += __ldg(&g_cntp[(b * SPLITS + p) * HH + h]);
        s += g_part[((size_t)(b * SPLITS + p) * HH + h) * DIM + d];
    }
    hubf_out[idx] = s / (float)max(c, 1);
}

// ---------------------------------------------------------------------------
// K3a: per-graph 64x64 kNN (top-4 min d2, tie-break lower index) -> g_knn
// ---------------------------------------------------------------------------
__global__ void __launch_bounds__(256)
knn_kernel(const float* __restrict__ hubf) {
    __shared__ float hf[HH][DIM + 1];
    __shared__ float d2row[8][HH];

    const int b = blockIdx.x;
    const int tid = threadIdx.x;
    const int warp = tid >> 5, lane = tid & 31;

    for (int i = tid; i < HH * DIM; i += 256) {
        int h = i >> 7, d = i & 127;
        hf[h][d] = hubf[((size_t)b * HH + h) * DIM + d];
    }
    __syncthreads();

    for (int i = warp; i < HH; i += 8) {
        for (int jj = 0; jj < HH; jj += 32) {
            int j = jj + lane;
            float s = 0.f;
#pragma unroll
            for (int d = 0; d < DIM; d++) {
                float diff = hf[i][d] - hf[j][d];
                s = fmaf(diff, diff, s);
            }
            d2row[warp][j] = s;
        }
        float v0 = d2row[warp][lane], v1 = d2row[warp][lane + 32];
        int   i0 = lane,              i1 = lane + 32;
#pragma unroll
        for (int k = 0; k < KK_; k++) {
            float bv; int bi;
            if (v0 < v1 || (v0 == v1 && i0 < i1)) { bv = v0; bi = i0; }
            else                                   { bv = v1; bi = i1; }
#pragma unroll
            for (int off = 16; off; off >>= 1) {
                float ov = __shfl_xor_sync(0xffffffffu, bv, off);
                int   oi = __shfl_xor_sync(0xffffffffu, bi, off);
                if (ov < bv || (ov == bv && oi < bi)) { bv = ov; bi = oi; }
            }
            if (lane == 0) g_knn[(b * HH + i) * KK_ + k] = bi;
            if (i0 == bi) v0 = 3.4e38f;
            if (i1 == bi) v1 = 3.4e38f;
        }
    }
}

// ---------------------------------------------------------------------------
// K3b: edge emit — one spoke per thread, float4 coalesced stores
// ---------------------------------------------------------------------------
__global__ void __launch_bounds__(512)
edge_kernel(const int* __restrict__ hub_idx,
            const int* __restrict__ batch_idx,
            float* __restrict__ e0, float* __restrict__ e1) {
    const int s = blockIdx.x * 512 + threadIdx.x;
    const int b = batch_idx[s];
    const int sh = hub_idx[s];
    const int4 kn = *(const int4*)&g_knn[(b * HH + sh) * KK_];
    const float fs = (float)s;
    const float boff = (float)(b * HH);
    *(float4*)&e0[(size_t)s * 4] = make_float4(fs, fs, fs, fs);
    *(float4*)&e1[(size_t)s * 4] = make_float4(kn.x + boff, kn.y + boff, kn.z + boff, kn.w + boff);
}

// ---------------------------------------------------------------------------
extern "C" void kernel_launch(void* const* d_in, const int* in_sizes, int n_in,
                              void* d_out, int out_size) {
    const float* x   = (const float*)d_in[0];
    const int*   hub = (const int*)d_in[1];
    const int*   bix = (const int*)d_in[2];
    const float* W1  = (const float*)d_in[3];
    const float* b1  = (const float*)d_in[4];
    const float* W2  = (const float*)d_in[5];
    const float* b2  = (const float*)d_in[6];

    float* out  = (float*)d_out;
    float* hubf = out;
    float* e0   = out + HUBF_ELEMS;
    float* e1   = out + HUBF_ELEMS + NK;

    cudaFuncSetAttribute(ffn_mma, cudaFuncAttributeMaxDynamicSharedMemorySize, FFN_SMEM);

    prep_weights<<<64, 256>>>(W1, W2);
    ffn_mma<<<FFN_GRID, 256, FFN_SMEM>>>(x, b1, b2);
    scatter_partial<<<SCAT_GRID, 128>>>(hub, bix);
    scatter_finalize<<<HUBF_ELEMS / 256, 256>>>(hubf);
    knn_kernel<<<BG, 256>>>(hubf);
    edge_kernel<<<NS / 512, 512>>>(hub, bix, e0, e1);
}

// round 7
// speedup vs baseline: 3.4992x; 1.3939x over previous
#include <cuda_runtime.h>
#include <cuda_fp16.h>
#include <cstdint>

#define NS   524288
#define DIM  128
#define BG   128
#define HH   64
#define KK_  4
#define BH   (BG * HH)
#define NK   (NS * KK_)
#define HUBF_ELEMS (BH * DIM)

#define TILES_PER_CTA 4
#define FFN_GRID (NS / 64 / TILES_PER_CTA)   /* 2048 */

// FFN output scratch
__device__ float g_hbuf[(size_t)NS * DIM];
// knn table: [B*H][4] local hub ids
__device__ int   g_knn[BH * KK_];

// Prepped fp16 weights, transposed [n][k], XOR-swizzled
__device__ __half gW1[256 * 128];   // 64KB, row stride 256B
__device__ __half gW2[128 * 256];   // 64KB, row stride 512B

// SMEM layout (ffn): 224KB
#define OFF_W1  0         /* [256][128] fp16, stride 256B */
#define OFF_W2  65536     /* [128][256] fp16, stride 512B */
#define OFF_XH  131072    /* [64][128] fp16 */
#define OFF_XL  147456
#define OFF_H1H 163840    /* [64][256] fp16 */
#define OFF_H1L 196608
#define FFN_SMEM 229376

// ---------------------------------------------------------------------------
__device__ __forceinline__ uint32_t smem_u32(const void* p) {
    uint32_t a;
    asm("{ .reg .u64 t; cvta.to.shared.u64 t, %1; cvt.u32.u64 %0, t; }" : "=r"(a) : "l"(p));
    return a;
}
__device__ __forceinline__ void ldsm4(uint32_t addr, uint32_t r[4]) {
    asm volatile("ldmatrix.sync.aligned.m8n8.x4.shared.b16 {%0,%1,%2,%3}, [%4];"
                 : "=r"(r[0]), "=r"(r[1]), "=r"(r[2]), "=r"(r[3]) : "r"(addr));
}
__device__ __forceinline__ void mma16816(float c[4], const uint32_t a[4], uint32_t b0, uint32_t b1) {
    asm volatile("mma.sync.aligned.m16n8k16.row.col.f32.f16.f16.f32 "
                 "{%0,%1,%2,%3}, {%4,%5,%6,%7}, {%8,%9}, {%0,%1,%2,%3};"
                 : "+f"(c[0]), "+f"(c[1]), "+f"(c[2]), "+f"(c[3])
                 : "r"(a[0]), "r"(a[1]), "r"(a[2]), "r"(a[3]), "r"(b0), "r"(b1));
}
__device__ __forceinline__ uint32_t a_addr(uint32_t base, int stride, int m0, int kb, int lane) {
    int row = m0 + (lane & 15);
    int k = kb + ((lane >> 4) << 4);
    return base + row * stride + (uint32_t)(k ^ ((row & 7) << 4));
}
__device__ __forceinline__ uint32_t b_addr(uint32_t base, int stride, int n0, int kb, int lane) {
    int row = n0 + (lane & 7) + ((lane & 16) >> 1);
    int k = kb + (((lane >> 3) & 1) << 4);
    return base + row * stride + (uint32_t)(k ^ ((row & 7) << 4));
}
__device__ __forceinline__ float gelu_exact(float v) {
    return 0.5f * v * (1.0f + erff(v * 0.7071067811865476f));
}
__device__ __forceinline__ uint32_t pack_h2(__half a, __half b) {
    __half2 t; t.x = a; t.y = b;
    return *(uint32_t*)&t;
}

// ---------------------------------------------------------------------------
// K0: weight prep — fp16 quantize + transpose + XOR swizzle
// ---------------------------------------------------------------------------
__global__ void prep_weights(const float* __restrict__ W1, const float* __restrict__ W2) {
    int tid = threadIdx.x + blockIdx.x * blockDim.x;
    int stride = blockDim.x * gridDim.x;
    for (int i = tid; i < 32768; i += stride) {          // W1: n 256, k 128
        int n = i >> 7, k = i & 127;
        uint32_t off = (uint32_t)(n * 256) + (uint32_t)((k * 2) ^ ((n & 7) << 4));
        *(__half*)((char*)gW1 + off) = __float2half_rn(W1[k * 256 + n]);
    }
    for (int i = tid; i < 32768; i += stride) {          // W2: n 128, k 256
        int n = i >> 8, k = i & 255;
        uint32_t off = (uint32_t)(n * 512) + (uint32_t)((k * 2) ^ ((n & 7) << 4));
        *(__half*)((char*)gW2 + off) = __float2half_rn(W2[k * 128 + n]);
    }
}

// ---------------------------------------------------------------------------
// K1: FFN via mma.sync fp16 — UNCHANGED from R6 (controlled experiment)
// ---------------------------------------------------------------------------
__global__ void __launch_bounds__(256)
ffn_mma(const float* __restrict__ x,
        const float* __restrict__ b1, const float* __restrict__ b2) {
    extern __shared__ char sm[];
    const uint32_t sb = smem_u32(sm);
    const int tid = threadIdx.x;
    const int wid = tid >> 5;
    const int lane = tid & 31;
    const int wm = wid & 1;
    const int wn = wid >> 1;

    {
        const uint4* s1 = (const uint4*)gW1;
        const uint4* s2 = (const uint4*)gW2;
        uint4* d1 = (uint4*)(sm + OFF_W1);
        uint4* d2 = (uint4*)(sm + OFF_W2);
#pragma unroll 4
        for (int i = tid; i < 4096; i += 256) { d1[i] = s1[i]; d2[i] = s2[i]; }
    }

    for (int t = 0; t < TILES_PER_CTA; t++) {
        const size_t rowbase = (size_t)(blockIdx.x * TILES_PER_CTA + t) * 64;

        __syncthreads();

        {
            const float4* xg = (const float4*)(x + rowbase * DIM);
#pragma unroll
            for (int ii = 0; ii < 8; ii++) {
                int i = tid + ii * 256;
                float4 v = xg[i];
                int row = i >> 5, k = (i & 31) * 4;
                __half h0 = __float2half_rn(v.x), h1v = __float2half_rn(v.y);
                __half h2 = __float2half_rn(v.z), h3 = __float2half_rn(v.w);
                __half l0 = __float2half_rn(v.x - __half2float(h0));
                __half l1 = __float2half_rn(v.y - __half2float(h1v));
                __half l2 = __float2half_rn(v.z - __half2float(h2));
                __half l3 = __float2half_rn(v.w - __half2float(h3));
                uint32_t off = (uint32_t)((k * 2) ^ ((row & 7) << 4)) + row * 256;
                *(uint2*)(sm + OFF_XH + off) = make_uint2(pack_h2(h0, h1v), pack_h2(h2, h3));
                *(uint2*)(sm + OFF_XL + off) = make_uint2(pack_h2(l0, l1), pack_h2(l2, l3));
            }
        }
        __syncthreads();

        float acc[2][8][4];
#pragma unroll
        for (int a = 0; a < 2; a++)
#pragma unroll
            for (int b = 0; b < 8; b++)
#pragma unroll
                for (int c = 0; c < 4; c++) acc[a][b][c] = 0.f;

#pragma unroll
        for (int ks = 0; ks < 8; ks++) {
            const int kb = ks * 32;
            uint32_t ah[2][4], al[2][4];
#pragma unroll
            for (int mt = 0; mt < 2; mt++) {
                ldsm4(a_addr(sb + OFF_XH, 256, wm * 32 + mt * 16, kb, lane), ah[mt]);
                ldsm4(a_addr(sb + OFF_XL, 256, wm * 32 + mt * 16, kb, lane), al[mt]);
            }
#pragma unroll
            for (int ntp = 0; ntp < 4; ntp++) {
                const int n0 = wn * 64 + ntp * 16;
                uint32_t bw[4];
                ldsm4(b_addr(sb + OFF_W1, 256, n0, kb, lane), bw);
#pragma unroll
                for (int mt = 0; mt < 2; mt++) {
                    mma16816(acc[mt][ntp * 2],     ah[mt], bw[0], bw[1]);
                    mma16816(acc[mt][ntp * 2],     al[mt], bw[0], bw[1]);
                    mma16816(acc[mt][ntp * 2 + 1], ah[mt], bw[2], bw[3]);
                    mma16816(acc[mt][ntp * 2 + 1], al[mt], bw[2], bw[3]);
                }
            }
        }

#pragma unroll
        for (int nt = 0; nt < 8; nt++) {
            const int col = wn * 64 + nt * 8 + (lane & 3) * 2;
            const float2 bb = *(const float2*)&b1[col];
#pragma unroll
            for (int mt = 0; mt < 2; mt++) {
                const int r = wm * 32 + mt * 16 + (lane >> 2);
#pragma unroll
                for (int h = 0; h < 2; h++) {
                    const int rr = r + h * 8;
                    float v0 = gelu_exact(acc[mt][nt][h * 2]     + bb.x);
                    float v1 = gelu_exact(acc[mt][nt][h * 2 + 1] + bb.y);
                    __half h0 = __float2half_rn(v0), h1v = __float2half_rn(v1);
                    __half l0 = __float2half_rn(v0 - __half2float(h0));
                    __half l1 = __float2half_rn(v1 - __half2float(h1v));
                    uint32_t off = rr * 512 + (uint32_t)((col * 2) ^ ((rr & 7) << 4));
                    *(uint32_t*)(sm + OFF_H1H + off) = pack_h2(h0, h1v);
                    *(uint32_t*)(sm + OFF_H1L + off) = pack_h2(l0, l1);
                }
            }
        }
        __syncthreads();

        float acc2[2][4][4];
#pragma unroll
        for (int a = 0; a < 2; a++)
#pragma unroll
            for (int b = 0; b < 4; b++)
#pragma unroll
                for (int c = 0; c < 4; c++) acc2[a][b][c] = 0.f;

#pragma unroll
        for (int ks = 0; ks < 16; ks++) {
            const int kb = ks * 32;
            uint32_t ah[2][4], al[2][4];
#pragma unroll
            for (int mt = 0; mt < 2; mt++) {
                ldsm4(a_addr(sb + OFF_H1H, 512, wm * 32 + mt * 16, kb, lane), ah[mt]);
                ldsm4(a_addr(sb + OFF_H1L, 512, wm * 32 + mt * 16, kb, lane), al[mt]);
            }
#pragma unroll
            for (int ntp = 0; ntp < 2; ntp++) {
                const int n0 = wn * 32 + ntp * 16;
                uint32_t bw[4];
                ldsm4(b_addr(sb + OFF_W2, 512, n0, kb, lane), bw);
#pragma unroll
                for (int mt = 0; mt < 2; mt++) {
                    mma16816(acc2[mt][ntp * 2],     ah[mt], bw[0], bw[1]);
                    mma16816(acc2[mt][ntp * 2],     al[mt], bw[0], bw[1]);
                    mma16816(acc2[mt][ntp * 2 + 1], ah[mt], bw[2], bw[3]);
                    mma16816(acc2[mt][ntp * 2 + 1], al[mt], bw[2], bw[3]);
                }
            }
        }

#pragma unroll
        for (int nt = 0; nt < 4; nt++) {
            const int col = wn * 32 + nt * 8 + (lane & 3) * 2;
            const float2 bb = *(const float2*)&b2[col];
#pragma unroll
            for (int mt = 0; mt < 2; mt++) {
                const int r = wm * 32 + mt * 16 + (lane >> 2);
#pragma unroll
                for (int h = 0; h < 2; h++) {
                    const int rr = r + h * 8;
                    float2 v = make_float2(acc2[mt][nt][h * 2] + bb.x,
                                           acc2[mt][nt][h * 2 + 1] + bb.y);
                    *(float2*)&g_hbuf[(rowbase + rr) * DIM + col] = v;
                }
            }
        }
    }
}

// ---------------------------------------------------------------------------
// K2: scatter-mean, gather formulation. Block = (graph b, hub-partition p of 8).
// One warp compacts the graph's spoke list into per-hub ordered lists
// (deterministic: preserves ascending spoke order), then half-blocks register-
// accumulate rows per hub (thread = dim, batch-4 loads) and write hubf.
// ---------------------------------------------------------------------------
#define MAXSPG 6144     /* max spokes per graph (mean 4096, 32 sigma) */
#define MAXHL  256      /* max spokes per hub (mean 64, 24 sigma) */

__global__ void __launch_bounds__(256)
scatter_gather(const int* __restrict__ hub_idx,
               const int* __restrict__ batch_idx,
               float* __restrict__ hubf_out) {
    __shared__ int shub[MAXSPG];
    __shared__ int list[8][MAXHL];
    __shared__ int lcnt[8];
    __shared__ int srange[2];

    const int b = blockIdx.x >> 3;
    const int p = blockIdx.x & 7;
    const int tid = threadIdx.x;

    if (tid < 8) lcnt[tid] = 0;
    if (tid < 2) {
        int target = b + tid, lo = 0, hi = NS;
        while (lo < hi) { int mid = (lo + hi) >> 1; if (batch_idx[mid] < target) lo = mid + 1; else hi = mid; }
        srange[tid] = lo;
    }
    __syncthreads();

    const int s0 = srange[0];
    const int n = srange[1] - s0;

    for (int i = tid; i < n; i += 256) shub[i] = hub_idx[s0 + i];
    __syncthreads();

    // warp 0: build ordered per-hub lists for hubs [p*8, p*8+8)
    if (tid < 32) {
        const int h0 = p * 8;
        for (int base = 0; base < n; base += 32) {
            int i = base + tid;
            int h = (i < n) ? shub[i] : -1;
            bool in = (h >= h0) && (h < h0 + 8);
            unsigned mm = __match_any_sync(0xffffffffu, h);
            if (in) {
                int hl = h - h0;
                int rank = __popc(mm & ((1u << tid) - 1u));
                int cnt = __popc(mm);
                int basec = lcnt[hl];
                list[hl][basec + rank] = i;
                if (rank == cnt - 1) lcnt[hl] = basec + cnt;
            }
            __syncwarp();
        }
    }
    __syncthreads();

    // gather: half-block (128 threads) per hub, 4 rounds cover 8 hubs
    const int half = tid >> 7;       // 0 or 1
    const int d = tid & 127;         // dim
#pragma unroll
    for (int hh = 0; hh < 4; hh++) {
        const int hl = hh * 2 + half;
        const int cnt = lcnt[hl];
        float sum = 0.f;
        int j = 0;
        for (; j + 4 <= cnt; j += 4) {
            float v0 = g_hbuf[(size_t)(s0 + list[hl][j])     * DIM + d];
            float v1 = g_hbuf[(size_t)(s0 + list[hl][j + 1]) * DIM + d];
            float v2 = g_hbuf[(size_t)(s0 + list[hl][j + 2]) * DIM + d];
            float v3 = g_hbuf[(size_t)(s0 + list[hl][j + 3]) * DIM + d];
            sum += v0; sum += v1; sum += v2; sum += v3;
        }
        for (; j < cnt; j++) sum += g_hbuf[(size_t)(s0 + list[hl][j]) * DIM + d];
        hubf_out[((size_t)b * HH + p * 8 + hl) * DIM + d] = sum / (float)max(cnt, 1);
    }
}

// ---------------------------------------------------------------------------
// K3a: per-graph 64x64 kNN (top-4 min d2, tie-break lower index) -> g_knn
// ---------------------------------------------------------------------------
__global__ void __launch_bounds__(256)
knn_kernel(const float* __restrict__ hubf) {
    __shared__ float hf[HH][DIM + 1];
    __shared__ float d2row[8][HH];

    const int b = blockIdx.x;
    const int tid = threadIdx.x;
    const int warp = tid >> 5, lane = tid & 31;

    for (int i = tid; i < HH * DIM; i += 256) {
        int h = i >> 7, d = i & 127;
        hf[h][d] = hubf[((size_t)b * HH + h) * DIM + d];
    }
    __syncthreads();

    for (int i = warp; i < HH; i += 8) {
        for (int jj = 0; jj < HH; jj += 32) {
            int j = jj + lane;
            float s = 0.f;
#pragma unroll
            for (int d = 0; d < DIM; d++) {
                float diff = hf[i][d] - hf[j][d];
                s = fmaf(diff, diff, s);
            }
            d2row[warp][j] = s;
        }
        float v0 = d2row[warp][lane], v1 = d2row[warp][lane + 32];
        int   i0 = lane,              i1 = lane + 32;
#pragma unroll
        for (int k = 0; k < KK_; k++) {
            float bv; int bi;
            if (v0 < v1 || (v0 == v1 && i0 < i1)) { bv = v0; bi = i0; }
            else                                   { bv = v1; bi = i1; }
#pragma unroll
            for (int off = 16; off; off >>= 1) {
                float ov = __shfl_xor_sync(0xffffffffu, bv, off);
                int   oi = __shfl_xor_sync(0xffffffffu, bi, off);
                if (ov < bv || (ov == bv && oi < bi)) { bv = ov; bi = oi; }
            }
            if (lane == 0) g_knn[(b * HH + i) * KK_ + k] = bi;
            if (i0 == bi) v0 = 3.4e38f;
            if (i1 == bi) v1 = 3.4e38f;
        }
    }
}

// ---------------------------------------------------------------------------
// K3b: edge emit — one spoke per thread, float4 coalesced stores
// ---------------------------------------------------------------------------
__global__ void __launch_bounds__(512)
edge_kernel(const int* __restrict__ hub_idx,
            const int* __restrict__ batch_idx,
            float* __restrict__ e0, float* __restrict__ e1) {
    const int s = blockIdx.x * 512 + threadIdx.x;
    const int b = batch_idx[s];
    const int sh = hub_idx[s];
    const int4 kn = *(const int4*)&g_knn[(b * HH + sh) * KK_];
    const float fs = (float)s;
    const float boff = (float)(b * HH);
    *(float4*)&e0[(size_t)s * 4] = make_float4(fs, fs, fs, fs);
    *(float4*)&e1[(size_t)s * 4] = make_float4(kn.x + boff, kn.y + boff, kn.z + boff, kn.w + boff);
}

// ---------------------------------------------------------------------------
extern "C" void kernel_launch(void* const* d_in, const int* in_sizes, int n_in,
                              void* d_out, int out_size) {
    const float* x   = (const float*)d_in[0];
    const int*   hub = (const int*)d_in[1];
    const int*   bix = (const int*)d_in[2];
    const float* W1  = (const float*)d_in[3];
    const float* b1  = (const float*)d_in[4];
    const float* W2  = (const float*)d_in[5];
    const float* b2  = (const float*)d_in[6];

    float* out  = (float*)d_out;
    float* hubf = out;
    float* e0   = out + HUBF_ELEMS;
    float* e1   = out + HUBF_ELEMS + NK;

    cudaFuncSetAttribute(ffn_mma, cudaFuncAttributeMaxDynamicSharedMemorySize, FFN_SMEM);

    prep_weights<<<64, 256>>>(W1, W2);
    ffn_mma<<<FFN_GRID, 256, FFN_SMEM>>>(x, b1, b2);
    scatter_gather<<<BG * 8, 256>>>(hub, bix, hubf);
    knn_kernel<<<BG, 256>>>(hubf);
    edge_kernel<<<NS / 512, 512>>>(hub, bix, e0, e1);
}

// round 8
// speedup vs baseline: 4.6675x; 1.3339x over previous
#include <cuda_runtime.h>
#include <cuda_fp16.h>
#include <cstdint>

#define NS   524288
#define DIM  128
#define BG   128
#define HH   64
#define KK_  4
#define BH   (BG * HH)
#define NK   (NS * KK_)
#define HUBF_ELEMS (BH * DIM)

#define TILES_PER_CTA 4
#define FFN_GRID (NS / 64 / TILES_PER_CTA)   /* 2048 */

// FFN output scratch
__device__ float g_hbuf[(size_t)NS * DIM];
// knn table: [B*H][4] local hub ids
__device__ int   g_knn[BH * KK_];

// Prepped fp16 weights, transposed [n][k], XOR-swizzled
__device__ __half gW1[256 * 128];   // 64KB, row stride 256B
__device__ __half gW2[128 * 256];   // 64KB, row stride 512B

// SMEM layout (ffn): 176KB
#define OFF_W1  0         /* [256][128] fp16, stride 256B */
#define OFF_W2  65536     /* [128][256] fp16, stride 512B */
#define OFF_X   131072    /* [64][128] fp16 */
#define OFF_H1  147456    /* [64][256] fp16 */
#define FFN_SMEM 180224

// ---------------------------------------------------------------------------
__device__ __forceinline__ uint32_t smem_u32(const void* p) {
    uint32_t a;
    asm("{ .reg .u64 t; cvta.to.shared.u64 t, %1; cvt.u32.u64 %0, t; }" : "=r"(a) : "l"(p));
    return a;
}
__device__ __forceinline__ void ldsm4(uint32_t addr, uint32_t r[4]) {
    asm volatile("ldmatrix.sync.aligned.m8n8.x4.shared.b16 {%0,%1,%2,%3}, [%4];"
                 : "=r"(r[0]), "=r"(r[1]), "=r"(r[2]), "=r"(r[3]) : "r"(addr));
}
__device__ __forceinline__ void mma16816(float c[4], const uint32_t a[4], uint32_t b0, uint32_t b1) {
    asm volatile("mma.sync.aligned.m16n8k16.row.col.f32.f16.f16.f32 "
                 "{%0,%1,%2,%3}, {%4,%5,%6,%7}, {%8,%9}, {%0,%1,%2,%3};"
                 : "+f"(c[0]), "+f"(c[1]), "+f"(c[2]), "+f"(c[3])
                 : "r"(a[0]), "r"(a[1]), "r"(a[2]), "r"(a[3]), "r"(b0), "r"(b1));
}
__device__ __forceinline__ uint32_t a_addr(uint32_t base, int stride, int m0, int kb, int lane) {
    int row = m0 + (lane & 15);
    int k = kb + ((lane >> 4) << 4);
    return base + row * stride + (uint32_t)(k ^ ((row & 7) << 4));
}
__device__ __forceinline__ uint32_t b_addr(uint32_t base, int stride, int n0, int kb, int lane) {
    int row = n0 + (lane & 7) + ((lane & 16) >> 1);
    int k = kb + (((lane >> 3) & 1) << 4);
    return base + row * stride + (uint32_t)(k ^ ((row & 7) << 4));
}
__device__ __forceinline__ float gelu_exact(float v) {
    return 0.5f * v * (1.0f + erff(v * 0.7071067811865476f));
}
__device__ __forceinline__ uint32_t pack_h2(__half a, __half b) {
    __half2 t; t.x = a; t.y = b;
    return *(uint32_t*)&t;
}

// ---------------------------------------------------------------------------
// K0: weight prep — fp16 quantize + transpose + XOR swizzle
// ---------------------------------------------------------------------------
__global__ void prep_weights(const float* __restrict__ W1, const float* __restrict__ W2) {
    int tid = threadIdx.x + blockIdx.x * blockDim.x;
    int stride = blockDim.x * gridDim.x;
    for (int i = tid; i < 32768; i += stride) {          // W1: n 256, k 128
        int n = i >> 7, k = i & 127;
        uint32_t off = (uint32_t)(n * 256) + (uint32_t)((k * 2) ^ ((n & 7) << 4));
        *(__half*)((char*)gW1 + off) = __float2half_rn(W1[k * 256 + n]);
    }
    for (int i = tid; i < 32768; i += stride) {          // W2: n 128, k 256
        int n = i >> 8, k = i & 255;
        uint32_t off = (uint32_t)(n * 512) + (uint32_t)((k * 2) ^ ((n & 7) << 4));
        *(__half*)((char*)gW2 + off) = __float2half_rn(W2[k * 128 + n]);
    }
}

// ---------------------------------------------------------------------------
// K1: FFN via mma.sync fp16, single plane (x, W, h1 all fp16-rn).
// W1+W2 resident in SMEM. 64 rows/tile, 4 tiles/CTA, 8 warps (2m x 4n).
// ---------------------------------------------------------------------------
__global__ void __launch_bounds__(256)
ffn_mma(const float* __restrict__ x,
        const float* __restrict__ b1, const float* __restrict__ b2) {
    extern __shared__ char sm[];
    const uint32_t sb = smem_u32(sm);
    const int tid = threadIdx.x;
    const int wid = tid >> 5;
    const int lane = tid & 31;
    const int wm = wid & 1;
    const int wn = wid >> 1;

    // load W1+W2 once: 131072 B = 8192 uint4
    {
        const uint4* s1 = (const uint4*)gW1;
        const uint4* s2 = (const uint4*)gW2;
        uint4* d1 = (uint4*)(sm + OFF_W1);
        uint4* d2 = (uint4*)(sm + OFF_W2);
#pragma unroll 4
        for (int i = tid; i < 4096; i += 256) { d1[i] = s1[i]; d2[i] = s2[i]; }
    }

    for (int t = 0; t < TILES_PER_CTA; t++) {
        const size_t rowbase = (size_t)(blockIdx.x * TILES_PER_CTA + t) * 64;

        __syncthreads();   // W ready / previous tile's reads done

        // ---- load x tile [64,128] f32 -> fp16, swizzled ----
        {
            const float4* xg = (const float4*)(x + rowbase * DIM);
#pragma unroll
            for (int ii = 0; ii < 8; ii++) {
                int i = tid + ii * 256;
                float4 v = xg[i];
                int row = i >> 5, k = (i & 31) * 4;
                uint32_t off = (uint32_t)((k * 2) ^ ((row & 7) << 4)) + row * 256;
                *(uint2*)(sm + OFF_X + off) =
                    make_uint2(pack_h2(__float2half_rn(v.x), __float2half_rn(v.y)),
                               pack_h2(__float2half_rn(v.z), __float2half_rn(v.w)));
            }
        }
        __syncthreads();

        // ---- GEMM1: [64,128] x [128,256], warp tile 32x64 ----
        float acc[2][8][4];
#pragma unroll
        for (int a = 0; a < 2; a++)
#pragma unroll
            for (int b = 0; b < 8; b++)
#pragma unroll
                for (int c = 0; c < 4; c++) acc[a][b][c] = 0.f;

#pragma unroll
        for (int ks = 0; ks < 8; ks++) {
            const int kb = ks * 32;
            uint32_t aw[2][4];
#pragma unroll
            for (int mt = 0; mt < 2; mt++)
                ldsm4(a_addr(sb + OFF_X, 256, wm * 32 + mt * 16, kb, lane), aw[mt]);
#pragma unroll
            for (int ntp = 0; ntp < 4; ntp++) {
                const int n0 = wn * 64 + ntp * 16;
                uint32_t bw[4];
                ldsm4(b_addr(sb + OFF_W1, 256, n0, kb, lane), bw);
#pragma unroll
                for (int mt = 0; mt < 2; mt++) {
                    mma16816(acc[mt][ntp * 2],     aw[mt], bw[0], bw[1]);
                    mma16816(acc[mt][ntp * 2 + 1], aw[mt], bw[2], bw[3]);
                }
            }
        }

        // ---- Epilogue 1: +b1, GELU, fp16 -> h1 (smem) ----
#pragma unroll
        for (int nt = 0; nt < 8; nt++) {
            const int col = wn * 64 + nt * 8 + (lane & 3) * 2;
            const float2 bb = *(const float2*)&b1[col];
#pragma unroll
            for (int mt = 0; mt < 2; mt++) {
                const int r = wm * 32 + mt * 16 + (lane >> 2);
#pragma unroll
                for (int h = 0; h < 2; h++) {
                    const int rr = r + h * 8;
                    float v0 = gelu_exact(acc[mt][nt][h * 2]     + bb.x);
                    float v1 = gelu_exact(acc[mt][nt][h * 2 + 1] + bb.y);
                    uint32_t off = rr * 512 + (uint32_t)((col * 2) ^ ((rr & 7) << 4));
                    *(uint32_t*)(sm + OFF_H1 + off) =
                        pack_h2(__float2half_rn(v0), __float2half_rn(v1));
                }
            }
        }
        __syncthreads();

        // ---- GEMM2: [64,256] x [256,128], warp tile 32x32 ----
        float acc2[2][4][4];
#pragma unroll
        for (int a = 0; a < 2; a++)
#pragma unroll
            for (int b = 0; b < 4; b++)
#pragma unroll
                for (int c = 0; c < 4; c++) acc2[a][b][c] = 0.f;

#pragma unroll
        for (int ks = 0; ks < 16; ks++) {
            const int kb = ks * 32;
            uint32_t aw[2][4];
#pragma unroll
            for (int mt = 0; mt < 2; mt++)
                ldsm4(a_addr(sb + OFF_H1, 512, wm * 32 + mt * 16, kb, lane), aw[mt]);
#pragma unroll
            for (int ntp = 0; ntp < 2; ntp++) {
                const int n0 = wn * 32 + ntp * 16;
                uint32_t bw[4];
                ldsm4(b_addr(sb + OFF_W2, 512, n0, kb, lane), bw);
#pragma unroll
                for (int mt = 0; mt < 2; mt++) {
                    mma16816(acc2[mt][ntp * 2],     aw[mt], bw[0], bw[1]);
                    mma16816(acc2[mt][ntp * 2 + 1], aw[mt], bw[2], bw[3]);
                }
            }
        }

        // ---- Epilogue 2: +b2 -> g_hbuf ----
#pragma unroll
        for (int nt = 0; nt < 4; nt++) {
            const int col = wn * 32 + nt * 8 + (lane & 3) * 2;
            const float2 bb = *(const float2*)&b2[col];
#pragma unroll
            for (int mt = 0; mt < 2; mt++) {
                const int r = wm * 32 + mt * 16 + (lane >> 2);
#pragma unroll
                for (int h = 0; h < 2; h++) {
                    const int rr = r + h * 8;
                    float2 v = make_float2(acc2[mt][nt][h * 2] + bb.x,
                                           acc2[mt][nt][h * 2 + 1] + bb.y);
                    *(float2*)&g_hbuf[(rowbase + rr) * DIM + col] = v;
                }
            }
        }
    }
}

// ---------------------------------------------------------------------------
// K2: scatter-mean, gather formulation. Block = (graph b, hub-partition p of 8).
// ---------------------------------------------------------------------------
#define MAXSPG 6144
#define MAXHL  256

__global__ void __launch_bounds__(256)
scatter_gather(const int* __restrict__ hub_idx,
               const int* __restrict__ batch_idx,
               float* __restrict__ hubf_out) {
    __shared__ int shub[MAXSPG];
    __shared__ int list[8][MAXHL];
    __shared__ int lcnt[8];
    __shared__ int srange[2];

    const int b = blockIdx.x >> 3;
    const int p = blockIdx.x & 7;
    const int tid = threadIdx.x;

    if (tid < 8) lcnt[tid] = 0;
    if (tid < 2) {
        int target = b + tid, lo = 0, hi = NS;
        while (lo < hi) { int mid = (lo + hi) >> 1; if (batch_idx[mid] < target) lo = mid + 1; else hi = mid; }
        srange[tid] = lo;
    }
    __syncthreads();

    const int s0 = srange[0];
    const int n = srange[1] - s0;

    for (int i = tid; i < n; i += 256) shub[i] = hub_idx[s0 + i];
    __syncthreads();

    if (tid < 32) {
        const int h0 = p * 8;
        for (int base = 0; base < n; base += 32) {
            int i = base + tid;
            int h = (i < n) ? shub[i] : -1;
            bool in = (h >= h0) && (h < h0 + 8);
            unsigned mm = __match_any_sync(0xffffffffu, h);
            if (in) {
                int hl = h - h0;
                int rank = __popc(mm & ((1u << tid) - 1u));
                int cnt = __popc(mm);
                int basec = lcnt[hl];
                list[hl][basec + rank] = i;
                if (rank == cnt - 1) lcnt[hl] = basec + cnt;
            }
            __syncwarp();
        }
    }
    __syncthreads();

    const int half = tid >> 7;
    const int d = tid & 127;
#pragma unroll
    for (int hh = 0; hh < 4; hh++) {
        const int hl = hh * 2 + half;
        const int cnt = lcnt[hl];
        float sum = 0.f;
        int j = 0;
        for (; j + 4 <= cnt; j += 4) {
            float v0 = g_hbuf[(size_t)(s0 + list[hl][j])     * DIM + d];
            float v1 = g_hbuf[(size_t)(s0 + list[hl][j + 1]) * DIM + d];
            float v2 = g_hbuf[(size_t)(s0 + list[hl][j + 2]) * DIM + d];
            float v3 = g_hbuf[(size_t)(s0 + list[hl][j + 3]) * DIM + d];
            sum += v0; sum += v1; sum += v2; sum += v3;
        }
        for (; j < cnt; j++) sum += g_hbuf[(size_t)(s0 + list[hl][j]) * DIM + d];
        hubf_out[((size_t)b * HH + p * 8 + hl) * DIM + d] = sum / (float)max(cnt, 1);
    }
}

// ---------------------------------------------------------------------------
// K3a: per-graph 64x64 kNN -> g_knn
// ---------------------------------------------------------------------------
__global__ void __launch_bounds__(256)
knn_kernel(const float* __restrict__ hubf) {
    __shared__ float hf[HH][DIM + 1];
    __shared__ float d2row[8][HH];

    const int b = blockIdx.x;
    const int tid = threadIdx.x;
    const int warp = tid >> 5, lane = tid & 31;

    for (int i = tid; i < HH * DIM; i += 256) {
        int h = i >> 7, d = i & 127;
        hf[h][d] = hubf[((size_t)b * HH + h) * DIM + d];
    }
    __syncthreads();

    for (int i = warp; i < HH; i += 8) {
        for (int jj = 0; jj < HH; jj += 32) {
            int j = jj + lane;
            float s = 0.f;
#pragma unroll
            for (int d = 0; d < DIM; d++) {
                float diff = hf[i][d] - hf[j][d];
                s = fmaf(diff, diff, s);
            }
            d2row[warp][j] = s;
        }
        float v0 = d2row[warp][lane], v1 = d2row[warp][lane + 32];
        int   i0 = lane,              i1 = lane + 32;
#pragma unroll
        for (int k = 0; k < KK_; k++) {
            float bv; int bi;
            if (v0 < v1 || (v0 == v1 && i0 < i1)) { bv = v0; bi = i0; }
            else                                   { bv = v1; bi = i1; }
#pragma unroll
            for (int off = 16; off; off >>= 1) {
                float ov = __shfl_xor_sync(0xffffffffu, bv, off);
                int   oi = __shfl_xor_sync(0xffffffffu, bi, off);
                if (ov < bv || (ov == bv && oi < bi)) { bv = ov; bi = oi; }
            }
            if (lane == 0) g_knn[(b * HH + i) * KK_ + k] = bi;
            if (i0 == bi) v0 = 3.4e38f;
            if (i1 == bi) v1 = 3.4e38f;
        }
    }
}

// ---------------------------------------------------------------------------
// K3b: edge emit
// ---------------------------------------------------------------------------
__global__ void __launch_bounds__(512)
edge_kernel(const int* __restrict__ hub_idx,
            const int* __restrict__ batch_idx,
            float* __restrict__ e0, float* __restrict__ e1) {
    const int s = blockIdx.x * 512 + threadIdx.x;
    const int b = batch_idx[s];
    const int sh = hub_idx[s];
    const int4 kn = *(const int4*)&g_knn[(b * HH + sh) * KK_];
    const float fs = (float)s;
    const float boff = (float)(b * HH);
    *(float4*)&e0[(size_t)s * 4] = make_float4(fs, fs, fs, fs);
    *(float4*)&e1[(size_t)s * 4] = make_float4(kn.x + boff, kn.y + boff, kn.z + boff, kn.w + boff);
}

// ---------------------------------------------------------------------------
extern "C" void kernel_launch(void* const* d_in, const int* in_sizes, int n_in,
                              void* d_out, int out_size) {
    const float* x   = (const float*)d_in[0];
    const int*   hub = (const int*)d_in[1];
    const int*   bix = (const int*)d_in[2];
    const float* W1  = (const float*)d_in[3];
    const float* b1  = (const float*)d_in[4];
    const float* W2  = (const float*)d_in[5];
    const float* b2  = (const float*)d_in[6];

    float* out  = (float*)d_out;
    float* hubf = out;
    float* e0   = out + HUBF_ELEMS;
    float* e1   = out + HUBF_ELEMS + NK;

    cudaFuncSetAttribute(ffn_mma, cudaFuncAttributeMaxDynamicSharedMemorySize, FFN_SMEM);

    prep_weights<<<64, 256>>>(W1, W2);
    ffn_mma<<<FFN_GRID, 256, FFN_SMEM>>>(x, b1, b2);
    scatter_gather<<<BG * 8, 256>>>(hub, bix, hubf);
    knn_kernel<<<BG, 256>>>(hubf);
    edge_kernel<<<NS / 512, 512>>>(hub, bix, e0, e1);
}

// round 9
// speedup vs baseline: 5.2046x; 1.1151x over previous
#include <cuda_runtime.h>
#include <cuda_fp16.h>
#include <cstdint>

#define NS   524288
#define DIM  128
#define BG   128
#define HH   64
#define KK_  4
#define BH   (BG * HH)
#define NK   (NS * KK_)
#define HUBF_ELEMS (BH * DIM)

#define TILES_PER_CTA 2
#define FFN_GRID (NS / 128 / TILES_PER_CTA)   /* 2048 */

// FFN output scratch
__device__ float g_hbuf[(size_t)NS * DIM];
// knn table: [B*H][4] local hub ids
__device__ int   g_knn[BH * KK_];

// Prepped fp16 weights, transposed [n][k], XOR-swizzled
__device__ __half gW1[256 * 128];   // 64KB, row stride 256B
__device__ __half gW2[128 * 256];   // 64KB, row stride 512B

// SMEM layout (ffn): 224KB
#define OFF_W1  0         /* [256][128] fp16, stride 256B */
#define OFF_W2  65536     /* [128][256] fp16, stride 512B */
#define OFF_X   131072    /* [128][128] fp16, 32KB */
#define OFF_H1  163840    /* [128][256] fp16, 64KB */
#define FFN_SMEM 229376

// ---------------------------------------------------------------------------
__device__ __forceinline__ uint32_t smem_u32(const void* p) {
    uint32_t a;
    asm("{ .reg .u64 t; cvta.to.shared.u64 t, %1; cvt.u32.u64 %0, t; }" : "=r"(a) : "l"(p));
    return a;
}
__device__ __forceinline__ void ldsm4(uint32_t addr, uint32_t r[4]) {
    asm volatile("ldmatrix.sync.aligned.m8n8.x4.shared.b16 {%0,%1,%2,%3}, [%4];"
                 : "=r"(r[0]), "=r"(r[1]), "=r"(r[2]), "=r"(r[3]) : "r"(addr));
}
__device__ __forceinline__ void mma16816(float c[4], const uint32_t a[4], uint32_t b0, uint32_t b1) {
    asm volatile("mma.sync.aligned.m16n8k16.row.col.f32.f16.f16.f32 "
                 "{%0,%1,%2,%3}, {%4,%5,%6,%7}, {%8,%9}, {%0,%1,%2,%3};"
                 : "+f"(c[0]), "+f"(c[1]), "+f"(c[2]), "+f"(c[3])
                 : "r"(a[0]), "r"(a[1]), "r"(a[2]), "r"(a[3]), "r"(b0), "r"(b1));
}
__device__ __forceinline__ uint32_t a_addr(uint32_t base, int stride, int m0, int kb, int lane) {
    int row = m0 + (lane & 15);
    int k = kb + ((lane >> 4) << 4);
    return base + row * stride + (uint32_t)(k ^ ((row & 7) << 4));
}
__device__ __forceinline__ uint32_t b_addr(uint32_t base, int stride, int n0, int kb, int lane) {
    int row = n0 + (lane & 7) + ((lane & 16) >> 1);
    int k = kb + (((lane >> 3) & 1) << 4);
    return base + row * stride + (uint32_t)(k ^ ((row & 7) << 4));
}
// tanh-form GELU via HW tanh.approx (error ~1e-4 rms, within budget)
__device__ __forceinline__ float gelu_fast(float v) {
    float c = v * fmaf(v * v, 0.044715f, 1.0f) * 0.7978845608f;
    float t;
    asm("tanh.approx.f32 %0, %1;" : "=f"(t) : "f"(c));
    return 0.5f * v * (1.0f + t);
}
__device__ __forceinline__ uint32_t pack_h2(__half a, __half b) {
    __half2 t; t.x = a; t.y = b;
    return *(uint32_t*)&t;
}

// ---------------------------------------------------------------------------
// K0: weight prep — fp16 quantize + transpose + XOR swizzle
// ---------------------------------------------------------------------------
__global__ void prep_weights(const float* __restrict__ W1, const float* __restrict__ W2) {
    int tid = threadIdx.x + blockIdx.x * blockDim.x;
    int stride = blockDim.x * gridDim.x;
    for (int i = tid; i < 32768; i += stride) {          // W1: n 256, k 128
        int n = i >> 7, k = i & 127;
        uint32_t off = (uint32_t)(n * 256) + (uint32_t)((k * 2) ^ ((n & 7) << 4));
        *(__half*)((char*)gW1 + off) = __float2half_rn(W1[k * 256 + n]);
    }
    for (int i = tid; i < 32768; i += stride) {          // W2: n 128, k 256
        int n = i >> 8, k = i & 255;
        uint32_t off = (uint32_t)(n * 512) + (uint32_t)((k * 2) ^ ((n & 7) << 4));
        *(__half*)((char*)gW2 + off) = __float2half_rn(W2[k * 128 + n]);
    }
}

// ---------------------------------------------------------------------------
// K1: FFN via mma.sync fp16, single plane. 512 threads (16 warps, 4m x 4n),
// 128-row tiles, 2 tiles/CTA. W1+W2 resident in SMEM.
// ---------------------------------------------------------------------------
__global__ void __launch_bounds__(512)
ffn_mma(const float* __restrict__ x,
        const float* __restrict__ b1, const float* __restrict__ b2) {
    extern __shared__ char sm[];
    const uint32_t sb = smem_u32(sm);
    const int tid = threadIdx.x;
    const int wid = tid >> 5;
    const int lane = tid & 31;
    const int wm = wid & 3;        // 0-3 (m)
    const int wn = wid >> 2;       // 0-3 (n)

    // load W1+W2 once: 131072 B = 8192 uint4
    {
        const uint4* s1 = (const uint4*)gW1;
        const uint4* s2 = (const uint4*)gW2;
        uint4* d1 = (uint4*)(sm + OFF_W1);
        uint4* d2 = (uint4*)(sm + OFF_W2);
#pragma unroll 4
        for (int i = tid; i < 4096; i += 512) { d1[i] = s1[i]; d2[i] = s2[i]; }
    }

    for (int t = 0; t < TILES_PER_CTA; t++) {
        const size_t rowbase = (size_t)(blockIdx.x * TILES_PER_CTA + t) * 128;

        __syncthreads();   // W ready / previous tile's reads done

        // ---- load x tile [128,128] f32 -> fp16, swizzled ----
        {
            const float4* xg = (const float4*)(x + rowbase * DIM);
#pragma unroll
            for (int ii = 0; ii < 8; ii++) {
                int i = tid + ii * 512;
                float4 v = xg[i];
                int row = i >> 5, k = (i & 31) * 4;
                uint32_t off = (uint32_t)((k * 2) ^ ((row & 7) << 4)) + row * 256;
                *(uint2*)(sm + OFF_X + off) =
                    make_uint2(pack_h2(__float2half_rn(v.x), __float2half_rn(v.y)),
                               pack_h2(__float2half_rn(v.z), __float2half_rn(v.w)));
            }
        }
        __syncthreads();

        // ---- GEMM1: [128,128] x [128,256], warp tile 32x64 ----
        float acc[2][8][4];
#pragma unroll
        for (int a = 0; a < 2; a++)
#pragma unroll
            for (int b = 0; b < 8; b++)
#pragma unroll
                for (int c = 0; c < 4; c++) acc[a][b][c] = 0.f;

#pragma unroll
        for (int ks = 0; ks < 8; ks++) {
            const int kb = ks * 32;
            uint32_t aw[2][4];
#pragma unroll
            for (int mt = 0; mt < 2; mt++)
                ldsm4(a_addr(sb + OFF_X, 256, wm * 32 + mt * 16, kb, lane), aw[mt]);
#pragma unroll
            for (int ntp = 0; ntp < 4; ntp++) {
                const int n0 = wn * 64 + ntp * 16;
                uint32_t bw[4];
                ldsm4(b_addr(sb + OFF_W1, 256, n0, kb, lane), bw);
#pragma unroll
                for (int mt = 0; mt < 2; mt++) {
                    mma16816(acc[mt][ntp * 2],     aw[mt], bw[0], bw[1]);
                    mma16816(acc[mt][ntp * 2 + 1], aw[mt], bw[2], bw[3]);
                }
            }
        }

        // ---- Epilogue 1: +b1, GELU(tanh HW), fp16 -> h1 (smem) ----
#pragma unroll
        for (int nt = 0; nt < 8; nt++) {
            const int col = wn * 64 + nt * 8 + (lane & 3) * 2;
            const float2 bb = *(const float2*)&b1[col];
#pragma unroll
            for (int mt = 0; mt < 2; mt++) {
                const int r = wm * 32 + mt * 16 + (lane >> 2);
#pragma unroll
                for (int h = 0; h < 2; h++) {
                    const int rr = r + h * 8;
                    float v0 = gelu_fast(acc[mt][nt][h * 2]     + bb.x);
                    float v1 = gelu_fast(acc[mt][nt][h * 2 + 1] + bb.y);
                    uint32_t off = rr * 512 + (uint32_t)((col * 2) ^ ((rr & 7) << 4));
                    *(uint32_t*)(sm + OFF_H1 + off) =
                        pack_h2(__float2half_rn(v0), __float2half_rn(v1));
                }
            }
        }
        __syncthreads();

        // ---- GEMM2: [128,256] x [256,128], warp tile 32x32 ----
        float acc2[2][4][4];
#pragma unroll
        for (int a = 0; a < 2; a++)
#pragma unroll
            for (int b = 0; b < 4; b++)
#pragma unroll
                for (int c = 0; c < 4; c++) acc2[a][b][c] = 0.f;

#pragma unroll
        for (int ks = 0; ks < 16; ks++) {
            const int kb = ks * 32;
            uint32_t aw[2][4];
#pragma unroll
            for (int mt = 0; mt < 2; mt++)
                ldsm4(a_addr(sb + OFF_H1, 512, wm * 32 + mt * 16, kb, lane), aw[mt]);
#pragma unroll
            for (int ntp = 0; ntp < 2; ntp++) {
                const int n0 = wn * 32 + ntp * 16;
                uint32_t bw[4];
                ldsm4(b_addr(sb + OFF_W2, 512, n0, kb, lane), bw);
#pragma unroll
                for (int mt = 0; mt < 2; mt++) {
                    mma16816(acc2[mt][ntp * 2],     aw[mt], bw[0], bw[1]);
                    mma16816(acc2[mt][ntp * 2 + 1], aw[mt], bw[2], bw[3]);
                }
            }
        }

        // ---- Epilogue 2: +b2 -> g_hbuf ----
#pragma unroll
        for (int nt = 0; nt < 4; nt++) {
            const int col = wn * 32 + nt * 8 + (lane & 3) * 2;
            const float2 bb = *(const float2*)&b2[col];
#pragma unroll
            for (int mt = 0; mt < 2; mt++) {
                const int r = wm * 32 + mt * 16 + (lane >> 2);
#pragma unroll
                for (int h = 0; h < 2; h++) {
                    const int rr = r + h * 8;
                    float2 v = make_float2(acc2[mt][nt][h * 2] + bb.x,
                                           acc2[mt][nt][h * 2 + 1] + bb.y);
                    *(float2*)&g_hbuf[(rowbase + rr) * DIM + col] = v;
                }
            }
        }
    }
}

// ---------------------------------------------------------------------------
// K2: scatter-mean, gather formulation. Block = (graph b, hub-partition p of 8).
// ---------------------------------------------------------------------------
#define MAXSPG 6144
#define MAXHL  256

__global__ void __launch_bounds__(256)
scatter_gather(const int* __restrict__ hub_idx,
               const int* __restrict__ batch_idx,
               float* __restrict__ hubf_out) {
    __shared__ int shub[MAXSPG];
    __shared__ int list[8][MAXHL];
    __shared__ int lcnt[8];
    __shared__ int srange[2];

    const int b = blockIdx.x >> 3;
    const int p = blockIdx.x & 7;
    const int tid = threadIdx.x;

    if (tid < 8) lcnt[tid] = 0;
    if (tid < 2) {
        int target = b + tid, lo = 0, hi = NS;
        while (lo < hi) { int mid = (lo + hi) >> 1; if (batch_idx[mid] < target) lo = mid + 1; else hi = mid; }
        srange[tid] = lo;
    }
    __syncthreads();

    const int s0 = srange[0];
    const int n = srange[1] - s0;

    for (int i = tid; i < n; i += 256) shub[i] = hub_idx[s0 + i];
    __syncthreads();

    if (tid < 32) {
        const int h0 = p * 8;
        for (int base = 0; base < n; base += 32) {
            int i = base + tid;
            int h = (i < n) ? shub[i] : -1;
            bool in = (h >= h0) && (h < h0 + 8);
            unsigned mm = __match_any_sync(0xffffffffu, h);
            if (in) {
                int hl = h - h0;
                int rank = __popc(mm & ((1u << tid) - 1u));
                int cnt = __popc(mm);
                int basec = lcnt[hl];
                list[hl][basec + rank] = i;
                if (rank == cnt - 1) lcnt[hl] = basec + cnt;
            }
            __syncwarp();
        }
    }
    __syncthreads();

    const int half = tid >> 7;
    const int d = tid & 127;
#pragma unroll
    for (int hh = 0; hh < 4; hh++) {
        const int hl = hh * 2 + half;
        const int cnt = lcnt[hl];
        float sum = 0.f;
        int j = 0;
        for (; j + 4 <= cnt; j += 4) {
            float v0 = g_hbuf[(size_t)(s0 + list[hl][j])     * DIM + d];
            float v1 = g_hbuf[(size_t)(s0 + list[hl][j + 1]) * DIM + d];
            float v2 = g_hbuf[(size_t)(s0 + list[hl][j + 2]) * DIM + d];
            float v3 = g_hbuf[(size_t)(s0 + list[hl][j + 3]) * DIM + d];
            sum += v0; sum += v1; sum += v2; sum += v3;
        }
        for (; j < cnt; j++) sum += g_hbuf[(size_t)(s0 + list[hl][j]) * DIM + d];
        hubf_out[((size_t)b * HH + p * 8 + hl) * DIM + d] = sum / (float)max(cnt, 1);
    }
}

// ---------------------------------------------------------------------------
// K3a: per-graph 64x64 kNN -> g_knn
// ---------------------------------------------------------------------------
__global__ void __launch_bounds__(256)
knn_kernel(const float* __restrict__ hubf) {
    __shared__ float hf[HH][DIM + 1];
    __shared__ float d2row[8][HH];

    const int b = blockIdx.x;
    const int tid = threadIdx.x;
    const int warp = tid >> 5, lane = tid & 31;

    for (int i = tid; i < HH * DIM; i += 256) {
        int h = i >> 7, d = i & 127;
        hf[h][d] = hubf[((size_t)b * HH + h) * DIM + d];
    }
    __syncthreads();

    for (int i = warp; i < HH; i += 8) {
        for (int jj = 0; jj < HH; jj += 32) {
            int j = jj + lane;
            float s = 0.f;
#pragma unroll
            for (int d = 0; d < DIM; d++) {
                float diff = hf[i][d] - hf[j][d];
                s = fmaf(diff, diff, s);
            }
            d2row[warp][j] = s;
        }
        float v0 = d2row[warp][lane], v1 = d2row[warp][lane + 32];
        int   i0 = lane,              i1 = lane + 32;
#pragma unroll
        for (int k = 0; k < KK_; k++) {
            float bv; int bi;
            if (v0 < v1 || (v0 == v1 && i0 < i1)) { bv = v0; bi = i0; }
            else                                   { bv = v1; bi = i1; }
#pragma unroll
            for (int off = 16; off; off >>= 1) {
                float ov = __shfl_xor_sync(0xffffffffu, bv, off);
                int   oi = __shfl_xor_sync(0xffffffffu, bi, off);
                if (ov < bv || (ov == bv && oi < bi)) { bv = ov; bi = oi; }
            }
            if (lane == 0) g_knn[(b * HH + i) * KK_ + k] = bi;
            if (i0 == bi) v0 = 3.4e38f;
            if (i1 == bi) v1 = 3.4e38f;
        }
    }
}

// ---------------------------------------------------------------------------
// K3b: edge emit
// ---------------------------------------------------------------------------
__global__ void __launch_bounds__(512)
edge_kernel(const int* __restrict__ hub_idx,
            const int* __restrict__ batch_idx,
            float* __restrict__ e0, float* __restrict__ e1) {
    const int s = blockIdx.x * 512 + threadIdx.x;
    const int b = batch_idx[s];
    const int sh = hub_idx[s];
    const int4 kn = *(const int4*)&g_knn[(b * HH + sh) * KK_];
    const float fs = (float)s;
    const float boff = (float)(b * HH);
    *(float4*)&e0[(size_t)s * 4] = make_float4(fs, fs, fs, fs);
    *(float4*)&e1[(size_t)s * 4] = make_float4(kn.x + boff, kn.y + boff, kn.z + boff, kn.w + boff);
}

// ---------------------------------------------------------------------------
extern "C" void kernel_launch(void* const* d_in, const int* in_sizes, int n_in,
                              void* d_out, int out_size) {
    const float* x   = (const float*)d_in[0];
    const int*   hub = (const int*)d_in[1];
    const int*   bix = (const int*)d_in[2];
    const float* W1  = (const float*)d_in[3];
    const float* b1  = (const float*)d_in[4];
    const float* W2  = (const float*)d_in[5];
    const float* b2  = (const float*)d_in[6];

    float* out  = (float*)d_out;
    float* hubf = out;
    float* e0   = out + HUBF_ELEMS;
    float* e1   = out + HUBF_ELEMS + NK;

    cudaFuncSetAttribute(ffn_mma, cudaFuncAttributeMaxDynamicSharedMemorySize, FFN_SMEM);

    prep_weights<<<64, 256>>>(W1, W2);
    ffn_mma<<<FFN_GRID, 512, FFN_SMEM>>>(x, b1, b2);
    scatter_gather<<<BG * 8, 256>>>(hub, bix, hubf);
    knn_kernel<<<BG, 256>>>(hubf);
    edge_kernel<<<NS / 512, 512>>>(hub, bix, e0, e1);
}

// round 10
// speedup vs baseline: 5.3893x; 1.0355x over previous
#include <cuda_runtime.h>
#include <cuda_fp16.h>
#include <cstdint>

#define NS   524288
#define DIM  128
#define BG   128
#define HH   64
#define KK_  4
#define BH   (BG * HH)
#define NK   (NS * KK_)
#define HUBF_ELEMS (BH * DIM)

#define TILES_PER_CTA 2
#define FFN_GRID (NS / 128 / TILES_PER_CTA)   /* 2048 */

// FFN output scratch (fp16 — consumed only by scatter-mean, noise averages out)
__device__ __half g_hbufh[(size_t)NS * DIM];

// Prepped fp16 weights, transposed [n][k], XOR-swizzled
__device__ __half gW1[256 * 128];   // 64KB, row stride 256B
__device__ __half gW2[128 * 256];   // 64KB, row stride 512B

// SMEM layout (ffn): 224KB
#define OFF_W1  0         /* [256][128] fp16, stride 256B */
#define OFF_W2  65536     /* [128][256] fp16, stride 512B */
#define OFF_X   131072    /* [128][128] fp16, 32KB */
#define OFF_H1  163840    /* [128][256] fp16, 64KB */
#define FFN_SMEM 229376

// ---------------------------------------------------------------------------
__device__ __forceinline__ uint32_t smem_u32(const void* p) {
    uint32_t a;
    asm("{ .reg .u64 t; cvta.to.shared.u64 t, %1; cvt.u32.u64 %0, t; }" : "=r"(a) : "l"(p));
    return a;
}
__device__ __forceinline__ void ldsm4(uint32_t addr, uint32_t r[4]) {
    asm volatile("ldmatrix.sync.aligned.m8n8.x4.shared.b16 {%0,%1,%2,%3}, [%4];"
                 : "=r"(r[0]), "=r"(r[1]), "=r"(r[2]), "=r"(r[3]) : "r"(addr));
}
__device__ __forceinline__ void mma16816(float c[4], const uint32_t a[4], uint32_t b0, uint32_t b1) {
    asm volatile("mma.sync.aligned.m16n8k16.row.col.f32.f16.f16.f32 "
                 "{%0,%1,%2,%3}, {%4,%5,%6,%7}, {%8,%9}, {%0,%1,%2,%3};"
                 : "+f"(c[0]), "+f"(c[1]), "+f"(c[2]), "+f"(c[3])
                 : "r"(a[0]), "r"(a[1]), "r"(a[2]), "r"(a[3]), "r"(b0), "r"(b1));
}
__device__ __forceinline__ uint32_t a_addr(uint32_t base, int stride, int m0, int kb, int lane) {
    int row = m0 + (lane & 15);
    int k = kb + ((lane >> 4) << 4);
    return base + row * stride + (uint32_t)(k ^ ((row & 7) << 4));
}
__device__ __forceinline__ uint32_t b_addr(uint32_t base, int stride, int n0, int kb, int lane) {
    int row = n0 + (lane & 7) + ((lane & 16) >> 1);
    int k = kb + (((lane >> 3) & 1) << 4);
    return base + row * stride + (uint32_t)(k ^ ((row & 7) << 4));
}
__device__ __forceinline__ float gelu_fast(float v) {
    float c = v * fmaf(v * v, 0.044715f, 1.0f) * 0.7978845608f;
    float t;
    asm("tanh.approx.f32 %0, %1;" : "=f"(t) : "f"(c));
    return 0.5f * v * (1.0f + t);
}
__device__ __forceinline__ uint32_t pack_h2(__half a, __half b) {
    __half2 t; t.x = a; t.y = b;
    return *(uint32_t*)&t;
}

// ---------------------------------------------------------------------------
// K0: weight prep — fp16 quantize + transpose + XOR swizzle
// ---------------------------------------------------------------------------
__global__ void prep_weights(const float* __restrict__ W1, const float* __restrict__ W2) {
    int tid = threadIdx.x + blockIdx.x * blockDim.x;
    int stride = blockDim.x * gridDim.x;
    for (int i = tid; i < 32768; i += stride) {          // W1: n 256, k 128
        int n = i >> 7, k = i & 127;
        uint32_t off = (uint32_t)(n * 256) + (uint32_t)((k * 2) ^ ((n & 7) << 4));
        *(__half*)((char*)gW1 + off) = __float2half_rn(W1[k * 256 + n]);
    }
    for (int i = tid; i < 32768; i += stride) {          // W2: n 128, k 256
        int n = i >> 8, k = i & 255;
        uint32_t off = (uint32_t)(n * 512) + (uint32_t)((k * 2) ^ ((n & 7) << 4));
        *(__half*)((char*)gW2 + off) = __float2half_rn(W2[k * 128 + n]);
    }
}

// ---------------------------------------------------------------------------
// K1: FFN via mma.sync fp16. 512 threads (16 warps, 4m x 4n), 128-row tiles,
// 2 tiles/CTA. W1+W2 resident. Next-tile x register-prefetched during GEMM2.
// ---------------------------------------------------------------------------
__global__ void __launch_bounds__(512)
ffn_mma(const float* __restrict__ x,
        const float* __restrict__ b1, const float* __restrict__ b2) {
    extern __shared__ char sm[];
    const uint32_t sb = smem_u32(sm);
    const int tid = threadIdx.x;
    const int wid = tid >> 5;
    const int lane = tid & 31;
    const int wm = wid & 3;
    const int wn = wid >> 2;

    // load W1+W2 once
    {
        const uint4* s1 = (const uint4*)gW1;
        const uint4* s2 = (const uint4*)gW2;
        uint4* d1 = (uint4*)(sm + OFF_W1);
        uint4* d2 = (uint4*)(sm + OFF_W2);
#pragma unroll 4
        for (int i = tid; i < 4096; i += 512) { d1[i] = s1[i]; d2[i] = s2[i]; }
    }

    // prefetch tile 0 x into registers
    float4 xr[8];
    {
        const float4* xg = (const float4*)(x + (size_t)blockIdx.x * TILES_PER_CTA * 128 * DIM);
#pragma unroll
        for (int ii = 0; ii < 8; ii++) xr[ii] = xg[tid + ii * 512];
    }

    for (int t = 0; t < TILES_PER_CTA; t++) {
        const size_t rowbase = (size_t)(blockIdx.x * TILES_PER_CTA + t) * 128;

        __syncthreads();   // W ready / previous tile's X+H1 reads done

        // ---- convert prefetched x regs -> fp16 smem, swizzled ----
#pragma unroll
        for (int ii = 0; ii < 8; ii++) {
            int i = tid + ii * 512;
            float4 v = xr[ii];
            int row = i >> 5, k = (i & 31) * 4;
            uint32_t off = (uint32_t)((k * 2) ^ ((row & 7) << 4)) + row * 256;
            *(uint2*)(sm + OFF_X + off) =
                make_uint2(pack_h2(__float2half_rn(v.x), __float2half_rn(v.y)),
                           pack_h2(__float2half_rn(v.z), __float2half_rn(v.w)));
        }
        __syncthreads();

        // ---- GEMM1: [128,128] x [128,256], warp tile 32x64 ----
        float acc[2][8][4];
#pragma unroll
        for (int a = 0; a < 2; a++)
#pragma unroll
            for (int b = 0; b < 8; b++)
#pragma unroll
                for (int c = 0; c < 4; c++) acc[a][b][c] = 0.f;

#pragma unroll
        for (int ks = 0; ks < 8; ks++) {
            const int kb = ks * 32;
            uint32_t aw[2][4];
#pragma unroll
            for (int mt = 0; mt < 2; mt++)
                ldsm4(a_addr(sb + OFF_X, 256, wm * 32 + mt * 16, kb, lane), aw[mt]);
#pragma unroll
            for (int ntp = 0; ntp < 4; ntp++) {
                const int n0 = wn * 64 + ntp * 16;
                uint32_t bw[4];
                ldsm4(b_addr(sb + OFF_W1, 256, n0, kb, lane), bw);
#pragma unroll
                for (int mt = 0; mt < 2; mt++) {
                    mma16816(acc[mt][ntp * 2],     aw[mt], bw[0], bw[1]);
                    mma16816(acc[mt][ntp * 2 + 1], aw[mt], bw[2], bw[3]);
                }
            }
        }

        // ---- Epilogue 1: +b1, GELU, fp16 -> h1 ----
#pragma unroll
        for (int nt = 0; nt < 8; nt++) {
            const int col = wn * 64 + nt * 8 + (lane & 3) * 2;
            const float2 bb = *(const float2*)&b1[col];
#pragma unroll
            for (int mt = 0; mt < 2; mt++) {
                const int r = wm * 32 + mt * 16 + (lane >> 2);
#pragma unroll
                for (int h = 0; h < 2; h++) {
                    const int rr = r + h * 8;
                    float v0 = gelu_fast(acc[mt][nt][h * 2]     + bb.x);
                    float v1 = gelu_fast(acc[mt][nt][h * 2 + 1] + bb.y);
                    uint32_t off = rr * 512 + (uint32_t)((col * 2) ^ ((rr & 7) << 4));
                    *(uint32_t*)(sm + OFF_H1 + off) =
                        pack_h2(__float2half_rn(v0), __float2half_rn(v1));
                }
            }
        }
        __syncthreads();

        // ---- prefetch next tile's x (overlaps with GEMM2) ----
        if (t + 1 < TILES_PER_CTA) {
            const float4* xg = (const float4*)(x + (rowbase + 128) * DIM);
#pragma unroll
            for (int ii = 0; ii < 8; ii++) xr[ii] = xg[tid + ii * 512];
        }

        // ---- GEMM2: [128,256] x [256,128], warp tile 32x32 ----
        float acc2[2][4][4];
#pragma unroll
        for (int a = 0; a < 2; a++)
#pragma unroll
            for (int b = 0; b < 4; b++)
#pragma unroll
                for (int c = 0; c < 4; c++) acc2[a][b][c] = 0.f;

#pragma unroll
        for (int ks = 0; ks < 16; ks++) {
            const int kb = ks * 32;
            uint32_t aw[2][4];
#pragma unroll
            for (int mt = 0; mt < 2; mt++)
                ldsm4(a_addr(sb + OFF_H1, 512, wm * 32 + mt * 16, kb, lane), aw[mt]);
#pragma unroll
            for (int ntp = 0; ntp < 2; ntp++) {
                const int n0 = wn * 32 + ntp * 16;
                uint32_t bw[4];
                ldsm4(b_addr(sb + OFF_W2, 512, n0, kb, lane), bw);
#pragma unroll
                for (int mt = 0; mt < 2; mt++) {
                    mma16816(acc2[mt][ntp * 2],     aw[mt], bw[0], bw[1]);
                    mma16816(acc2[mt][ntp * 2 + 1], aw[mt], bw[2], bw[3]);
                }
            }
        }

        // ---- Epilogue 2: +b2 -> g_hbufh (fp16) ----
#pragma unroll
        for (int nt = 0; nt < 4; nt++) {
            const int col = wn * 32 + nt * 8 + (lane & 3) * 2;
            const float2 bb = *(const float2*)&b2[col];
#pragma unroll
            for (int mt = 0; mt < 2; mt++) {
                const int r = wm * 32 + mt * 16 + (lane >> 2);
#pragma unroll
                for (int h = 0; h < 2; h++) {
                    const int rr = r + h * 8;
                    *(uint32_t*)&g_hbufh[(rowbase + rr) * DIM + col] =
                        pack_h2(__float2half_rn(acc2[mt][nt][h * 2] + bb.x),
                                __float2half_rn(acc2[mt][nt][h * 2 + 1] + bb.y));
                }
            }
        }
    }
}

// ---------------------------------------------------------------------------
// K2: scatter-mean, gather formulation (fp16 h reads).
// ---------------------------------------------------------------------------
#define MAXSPG 6144
#define MAXHL  256

__global__ void __launch_bounds__(256)
scatter_gather(const int* __restrict__ hub_idx,
               const int* __restrict__ batch_idx,
               float* __restrict__ hubf_out) {
    __shared__ int shub[MAXSPG];
    __shared__ int list[8][MAXHL];
    __shared__ int lcnt[8];
    __shared__ int srange[2];

    const int b = blockIdx.x >> 3;
    const int p = blockIdx.x & 7;
    const int tid = threadIdx.x;

    if (tid < 8) lcnt[tid] = 0;
    if (tid < 2) {
        int target = b + tid, lo = 0, hi = NS;
        while (lo < hi) { int mid = (lo + hi) >> 1; if (batch_idx[mid] < target) lo = mid + 1; else hi = mid; }
        srange[tid] = lo;
    }
    __syncthreads();

    const int s0 = srange[0];
    const int n = srange[1] - s0;

    for (int i = tid; i < n; i += 256) shub[i] = hub_idx[s0 + i];
    __syncthreads();

    if (tid < 32) {
        const int h0 = p * 8;
        for (int base = 0; base < n; base += 32) {
            int i = base + tid;
            int h = (i < n) ? shub[i] : -1;
            bool in = (h >= h0) && (h < h0 + 8);
            unsigned mm = __match_any_sync(0xffffffffu, h);
            if (in) {
                int hl = h - h0;
                int rank = __popc(mm & ((1u << tid) - 1u));
                int cnt = __popc(mm);
                int basec = lcnt[hl];
                list[hl][basec + rank] = i;
                if (rank == cnt - 1) lcnt[hl] = basec + cnt;
            }
            __syncwarp();
        }
    }
    __syncthreads();

    const int half = tid >> 7;
    const int d = tid & 127;
#pragma unroll
    for (int hh = 0; hh < 4; hh++) {
        const int hl = hh * 2 + half;
        const int cnt = lcnt[hl];
        float sum = 0.f;
        int j = 0;
        for (; j + 4 <= cnt; j += 4) {
            float v0 = __half2float(g_hbufh[(size_t)(s0 + list[hl][j])     * DIM + d]);
            float v1 = __half2float(g_hbufh[(size_t)(s0 + list[hl][j + 1]) * DIM + d]);
            float v2 = __half2float(g_hbufh[(size_t)(s0 + list[hl][j + 2]) * DIM + d]);
            float v3 = __half2float(g_hbufh[(size_t)(s0 + list[hl][j + 3]) * DIM + d]);
            sum += v0; sum += v1; sum += v2; sum += v3;
        }
        for (; j < cnt; j++) sum += __half2float(g_hbufh[(size_t)(s0 + list[hl][j]) * DIM + d]);
        hubf_out[((size_t)b * HH + p * 8 + hl) * DIM + d] = sum / (float)max(cnt, 1);
    }
}

// ---------------------------------------------------------------------------
// K3: per-graph 64x64 kNN + fused edge emission
// ---------------------------------------------------------------------------
__global__ void __launch_bounds__(256)
knn_edge_kernel(const int* __restrict__ hub_idx,
                const int* __restrict__ batch_idx,
                const float* __restrict__ hubf,
                float* __restrict__ e0, float* __restrict__ e1) {
    __shared__ float hf[HH][DIM + 1];
    __shared__ float d2row[8][HH];
    __shared__ int sknn[HH][KK_];
    __shared__ int srange[2];

    const int b = blockIdx.x;
    const int tid = threadIdx.x;
    const int warp = tid >> 5, lane = tid & 31;

    for (int i = tid; i < HH * DIM; i += 256) {
        int h = i >> 7, d = i & 127;
        hf[h][d] = hubf[((size_t)b * HH + h) * DIM + d];
    }
    if (tid < 2) {
        int target = b + tid, lo = 0, hi = NS;
        while (lo < hi) { int mid = (lo + hi) >> 1; if (batch_idx[mid] < target) lo = mid + 1; else hi = mid; }
        srange[tid] = lo;
    }
    __syncthreads();

    for (int i = warp; i < HH; i += 8) {
        for (int jj = 0; jj < HH; jj += 32) {
            int j = jj + lane;
            float s = 0.f;
#pragma unroll
            for (int d = 0; d < DIM; d++) {
                float diff = hf[i][d] - hf[j][d];
                s = fmaf(diff, diff, s);
            }
            d2row[warp][j] = s;
        }
        float v0 = d2row[warp][lane], v1 = d2row[warp][lane + 32];
        int   i0 = lane,              i1 = lane + 32;
#pragma unroll
        for (int k = 0; k < KK_; k++) {
            float bv; int bi;
            if (v0 < v1 || (v0 == v1 && i0 < i1)) { bv = v0; bi = i0; }
            else                                   { bv = v1; bi = i1; }
#pragma unroll
            for (int off = 16; off; off >>= 1) {
                float ov = __shfl_xor_sync(0xffffffffu, bv, off);
                int   oi = __shfl_xor_sync(0xffffffffu, bi, off);
                if (ov < bv || (ov == bv && oi < bi)) { bv = ov; bi = oi; }
            }
            if (lane == 0) sknn[i][k] = bi;
            if (i0 == bi) v0 = 3.4e38f;
            if (i1 == bi) v1 = 3.4e38f;
        }
    }
    __syncthreads();

    // fused edge emission for this graph's spokes
    const int s0 = srange[0], s1 = srange[1];
    const float boff = (float)(b * HH);
    for (int s = s0 + tid; s < s1; s += 256) {
        const int sh = hub_idx[s];
        const float fs = (float)s;
        const int4 kn = *(const int4*)&sknn[sh][0];
        *(float4*)&e0[(size_t)s * 4] = make_float4(fs, fs, fs, fs);
        *(float4*)&e1[(size_t)s * 4] = make_float4(kn.x + boff, kn.y + boff, kn.z + boff, kn.w + boff);
    }
}

// ---------------------------------------------------------------------------
extern "C" void kernel_launch(void* const* d_in, const int* in_sizes, int n_in,
                              void* d_out, int out_size) {
    const float* x   = (const float*)d_in[0];
    const int*   hub = (const int*)d_in[1];
    const int*   bix = (const int*)d_in[2];
    const float* W1  = (const float*)d_in[3];
    const float* b1  = (const float*)d_in[4];
    const float* W2  = (const float*)d_in[5];
    const float* b2  = (const float*)d_in[6];

    float* out  = (float*)d_out;
    float* hubf = out;
    float* e0   = out + HUBF_ELEMS;
    float* e1   = out + HUBF_ELEMS + NK;

    cudaFuncSetAttribute(ffn_mma, cudaFuncAttributeMaxDynamicSharedMemorySize, FFN_SMEM);

    prep_weights<<<64, 256>>>(W1, W2);
    ffn_mma<<<FFN_GRID, 512, FFN_SMEM>>>(x, b1, b2);
    scatter_gather<<<BG * 8, 256>>>(hub, bix, hubf);
    knn_edge_kernel<<<BG, 256>>>(hub, bix, hubf, e0, e1);
}

// round 11
// speedup vs baseline: 5.6780x; 1.0536x over previous
#include <cuda_runtime.h>
#include <cuda_fp16.h>
#include <cstdint>

#define NS   524288
#define DIM  128
#define BG   128
#define HH   64
#define KK_  4
#define BH   (BG * HH)
#define NK   (NS * KK_)
#define HUBF_ELEMS (BH * DIM)

#define TILES_PER_HALF 2
#define FFN_GRID (NS / 256)     /* 2048: each CTA does 4x64-row tiles (2 per half) */

// FFN output scratch (fp16)
__device__ __half g_hbufh[(size_t)NS * DIM];

// Prepped fp16 weights, transposed [n][k], XOR-swizzled
__device__ __half gW1[256 * 128];   // 64KB, row stride 256B
__device__ __half gW2[128 * 256];   // 64KB, row stride 512B

// SMEM layout (ffn): 224KB
#define OFF_W1  0          /* [256][128] fp16, stride 256B, shared */
#define OFF_W2  65536      /* [128][256] fp16, stride 512B, shared */
#define OFF_X   131072     /* per-half [64][128] fp16: +half*16384 */
#define OFF_H1  163840     /* per-half [64][256] fp16: +half*32768 */
#define FFN_SMEM 229376

// ---------------------------------------------------------------------------
__device__ __forceinline__ uint32_t smem_u32(const void* p) {
    uint32_t a;
    asm("{ .reg .u64 t; cvta.to.shared.u64 t, %1; cvt.u32.u64 %0, t; }" : "=r"(a) : "l"(p));
    return a;
}
__device__ __forceinline__ void ldsm4(uint32_t addr, uint32_t r[4]) {
    asm volatile("ldmatrix.sync.aligned.m8n8.x4.shared.b16 {%0,%1,%2,%3}, [%4];"
                 : "=r"(r[0]), "=r"(r[1]), "=r"(r[2]), "=r"(r[3]) : "r"(addr));
}
__device__ __forceinline__ void mma16816(float c[4], const uint32_t a[4], uint32_t b0, uint32_t b1) {
    asm volatile("mma.sync.aligned.m16n8k16.row.col.f32.f16.f16.f32 "
                 "{%0,%1,%2,%3}, {%4,%5,%6,%7}, {%8,%9}, {%0,%1,%2,%3};"
                 : "+f"(c[0]), "+f"(c[1]), "+f"(c[2]), "+f"(c[3])
                 : "r"(a[0]), "r"(a[1]), "r"(a[2]), "r"(a[3]), "r"(b0), "r"(b1));
}
__device__ __forceinline__ uint32_t a_addr(uint32_t base, int stride, int m0, int kb, int lane) {
    int row = m0 + (lane & 15);
    int k = kb + ((lane >> 4) << 4);
    return base + row * stride + (uint32_t)(k ^ ((row & 7) << 4));
}
__device__ __forceinline__ uint32_t b_addr(uint32_t base, int stride, int n0, int kb, int lane) {
    int row = n0 + (lane & 7) + ((lane & 16) >> 1);
    int k = kb + (((lane >> 3) & 1) << 4);
    return base + row * stride + (uint32_t)(k ^ ((row & 7) << 4));
}
__device__ __forceinline__ float gelu_fast(float v) {
    float c = v * fmaf(v * v, 0.044715f, 1.0f) * 0.7978845608f;
    float t;
    asm("tanh.approx.f32 %0, %1;" : "=f"(t) : "f"(c));
    return 0.5f * v * (1.0f + t);
}
__device__ __forceinline__ uint32_t pack_h2(__half a, __half b) {
    __half2 t; t.x = a; t.y = b;
    return *(uint32_t*)&t;
}
#define HBAR(id) asm volatile("bar.sync %0, 256;" :: "r"(id) : "memory")

// ---------------------------------------------------------------------------
// K0: weight prep
// ---------------------------------------------------------------------------
__global__ void prep_weights(const float* __restrict__ W1, const float* __restrict__ W2) {
    int tid = threadIdx.x + blockIdx.x * blockDim.x;
    int stride = blockDim.x * gridDim.x;
    for (int i = tid; i < 32768; i += stride) {          // W1: n 256, k 128
        int n = i >> 7, k = i & 127;
        uint32_t off = (uint32_t)(n * 256) + (uint32_t)((k * 2) ^ ((n & 7) << 4));
        *(__half*)((char*)gW1 + off) = __float2half_rn(W1[k * 256 + n]);
    }
    for (int i = tid; i < 32768; i += stride) {          // W2: n 128, k 256
        int n = i >> 8, k = i & 255;
        uint32_t off = (uint32_t)(n * 512) + (uint32_t)((k * 2) ^ ((n & 7) << 4));
        *(__half*)((char*)gW2 + off) = __float2half_rn(W2[k * 128 + n]);
    }
}

// ---------------------------------------------------------------------------
// K1: FFN, phase-shifted halves. 512 threads = 2 independent 256-thread halves
// (own X/H1 buffers + named barriers), sharing resident W1+W2. Each half runs
// 2 x 64-row tiles; halves drift out of phase so one half's mma fills the
// other's epilogue/load bubbles.
// ---------------------------------------------------------------------------
__global__ void __launch_bounds__(512)
ffn_mma(const float* __restrict__ x,
        const float* __restrict__ b1, const float* __restrict__ b2) {
    extern __shared__ char sm[];
    const uint32_t sb = smem_u32(sm);
    const int tid = threadIdx.x;
    const int wid = tid >> 5;
    const int lane = tid & 31;
    const int half = wid >> 3;           // 0 / 1
    const int tid_h = tid & 255;         // thread id within half
    const int hw = wid & 7;              // warp within half
    const int wm = hw & 1;               // 2 m-warps (32 rows each)
    const int wn = hw >> 1;              // 4 n-warps

    const uint32_t offX  = OFF_X  + (uint32_t)half * 16384;
    const uint32_t offH1 = OFF_H1 + (uint32_t)half * 32768;
    const int bar = 1 + half;

    // load W1+W2 once (all 512 threads)
    {
        const uint4* s1 = (const uint4*)gW1;
        const uint4* s2 = (const uint4*)gW2;
        uint4* d1 = (uint4*)(sm + OFF_W1);
        uint4* d2 = (uint4*)(sm + OFF_W2);
#pragma unroll 4
        for (int i = tid; i < 4096; i += 512) { d1[i] = s1[i]; d2[i] = s2[i]; }
    }
    __syncthreads();

    for (int t = 0; t < TILES_PER_HALF; t++) {
        const size_t rowbase =
            (size_t)(blockIdx.x * (2 * TILES_PER_HALF) + half * TILES_PER_HALF + t) * 64;

        // ---- load x tile [64,128] f32 -> fp16 smem, swizzled (256 threads) ----
        {
            const float4* xg = (const float4*)(x + rowbase * DIM);
#pragma unroll
            for (int ii = 0; ii < 8; ii++) {
                int i = tid_h + ii * 256;
                float4 v = xg[i];
                int row = i >> 5, k = (i & 31) * 4;
                uint32_t off = (uint32_t)((k * 2) ^ ((row & 7) << 4)) + row * 256;
                *(uint2*)(sm + offX + off) =
                    make_uint2(pack_h2(__float2half_rn(v.x), __float2half_rn(v.y)),
                               pack_h2(__float2half_rn(v.z), __float2half_rn(v.w)));
            }
        }
        HBAR(bar);

        // ---- GEMM1: [64,128] x [128,256], warp tile 32x64 ----
        float acc[2][8][4];
#pragma unroll
        for (int a = 0; a < 2; a++)
#pragma unroll
            for (int b = 0; b < 8; b++)
#pragma unroll
                for (int c = 0; c < 4; c++) acc[a][b][c] = 0.f;

#pragma unroll
        for (int ks = 0; ks < 8; ks++) {
            const int kb = ks * 32;
            uint32_t aw[2][4];
#pragma unroll
            for (int mt = 0; mt < 2; mt++)
                ldsm4(a_addr(sb + offX, 256, wm * 32 + mt * 16, kb, lane), aw[mt]);
#pragma unroll
            for (int ntp = 0; ntp < 4; ntp++) {
                const int n0 = wn * 64 + ntp * 16;
                uint32_t bw[4];
                ldsm4(b_addr(sb + OFF_W1, 256, n0, kb, lane), bw);
#pragma unroll
                for (int mt = 0; mt < 2; mt++) {
                    mma16816(acc[mt][ntp * 2],     aw[mt], bw[0], bw[1]);
                    mma16816(acc[mt][ntp * 2 + 1], aw[mt], bw[2], bw[3]);
                }
            }
        }

        // ---- Epilogue 1: +b1, GELU, fp16 -> h1 ----
#pragma unroll
        for (int nt = 0; nt < 8; nt++) {
            const int col = wn * 64 + nt * 8 + (lane & 3) * 2;
            const float2 bb = *(const float2*)&b1[col];
#pragma unroll
            for (int mt = 0; mt < 2; mt++) {
                const int r = wm * 32 + mt * 16 + (lane >> 2);
#pragma unroll
                for (int h = 0; h < 2; h++) {
                    const int rr = r + h * 8;
                    float v0 = gelu_fast(acc[mt][nt][h * 2]     + bb.x);
                    float v1 = gelu_fast(acc[mt][nt][h * 2 + 1] + bb.y);
                    uint32_t off = rr * 512 + (uint32_t)((col * 2) ^ ((rr & 7) << 4));
                    *(uint32_t*)(sm + offH1 + off) =
                        pack_h2(__float2half_rn(v0), __float2half_rn(v1));
                }
            }
        }
        HBAR(bar);

        // ---- GEMM2: [64,256] x [256,128], warp tile 32x32 ----
        float acc2[2][4][4];
#pragma unroll
        for (int a = 0; a < 2; a++)
#pragma unroll
            for (int b = 0; b < 4; b++)
#pragma unroll
                for (int c = 0; c < 4; c++) acc2[a][b][c] = 0.f;

#pragma unroll
        for (int ks = 0; ks < 16; ks++) {
            const int kb = ks * 32;
            uint32_t aw[2][4];
#pragma unroll
            for (int mt = 0; mt < 2; mt++)
                ldsm4(a_addr(sb + offH1, 512, wm * 32 + mt * 16, kb, lane), aw[mt]);
#pragma unroll
            for (int ntp = 0; ntp < 2; ntp++) {
                const int n0 = wn * 32 + ntp * 16;
                uint32_t bw[4];
                ldsm4(b_addr(sb + OFF_W2, 512, n0, kb, lane), bw);
#pragma unroll
                for (int mt = 0; mt < 2; mt++) {
                    mma16816(acc2[mt][ntp * 2],     aw[mt], bw[0], bw[1]);
                    mma16816(acc2[mt][ntp * 2 + 1], aw[mt], bw[2], bw[3]);
                }
            }
        }

        // ---- Epilogue 2: +b2 -> g_hbufh (fp16) ----
#pragma unroll
        for (int nt = 0; nt < 4; nt++) {
            const int col = wn * 32 + nt * 8 + (lane & 3) * 2;
            const float2 bb = *(const float2*)&b2[col];
#pragma unroll
            for (int mt = 0; mt < 2; mt++) {
                const int r = wm * 32 + mt * 16 + (lane >> 2);
#pragma unroll
                for (int h = 0; h < 2; h++) {
                    const int rr = r + h * 8;
                    *(uint32_t*)&g_hbufh[(rowbase + rr) * DIM + col] =
                        pack_h2(__float2half_rn(acc2[mt][nt][h * 2] + bb.x),
                                __float2half_rn(acc2[mt][nt][h * 2 + 1] + bb.y));
                }
            }
        }
        HBAR(bar);   // X/H1 reads done before next tile overwrites
    }
}

// ---------------------------------------------------------------------------
// K2: scatter-mean, gather formulation. Block = (graph b, 4-hub partition of 16).
// ---------------------------------------------------------------------------
#define MAXSPG 6144
#define MAXHL  256
#define SPLITS 16

__global__ void __launch_bounds__(256)
scatter_gather(const int* __restrict__ hub_idx,
               const int* __restrict__ batch_idx,
               float* __restrict__ hubf_out) {
    __shared__ int shub[MAXSPG];
    __shared__ int list[4][MAXHL];
    __shared__ int lcnt[4];
    __shared__ int srange[2];

    const int b = blockIdx.x >> 4;
    const int p = blockIdx.x & 15;
    const int tid = threadIdx.x;

    if (tid < 4) lcnt[tid] = 0;
    if (tid < 2) {
        int target = b + tid, lo = 0, hi = NS;
        while (lo < hi) { int mid = (lo + hi) >> 1; if (batch_idx[mid] < target) lo = mid + 1; else hi = mid; }
        srange[tid] = lo;
    }
    __syncthreads();

    const int s0 = srange[0];
    const int n = srange[1] - s0;

    for (int i = tid; i < n; i += 256) shub[i] = hub_idx[s0 + i];
    __syncthreads();

    if (tid < 32) {
        const int h0 = p * 4;
        for (int base = 0; base < n; base += 32) {
            int i = base + tid;
            int h = (i < n) ? shub[i] : -1;
            bool in = (h >= h0) && (h < h0 + 4);
            unsigned mm = __match_any_sync(0xffffffffu, h);
            if (in) {
                int hl = h - h0;
                int rank = __popc(mm & ((1u << tid) - 1u));
                int cnt = __popc(mm);
                int basec = lcnt[hl];
                list[hl][basec + rank] = i;
                if (rank == cnt - 1) lcnt[hl] = basec + cnt;
            }
            __syncwarp();
        }
    }
    __syncthreads();

    const int half = tid >> 7;
    const int d = tid & 127;
#pragma unroll
    for (int hh = 0; hh < 2; hh++) {
        const int hl = hh * 2 + half;
        const int cnt = lcnt[hl];
        float sum = 0.f;
        int j = 0;
        for (; j + 4 <= cnt; j += 4) {
            float v0 = __half2float(g_hbufh[(size_t)(s0 + list[hl][j])     * DIM + d]);
            float v1 = __half2float(g_hbufh[(size_t)(s0 + list[hl][j + 1]) * DIM + d]);
            float v2 = __half2float(g_hbufh[(size_t)(s0 + list[hl][j + 2]) * DIM + d]);
            float v3 = __half2float(g_hbufh[(size_t)(s0 + list[hl][j + 3]) * DIM + d]);
            sum += v0; sum += v1; sum += v2; sum += v3;
        }
        for (; j < cnt; j++) sum += __half2float(g_hbufh[(size_t)(s0 + list[hl][j]) * DIM + d]);
        hubf_out[((size_t)b * HH + p * 4 + hl) * DIM + d] = sum / (float)max(cnt, 1);
    }
}

// ---------------------------------------------------------------------------
// K3: per-graph 64x64 kNN + fused edge emission (512 threads)
// ---------------------------------------------------------------------------
__global__ void __launch_bounds__(512)
knn_edge_kernel(const int* __restrict__ hub_idx,
                const int* __restrict__ batch_idx,
                const float* __restrict__ hubf,
                float* __restrict__ e0, float* __restrict__ e1) {
    __shared__ float hf[HH][DIM + 1];
    __shared__ float d2row[16][HH];
    __shared__ int sknn[HH][KK_];
    __shared__ int srange[2];

    const int b = blockIdx.x;
    const int tid = threadIdx.x;
    const int warp = tid >> 5, lane = tid & 31;

    for (int i = tid; i < HH * DIM; i += 512) {
        int h = i >> 7, d = i & 127;
        hf[h][d] = hubf[((size_t)b * HH + h) * DIM + d];
    }
    if (tid < 2) {
        int target = b + tid, lo = 0, hi = NS;
        while (lo < hi) { int mid = (lo + hi) >> 1; if (batch_idx[mid] < target) lo = mid + 1; else hi = mid; }
        srange[tid] = lo;
    }
    __syncthreads();

    for (int i = warp; i < HH; i += 16) {
        for (int jj = 0; jj < HH; jj += 32) {
            int j = jj + lane;
            float s = 0.f;
#pragma unroll
            for (int d = 0; d < DIM; d++) {
                float diff = hf[i][d] - hf[j][d];
                s = fmaf(diff, diff, s);
            }
            d2row[warp][j] = s;
        }
        float v0 = d2row[warp][lane], v1 = d2row[warp][lane + 32];
        int   i0 = lane,              i1 = lane + 32;
#pragma unroll
        for (int k = 0; k < KK_; k++) {
            float bv; int bi;
            if (v0 < v1 || (v0 == v1 && i0 < i1)) { bv = v0; bi = i0; }
            else                                   { bv = v1; bi = i1; }
#pragma unroll
            for (int off = 16; off; off >>= 1) {
                float ov = __shfl_xor_sync(0xffffffffu, bv, off);
                int   oi = __shfl_xor_sync(0xffffffffu, bi, off);
                if (ov < bv || (ov == bv && oi < bi)) { bv = ov; bi = oi; }
            }
            if (lane == 0) sknn[i][k] = bi;
            if (i0 == bi) v0 = 3.4e38f;
            if (i1 == bi) v1 = 3.4e38f;
        }
    }
    __syncthreads();

    const int s0 = srange[0], s1 = srange[1];
    const float boff = (float)(b * HH);
    for (int s = s0 + tid; s < s1; s += 512) {
        const int sh = hub_idx[s];
        const float fs = (float)s;
        const int4 kn = *(const int4*)&sknn[sh][0];
        *(float4*)&e0[(size_t)s * 4] = make_float4(fs, fs, fs, fs);
        *(float4*)&e1[(size_t)s * 4] = make_float4(kn.x + boff, kn.y + boff, kn.z + boff, kn.w + boff);
    }
}

// ---------------------------------------------------------------------------
extern "C" void kernel_launch(void* const* d_in, const int* in_sizes, int n_in,
                              void* d_out, int out_size) {
    const float* x   = (const float*)d_in[0];
    const int*   hub = (const int*)d_in[1];
    const int*   bix = (const int*)d_in[2];
    const float* W1  = (const float*)d_in[3];
    const float* b1  = (const float*)d_in[4];
    const float* W2  = (const float*)d_in[5];
    const float* b2  = (const float*)d_in[6];

    float* out  = (float*)d_out;
    float* hubf = out;
    float* e0   = out + HUBF_ELEMS;
    float* e1   = out + HUBF_ELEMS + NK;

    cudaFuncSetAttribute(ffn_mma, cudaFuncAttributeMaxDynamicSharedMemorySize, FFN_SMEM);

    prep_weights<<<64, 256>>>(W1, W2);
    ffn_mma<<<FFN_GRID, 512, FFN_SMEM>>>(x, b1, b2);
    scatter_gather<<<BG * SPLITS, 256>>>(hub, bix, hubf);
    knn_edge_kernel<<<BG, 512>>>(hub, bix, hubf, e0, e1);
}

// round 12
// speedup vs baseline: 5.7401x; 1.0109x over previous
#include <cuda_runtime.h>
#include <cuda_fp16.h>
#include <cstdint>

#define NS   524288
#define DIM  128
#define BG   128
#define HH   64
#define KK_  4
#define BH   (BG * HH)
#define NK   (NS * KK_)
#define HUBF_ELEMS (BH * DIM)

#define TILES_PER_HALF 2
#define FFN_GRID (NS / 256)     /* 2048 */

// FFN output scratch (fp16)
__device__ __half g_hbufh[(size_t)NS * DIM];

// Prepped fp16 weights, transposed [n][k], XOR-swizzled
__device__ __half gW1[256 * 128];
__device__ __half gW2[128 * 256];

// SMEM layout (ffn): 224KB
#define OFF_W1  0
#define OFF_W2  65536
#define OFF_X   131072     /* per-half: +half*16384 */
#define OFF_H1  163840     /* per-half: +half*32768 */
#define FFN_SMEM 229376

// ---------------------------------------------------------------------------
__device__ __forceinline__ uint32_t smem_u32(const void* p) {
    uint32_t a;
    asm("{ .reg .u64 t; cvta.to.shared.u64 t, %1; cvt.u32.u64 %0, t; }" : "=r"(a) : "l"(p));
    return a;
}
__device__ __forceinline__ void ldsm4(uint32_t addr, uint32_t r[4]) {
    asm volatile("ldmatrix.sync.aligned.m8n8.x4.shared.b16 {%0,%1,%2,%3}, [%4];"
                 : "=r"(r[0]), "=r"(r[1]), "=r"(r[2]), "=r"(r[3]) : "r"(addr));
}
__device__ __forceinline__ void mma16816(float c[4], const uint32_t a[4], uint32_t b0, uint32_t b1) {
    asm volatile("mma.sync.aligned.m16n8k16.row.col.f32.f16.f16.f32 "
                 "{%0,%1,%2,%3}, {%4,%5,%6,%7}, {%8,%9}, {%0,%1,%2,%3};"
                 : "+f"(c[0]), "+f"(c[1]), "+f"(c[2]), "+f"(c[3])
                 : "r"(a[0]), "r"(a[1]), "r"(a[2]), "r"(a[3]), "r"(b0), "r"(b1));
}
__device__ __forceinline__ uint32_t a_addr(uint32_t base, int stride, int m0, int kb, int lane) {
    int row = m0 + (lane & 15);
    int k = kb + ((lane >> 4) << 4);
    return base + row * stride + (uint32_t)(k ^ ((row & 7) << 4));
}
__device__ __forceinline__ uint32_t b_addr(uint32_t base, int stride, int n0, int kb, int lane) {
    int row = n0 + (lane & 7) + ((lane & 16) >> 1);
    int k = kb + (((lane >> 3) & 1) << 4);
    return base + row * stride + (uint32_t)(k ^ ((row & 7) << 4));
}
__device__ __forceinline__ float gelu_fast(float v) {
    float c = v * fmaf(v * v, 0.044715f, 1.0f) * 0.7978845608f;
    float t;
    asm("tanh.approx.f32 %0, %1;" : "=f"(t) : "f"(c));
    return 0.5f * v * (1.0f + t);
}
__device__ __forceinline__ uint32_t pack_h2(__half a, __half b) {
    __half2 t; t.x = a; t.y = b;
    return *(uint32_t*)&t;
}
#define HBAR(id) asm volatile("bar.sync %0, 256;" :: "r"(id) : "memory")

// ---------------------------------------------------------------------------
// K0: weight prep
// ---------------------------------------------------------------------------
__global__ void prep_weights(const float* __restrict__ W1, const float* __restrict__ W2) {
    int tid = threadIdx.x + blockIdx.x * blockDim.x;
    int stride = blockDim.x * gridDim.x;
    for (int i = tid; i < 32768; i += stride) {
        int n = i >> 7, k = i & 127;
        uint32_t off = (uint32_t)(n * 256) + (uint32_t)((k * 2) ^ ((n & 7) << 4));
        *(__half*)((char*)gW1 + off) = __float2half_rn(W1[k * 256 + n]);
    }
    for (int i = tid; i < 32768; i += stride) {
        int n = i >> 8, k = i & 255;
        uint32_t off = (uint32_t)(n * 512) + (uint32_t)((k * 2) ^ ((n & 7) << 4));
        *(__half*)((char*)gW2 + off) = __float2half_rn(W2[k * 128 + n]);
    }
}

// dummy launch to position ffn_mma at ncu's sampled launch index (3)
__global__ void nudge_kernel() {}

// ---------------------------------------------------------------------------
// K1: FFN, phase-shifted halves (unchanged from R11)
// ---------------------------------------------------------------------------
__global__ void __launch_bounds__(512)
ffn_mma(const float* __restrict__ x,
        const float* __restrict__ b1, const float* __restrict__ b2) {
    extern __shared__ char sm[];
    const uint32_t sb = smem_u32(sm);
    const int tid = threadIdx.x;
    const int wid = tid >> 5;
    const int lane = tid & 31;
    const int half = wid >> 3;
    const int tid_h = tid & 255;
    const int hw = wid & 7;
    const int wm = hw & 1;
    const int wn = hw >> 1;

    const uint32_t offX  = OFF_X  + (uint32_t)half * 16384;
    const uint32_t offH1 = OFF_H1 + (uint32_t)half * 32768;
    const int bar = 1 + half;

    {
        const uint4* s1 = (const uint4*)gW1;
        const uint4* s2 = (const uint4*)gW2;
        uint4* d1 = (uint4*)(sm + OFF_W1);
        uint4* d2 = (uint4*)(sm + OFF_W2);
#pragma unroll 4
        for (int i = tid; i < 4096; i += 512) { d1[i] = s1[i]; d2[i] = s2[i]; }
    }
    __syncthreads();

    for (int t = 0; t < TILES_PER_HALF; t++) {
        const size_t rowbase =
            (size_t)(blockIdx.x * (2 * TILES_PER_HALF) + half * TILES_PER_HALF + t) * 64;

        {
            const float4* xg = (const float4*)(x + rowbase * DIM);
#pragma unroll
            for (int ii = 0; ii < 8; ii++) {
                int i = tid_h + ii * 256;
                float4 v = xg[i];
                int row = i >> 5, k = (i & 31) * 4;
                uint32_t off = (uint32_t)((k * 2) ^ ((row & 7) << 4)) + row * 256;
                *(uint2*)(sm + offX + off) =
                    make_uint2(pack_h2(__float2half_rn(v.x), __float2half_rn(v.y)),
                               pack_h2(__float2half_rn(v.z), __float2half_rn(v.w)));
            }
        }
        HBAR(bar);

        float acc[2][8][4];
#pragma unroll
        for (int a = 0; a < 2; a++)
#pragma unroll
            for (int b = 0; b < 8; b++)
#pragma unroll
                for (int c = 0; c < 4; c++) acc[a][b][c] = 0.f;

#pragma unroll
        for (int ks = 0; ks < 8; ks++) {
            const int kb = ks * 32;
            uint32_t aw[2][4];
#pragma unroll
            for (int mt = 0; mt < 2; mt++)
                ldsm4(a_addr(sb + offX, 256, wm * 32 + mt * 16, kb, lane), aw[mt]);
#pragma unroll
            for (int ntp = 0; ntp < 4; ntp++) {
                const int n0 = wn * 64 + ntp * 16;
                uint32_t bw[4];
                ldsm4(b_addr(sb + OFF_W1, 256, n0, kb, lane), bw);
#pragma unroll
                for (int mt = 0; mt < 2; mt++) {
                    mma16816(acc[mt][ntp * 2],     aw[mt], bw[0], bw[1]);
                    mma16816(acc[mt][ntp * 2 + 1], aw[mt], bw[2], bw[3]);
                }
            }
        }

#pragma unroll
        for (int nt = 0; nt < 8; nt++) {
            const int col = wn * 64 + nt * 8 + (lane & 3) * 2;
            const float2 bb = *(const float2*)&b1[col];
#pragma unroll
            for (int mt = 0; mt < 2; mt++) {
                const int r = wm * 32 + mt * 16 + (lane >> 2);
#pragma unroll
                for (int h = 0; h < 2; h++) {
                    const int rr = r + h * 8;
                    float v0 = gelu_fast(acc[mt][nt][h * 2]     + bb.x);
                    float v1 = gelu_fast(acc[mt][nt][h * 2 + 1] + bb.y);
                    uint32_t off = rr * 512 + (uint32_t)((col * 2) ^ ((rr & 7) << 4));
                    *(uint32_t*)(sm + offH1 + off) =
                        pack_h2(__float2half_rn(v0), __float2half_rn(v1));
                }
            }
        }
        HBAR(bar);

        float acc2[2][4][4];
#pragma unroll
        for (int a = 0; a < 2; a++)
#pragma unroll
            for (int b = 0; b < 4; b++)
#pragma unroll
                for (int c = 0; c < 4; c++) acc2[a][b][c] = 0.f;

#pragma unroll
        for (int ks = 0; ks < 16; ks++) {
            const int kb = ks * 32;
            uint32_t aw[2][4];
#pragma unroll
            for (int mt = 0; mt < 2; mt++)
                ldsm4(a_addr(sb + offH1, 512, wm * 32 + mt * 16, kb, lane), aw[mt]);
#pragma unroll
            for (int ntp = 0; ntp < 2; ntp++) {
                const int n0 = wn * 32 + ntp * 16;
                uint32_t bw[4];
                ldsm4(b_addr(sb + OFF_W2, 512, n0, kb, lane), bw);
#pragma unroll
                for (int mt = 0; mt < 2; mt++) {
                    mma16816(acc2[mt][ntp * 2],     aw[mt], bw[0], bw[1]);
                    mma16816(acc2[mt][ntp * 2 + 1], aw[mt], bw[2], bw[3]);
                }
            }
        }

#pragma unroll
        for (int nt = 0; nt < 4; nt++) {
            const int col = wn * 32 + nt * 8 + (lane & 3) * 2;
            const float2 bb = *(const float2*)&b2[col];
#pragma unroll
            for (int mt = 0; mt < 2; mt++) {
                const int r = wm * 32 + mt * 16 + (lane >> 2);
#pragma unroll
                for (int h = 0; h < 2; h++) {
                    const int rr = r + h * 8;
                    *(uint32_t*)&g_hbufh[(rowbase + rr) * DIM + col] =
                        pack_h2(__float2half_rn(acc2[mt][nt][h * 2] + bb.x),
                                __float2half_rn(acc2[mt][nt][h * 2 + 1] + bb.y));
                }
            }
        }
        HBAR(bar);
    }
}

// ---------------------------------------------------------------------------
// K2: scatter-mean, gather formulation (16 partitions/graph)
// ---------------------------------------------------------------------------
#define MAXSPG 6144
#define MAXHL  256
#define SPLITS 16

__global__ void __launch_bounds__(256)
scatter_gather(const int* __restrict__ hub_idx,
               const int* __restrict__ batch_idx,
               float* __restrict__ hubf_out) {
    __shared__ int shub[MAXSPG];
    __shared__ int list[4][MAXHL];
    __shared__ int lcnt[4];
    __shared__ int srange[2];

    const int b = blockIdx.x >> 4;
    const int p = blockIdx.x & 15;
    const int tid = threadIdx.x;

    if (tid < 4) lcnt[tid] = 0;
    if (tid < 2) {
        int target = b + tid, lo = 0, hi = NS;
        while (lo < hi) { int mid = (lo + hi) >> 1; if (batch_idx[mid] < target) lo = mid + 1; else hi = mid; }
        srange[tid] = lo;
    }
    __syncthreads();

    const int s0 = srange[0];
    const int n = srange[1] - s0;

    for (int i = tid; i < n; i += 256) shub[i] = hub_idx[s0 + i];
    __syncthreads();

    if (tid < 32) {
        const int h0 = p * 4;
        for (int base = 0; base < n; base += 32) {
            int i = base + tid;
            int h = (i < n) ? shub[i] : -1;
            bool in = (h >= h0) && (h < h0 + 4);
            unsigned mm = __match_any_sync(0xffffffffu, h);
            if (in) {
                int hl = h - h0;
                int rank = __popc(mm & ((1u << tid) - 1u));
                int cnt = __popc(mm);
                int basec = lcnt[hl];
                list[hl][basec + rank] = i;
                if (rank == cnt - 1) lcnt[hl] = basec + cnt;
            }
            __syncwarp();
        }
    }
    __syncthreads();

    const int half = tid >> 7;
    const int d = tid & 127;
#pragma unroll
    for (int hh = 0; hh < 2; hh++) {
        const int hl = hh * 2 + half;
        const int cnt = lcnt[hl];
        float sum = 0.f;
        int j = 0;
        for (; j + 4 <= cnt; j += 4) {
            float v0 = __half2float(g_hbufh[(size_t)(s0 + list[hl][j])     * DIM + d]);
            float v1 = __half2float(g_hbufh[(size_t)(s0 + list[hl][j + 1]) * DIM + d]);
            float v2 = __half2float(g_hbufh[(size_t)(s0 + list[hl][j + 2]) * DIM + d]);
            float v3 = __half2float(g_hbufh[(size_t)(s0 + list[hl][j + 3]) * DIM + d]);
            sum += v0; sum += v1; sum += v2; sum += v3;
        }
        for (; j < cnt; j++) sum += __half2float(g_hbufh[(size_t)(s0 + list[hl][j]) * DIM + d]);
        hubf_out[((size_t)b * HH + p * 4 + hl) * DIM + d] = sum / (float)max(cnt, 1);
    }
}

// ---------------------------------------------------------------------------
// K3: per-graph 64x64 kNN + fused edge emission (256 threads — R10 shape)
// ---------------------------------------------------------------------------
__global__ void __launch_bounds__(256)
knn_edge_kernel(const int* __restrict__ hub_idx,
                const int* __restrict__ batch_idx,
                const float* __restrict__ hubf,
                float* __restrict__ e0, float* __restrict__ e1) {
    __shared__ float hf[HH][DIM + 1];
    __shared__ float d2row[8][HH];
    __shared__ int sknn[HH][KK_];
    __shared__ int srange[2];

    const int b = blockIdx.x;
    const int tid = threadIdx.x;
    const int warp = tid >> 5, lane = tid & 31;

    for (int i = tid; i < HH * DIM; i += 256) {
        int h = i >> 7, d = i & 127;
        hf[h][d] = hubf[((size_t)b * HH + h) * DIM + d];
    }
    if (tid < 2) {
        int target = b + tid, lo = 0, hi = NS;
        while (lo < hi) { int mid = (lo + hi) >> 1; if (batch_idx[mid] < target) lo = mid + 1; else hi = mid; }
        srange[tid] = lo;
    }
    __syncthreads();

    for (int i = warp; i < HH; i += 8) {
        for (int jj = 0; jj < HH; jj += 32) {
            int j = jj + lane;
            float s = 0.f;
#pragma unroll
            for (int d = 0; d < DIM; d++) {
                float diff = hf[i][d] - hf[j][d];
                s = fmaf(diff, diff, s);
            }
            d2row[warp][j] = s;
        }
        float v0 = d2row[warp][lane], v1 = d2row[warp][lane + 32];
        int   i0 = lane,              i1 = lane + 32;
#pragma unroll
        for (int k = 0; k < KK_; k++) {
            float bv; int bi;
            if (v0 < v1 || (v0 == v1 && i0 < i1)) { bv = v0; bi = i0; }
            else                                   { bv = v1; bi = i1; }
#pragma unroll
            for (int off = 16; off; off >>= 1) {
                float ov = __shfl_xor_sync(0xffffffffu, bv, off);
                int   oi = __shfl_xor_sync(0xffffffffu, bi, off);
                if (ov < bv || (ov == bv && oi < bi)) { bv = ov; bi = oi; }
            }
            if (lane == 0) sknn[i][k] = bi;
            if (i0 == bi) v0 = 3.4e38f;
            if (i1 == bi) v1 = 3.4e38f;
        }
    }
    __syncthreads();

    const int s0 = srange[0], s1 = srange[1];
    const float boff = (float)(b * HH);
    for (int s = s0 + tid; s < s1; s += 256) {
        const int sh = hub_idx[s];
        const float fs = (float)s;
        const int4 kn = *(const int4*)&sknn[sh][0];
        *(float4*)&e0[(size_t)s * 4] = make_float4(fs, fs, fs, fs);
        *(float4*)&e1[(size_t)s * 4] = make_float4(kn.x + boff, kn.y + boff, kn.z + boff, kn.w + boff);
    }
}

// ---------------------------------------------------------------------------
extern "C" void kernel_launch(void* const* d_in, const int* in_sizes, int n_in,
                              void* d_out, int out_size) {
    const float* x   = (const float*)d_in[0];
    const int*   hub = (const int*)d_in[1];
    const int*   bix = (const int*)d_in[2];
    const float* W1  = (const float*)d_in[3];
    const float* b1  = (const float*)d_in[4];
    const float* W2  = (const float*)d_in[5];
    const float* b2  = (const float*)d_in[6];

    float* out  = (float*)d_out;
    float* hubf = out;
    float* e0   = out + HUBF_ELEMS;
    float* e1   = out + HUBF_ELEMS + NK;

    cudaFuncSetAttribute(ffn_mma, cudaFuncAttributeMaxDynamicSharedMemorySize, FFN_SMEM);

    prep_weights<<<64, 256>>>(W1, W2);        // idx 0
    nudge_kernel<<<1, 32>>>();                // idx 1
    nudge_kernel<<<1, 32>>>();                // idx 2
    ffn_mma<<<FFN_GRID, 512, FFN_SMEM>>>(x, b1, b2);   // idx 3 <- ncu samples here
    scatter_gather<<<BG * SPLITS, 256>>>(hub, bix, hubf);
    knn_edge_kernel<<<BG, 256>>>(hub, bix, hubf, e0, e1);
}

// round 13
// speedup vs baseline: 5.7805x; 1.0070x over previous
#include <cuda_runtime.h>
#include <cuda_fp16.h>
#include <cstdint>

#define NS   524288
#define DIM  128
#define BG   128
#define HH   64
#define KK_  4
#define BH   (BG * HH)
#define NK   (NS * KK_)
#define HUBF_ELEMS (BH * DIM)

#define TILES_PER_HALF 2
#define FFN_GRID (NS / 256)     /* 2048 */

// FFN output scratch (fp16)
__device__ __half g_hbufh[(size_t)NS * DIM];

// Prepped fp16 weights, transposed [n][k], XOR-swizzled
__device__ __half gW1[256 * 128];
__device__ __half gW2[128 * 256];

// SMEM layout (ffn): 224KB
#define OFF_W1  0
#define OFF_W2  65536
#define OFF_X   131072     /* per-half: +half*16384 */
#define OFF_H1  163840     /* per-half: +half*32768 */
#define FFN_SMEM 229376

// ---------------------------------------------------------------------------
__device__ __forceinline__ uint32_t smem_u32(const void* p) {
    uint32_t a;
    asm("{ .reg .u64 t; cvta.to.shared.u64 t, %1; cvt.u32.u64 %0, t; }" : "=r"(a) : "l"(p));
    return a;
}
__device__ __forceinline__ void ldsm4(uint32_t addr, uint32_t r[4]) {
    asm volatile("ldmatrix.sync.aligned.m8n8.x4.shared.b16 {%0,%1,%2,%3}, [%4];"
                 : "=r"(r[0]), "=r"(r[1]), "=r"(r[2]), "=r"(r[3]) : "r"(addr));
}
__device__ __forceinline__ void mma16816(float c[4], const uint32_t a[4], uint32_t b0, uint32_t b1) {
    asm volatile("mma.sync.aligned.m16n8k16.row.col.f32.f16.f16.f32 "
                 "{%0,%1,%2,%3}, {%4,%5,%6,%7}, {%8,%9}, {%0,%1,%2,%3};"
                 : "+f"(c[0]), "+f"(c[1]), "+f"(c[2]), "+f"(c[3])
                 : "r"(a[0]), "r"(a[1]), "r"(a[2]), "r"(a[3]), "r"(b0), "r"(b1));
}
__device__ __forceinline__ uint32_t a_addr(uint32_t base, int stride, int m0, int kb, int lane) {
    int row = m0 + (lane & 15);
    int k = kb + ((lane >> 4) << 4);
    return base + row * stride + (uint32_t)(k ^ ((row & 7) << 4));
}
__device__ __forceinline__ uint32_t b_addr(uint32_t base, int stride, int n0, int kb, int lane) {
    int row = n0 + (lane & 7) + ((lane & 16) >> 1);
    int k = kb + (((lane >> 3) & 1) << 4);
    return base + row * stride + (uint32_t)(k ^ ((row & 7) << 4));
}
__device__ __forceinline__ float gelu_fast(float v) {
    float c = v * fmaf(v * v, 0.044715f, 1.0f) * 0.7978845608f;
    float t;
    asm("tanh.approx.f32 %0, %1;" : "=f"(t) : "f"(c));
    return 0.5f * v * (1.0f + t);
}
__device__ __forceinline__ uint32_t pack_h2(__half a, __half b) {
    __half2 t; t.x = a; t.y = b;
    return *(uint32_t*)&t;
}
#define HBAR(id) asm volatile("bar.sync %0, 256;" :: "r"(id) : "memory")

// ---------------------------------------------------------------------------
// K0: weight prep
// ---------------------------------------------------------------------------
__global__ void prep_weights(const float* __restrict__ W1, const float* __restrict__ W2) {
    int tid = threadIdx.x + blockIdx.x * blockDim.x;
    int stride = blockDim.x * gridDim.x;
    for (int i = tid; i < 32768; i += stride) {
        int n = i >> 7, k = i & 127;
        uint32_t off = (uint32_t)(n * 256) + (uint32_t)((k * 2) ^ ((n & 7) << 4));
        *(__half*)((char*)gW1 + off) = __float2half_rn(W1[k * 256 + n]);
    }
    for (int i = tid; i < 32768; i += stride) {
        int n = i >> 8, k = i & 255;
        uint32_t off = (uint32_t)(n * 512) + (uint32_t)((k * 2) ^ ((n & 7) << 4));
        *(__half*)((char*)gW2 + off) = __float2half_rn(W2[k * 128 + n]);
    }
}

// dummy launches to keep ffn_mma at ncu's sampled launch index
__global__ void nudge_kernel() {}

// ---------------------------------------------------------------------------
// K1: FFN, phase-shifted halves (frozen — profiled at 291us R12)
// ---------------------------------------------------------------------------
__global__ void __launch_bounds__(512)
ffn_mma(const float* __restrict__ x,
        const float* __restrict__ b1, const float* __restrict__ b2) {
    extern __shared__ char sm[];
    const uint32_t sb = smem_u32(sm);
    const int tid = threadIdx.x;
    const int wid = tid >> 5;
    const int lane = tid & 31;
    const int half = wid >> 3;
    const int tid_h = tid & 255;
    const int hw = wid & 7;
    const int wm = hw & 1;
    const int wn = hw >> 1;

    const uint32_t offX  = OFF_X  + (uint32_t)half * 16384;
    const uint32_t offH1 = OFF_H1 + (uint32_t)half * 32768;
    const int bar = 1 + half;

    {
        const uint4* s1 = (const uint4*)gW1;
        const uint4* s2 = (const uint4*)gW2;
        uint4* d1 = (uint4*)(sm + OFF_W1);
        uint4* d2 = (uint4*)(sm + OFF_W2);
#pragma unroll 4
        for (int i = tid; i < 4096; i += 512) { d1[i] = s1[i]; d2[i] = s2[i]; }
    }
    __syncthreads();

    for (int t = 0; t < TILES_PER_HALF; t++) {
        const size_t rowbase =
            (size_t)(blockIdx.x * (2 * TILES_PER_HALF) + half * TILES_PER_HALF + t) * 64;

        {
            const float4* xg = (const float4*)(x + rowbase * DIM);
#pragma unroll
            for (int ii = 0; ii < 8; ii++) {
                int i = tid_h + ii * 256;
                float4 v = xg[i];
                int row = i >> 5, k = (i & 31) * 4;
                uint32_t off = (uint32_t)((k * 2) ^ ((row & 7) << 4)) + row * 256;
                *(uint2*)(sm + offX + off) =
                    make_uint2(pack_h2(__float2half_rn(v.x), __float2half_rn(v.y)),
                               pack_h2(__float2half_rn(v.z), __float2half_rn(v.w)));
            }
        }
        HBAR(bar);

        float acc[2][8][4];
#pragma unroll
        for (int a = 0; a < 2; a++)
#pragma unroll
            for (int b = 0; b < 8; b++)
#pragma unroll
                for (int c = 0; c < 4; c++) acc[a][b][c] = 0.f;

#pragma unroll
        for (int ks = 0; ks < 8; ks++) {
            const int kb = ks * 32;
            uint32_t aw[2][4];
#pragma unroll
            for (int mt = 0; mt < 2; mt++)
                ldsm4(a_addr(sb + offX, 256, wm * 32 + mt * 16, kb, lane), aw[mt]);
#pragma unroll
            for (int ntp = 0; ntp < 4; ntp++) {
                const int n0 = wn * 64 + ntp * 16;
                uint32_t bw[4];
                ldsm4(b_addr(sb + OFF_W1, 256, n0, kb, lane), bw);
#pragma unroll
                for (int mt = 0; mt < 2; mt++) {
                    mma16816(acc[mt][ntp * 2],     aw[mt], bw[0], bw[1]);
                    mma16816(acc[mt][ntp * 2 + 1], aw[mt], bw[2], bw[3]);
                }
            }
        }

#pragma unroll
        for (int nt = 0; nt < 8; nt++) {
            const int col = wn * 64 + nt * 8 + (lane & 3) * 2;
            const float2 bb = *(const float2*)&b1[col];
#pragma unroll
            for (int mt = 0; mt < 2; mt++) {
                const int r = wm * 32 + mt * 16 + (lane >> 2);
#pragma unroll
                for (int h = 0; h < 2; h++) {
                    const int rr = r + h * 8;
                    float v0 = gelu_fast(acc[mt][nt][h * 2]     + bb.x);
                    float v1 = gelu_fast(acc[mt][nt][h * 2 + 1] + bb.y);
                    uint32_t off = rr * 512 + (uint32_t)((col * 2) ^ ((rr & 7) << 4));
                    *(uint32_t*)(sm + offH1 + off) =
                        pack_h2(__float2half_rn(v0), __float2half_rn(v1));
                }
            }
        }
        HBAR(bar);

        float acc2[2][4][4];
#pragma unroll
        for (int a = 0; a < 2; a++)
#pragma unroll
            for (int b = 0; b < 4; b++)
#pragma unroll
                for (int c = 0; c < 4; c++) acc2[a][b][c] = 0.f;

#pragma unroll
        for (int ks = 0; ks < 16; ks++) {
            const int kb = ks * 32;
            uint32_t aw[2][4];
#pragma unroll
            for (int mt = 0; mt < 2; mt++)
                ldsm4(a_addr(sb + offH1, 512, wm * 32 + mt * 16, kb, lane), aw[mt]);
#pragma unroll
            for (int ntp = 0; ntp < 2; ntp++) {
                const int n0 = wn * 32 + ntp * 16;
                uint32_t bw[4];
                ldsm4(b_addr(sb + OFF_W2, 512, n0, kb, lane), bw);
#pragma unroll
                for (int mt = 0; mt < 2; mt++) {
                    mma16816(acc2[mt][ntp * 2],     aw[mt], bw[0], bw[1]);
                    mma16816(acc2[mt][ntp * 2 + 1], aw[mt], bw[2], bw[3]);
                }
            }
        }

#pragma unroll
        for (int nt = 0; nt < 4; nt++) {
            const int col = wn * 32 + nt * 8 + (lane & 3) * 2;
            const float2 bb = *(const float2*)&b2[col];
#pragma unroll
            for (int mt = 0; mt < 2; mt++) {
                const int r = wm * 32 + mt * 16 + (lane >> 2);
#pragma unroll
                for (int h = 0; h < 2; h++) {
                    const int rr = r + h * 8;
                    *(uint32_t*)&g_hbufh[(rowbase + rr) * DIM + col] =
                        pack_h2(__float2half_rn(acc2[mt][nt][h * 2] + bb.x),
                                __float2half_rn(acc2[mt][nt][h * 2 + 1] + bb.y));
                }
            }
        }
        HBAR(bar);
    }
}

// ---------------------------------------------------------------------------
// K2: scatter-mean v3. Block = (graph b, 4-hub group p of 16).
// Phase 1: 8 warps IN PARALLEL scan disjoint chunks of the graph's spokes
//          straight from gmem, building per-(warp,hub) ordered lists.
// Phase 2: compact into one contiguous list per hub (deterministic order:
//          chunk-major, ascending within chunk).
// Phase 3: gather with 8-wide MLP, divide by count.
// ---------------------------------------------------------------------------
#define SPLITS 16
#define WLMAX  96      /* max spokes per (warp-chunk, hub): mean ~8 */
#define CLMAX  768     /* max spokes per hub per graph: mean ~64 */

__global__ void __launch_bounds__(256)
scatter_gather(const int* __restrict__ hub_idx,
               const int* __restrict__ batch_idx,
               float* __restrict__ hubf_out) {
    __shared__ int wlist[8][4][WLMAX];
    __shared__ int wcnt[8][4];
    __shared__ int clist[4][CLMAX];
    __shared__ int ccnt[4];
    __shared__ int coff[8][4];
    __shared__ int srange[2];

    const int b = blockIdx.x >> 4;
    const int p = blockIdx.x & 15;
    const int h0 = p * 4;
    const int tid = threadIdx.x;
    const int w = tid >> 5;
    const int lane = tid & 31;

    if (lane < 4) wcnt[w][lane] = 0;
    if (tid < 2) {
        int target = b + tid, lo = 0, hi = NS;
        while (lo < hi) { int mid = (lo + hi) >> 1; if (batch_idx[mid] < target) lo = mid + 1; else hi = mid; }
        srange[tid] = lo;
    }
    __syncthreads();

    const int s0 = srange[0];
    const int n = srange[1] - s0;
    const int chunk = (n + 7) >> 3;
    const int cs = s0 + w * chunk;
    const int ce = min(cs + chunk, s0 + n);

    // phase 1: per-warp parallel list build (preserves in-chunk order)
    const unsigned lt = (1u << lane) - 1u;
    for (int base = cs; base < ce; base += 32) {
        int i = base + lane;
        int h = (i < ce) ? __ldg(&hub_idx[i]) : -1;
        int hl = h - h0;
        bool in = (hl >= 0) && (hl < 4);
        unsigned mm = __match_any_sync(0xffffffffu, h);
        if (in) {
            int rank = __popc(mm & lt);
            int cnt = __popc(mm);
            int basec = wcnt[w][hl];
            wlist[w][hl][basec + rank] = i;
            if (rank == cnt - 1) wcnt[w][hl] = basec + cnt;
        }
        __syncwarp();
    }
    __syncthreads();

    // phase 2a: prefix offsets (4 threads)
    if (tid < 4) {
        int run = 0;
#pragma unroll
        for (int ww = 0; ww < 8; ww++) { coff[ww][tid] = run; run += wcnt[ww][tid]; }
        ccnt[tid] = run;
    }
    __syncthreads();

    // phase 2b: each warp copies its lists into the compacted per-hub lists
#pragma unroll
    for (int hl = 0; hl < 4; hl++) {
        int c = wcnt[w][hl], o = coff[w][hl];
        for (int j = lane; j < c; j += 32) clist[hl][o + j] = wlist[w][hl][j];
    }
    __syncthreads();

    // phase 3: gather, 128 threads (one dim each) per hub, 2 hubs per half
    const int half = tid >> 7;
    const int d = tid & 127;
#pragma unroll
    for (int hh = 0; hh < 2; hh++) {
        const int hl = hh * 2 + half;
        const int cnt = ccnt[hl];
        float sum = 0.f;
        int j = 0;
        for (; j + 8 <= cnt; j += 8) {
            float v0 = __half2float(g_hbufh[(size_t)clist[hl][j]     * DIM + d]);
            float v1 = __half2float(g_hbufh[(size_t)clist[hl][j + 1] * DIM + d]);
            float v2 = __half2float(g_hbufh[(size_t)clist[hl][j + 2] * DIM + d]);
            float v3 = __half2float(g_hbufh[(size_t)clist[hl][j + 3] * DIM + d]);
            float v4 = __half2float(g_hbufh[(size_t)clist[hl][j + 4] * DIM + d]);
            float v5 = __half2float(g_hbufh[(size_t)clist[hl][j + 5] * DIM + d]);
            float v6 = __half2float(g_hbufh[(size_t)clist[hl][j + 6] * DIM + d]);
            float v7 = __half2float(g_hbufh[(size_t)clist[hl][j + 7] * DIM + d]);
            sum += v0; sum += v1; sum += v2; sum += v3;
            sum += v4; sum += v5; sum += v6; sum += v7;
        }
        for (; j < cnt; j++) sum += __half2float(g_hbufh[(size_t)clist[hl][j] * DIM + d]);
        hubf_out[((size_t)b * HH + h0 + hl) * DIM + d] = sum / (float)max(cnt, 1);
    }
}

// ---------------------------------------------------------------------------
// K3: per-graph 64x64 kNN + fused edge emission (256 threads)
// ---------------------------------------------------------------------------
__global__ void __launch_bounds__(256)
knn_edge_kernel(const int* __restrict__ hub_idx,
                const int* __restrict__ batch_idx,
                const float* __restrict__ hubf,
                float* __restrict__ e0, float* __restrict__ e1) {
    __shared__ float hf[HH][DIM + 1];
    __shared__ float d2row[8][HH];
    __shared__ int sknn[HH][KK_];
    __shared__ int srange[2];

    const int b = blockIdx.x;
    const int tid = threadIdx.x;
    const int warp = tid >> 5, lane = tid & 31;

    for (int i = tid; i < HH * DIM; i += 256) {
        int h = i >> 7, d = i & 127;
        hf[h][d] = hubf[((size_t)b * HH + h) * DIM + d];
    }
    if (tid < 2) {
        int target = b + tid, lo = 0, hi = NS;
        while (lo < hi) { int mid = (lo + hi) >> 1; if (batch_idx[mid] < target) lo = mid + 1; else hi = mid; }
        srange[tid] = lo;
    }
    __syncthreads();

    for (int i = warp; i < HH; i += 8) {
        for (int jj = 0; jj < HH; jj += 32) {
            int j = jj + lane;
            float s = 0.f;
#pragma unroll
            for (int d = 0; d < DIM; d++) {
                float diff = hf[i][d] - hf[j][d];
                s = fmaf(diff, diff, s);
            }
            d2row[warp][j] = s;
        }
        float v0 = d2row[warp][lane], v1 = d2row[warp][lane + 32];
        int   i0 = lane,              i1 = lane + 32;
#pragma unroll
        for (int k = 0; k < KK_; k++) {
            float bv; int bi;
            if (v0 < v1 || (v0 == v1 && i0 < i1)) { bv = v0; bi = i0; }
            else                                   { bv = v1; bi = i1; }
#pragma unroll
            for (int off = 16; off; off >>= 1) {
                float ov = __shfl_xor_sync(0xffffffffu, bv, off);
                int   oi = __shfl_xor_sync(0xffffffffu, bi, off);
                if (ov < bv || (ov == bv && oi < bi)) { bv = ov; bi = oi; }
            }
            if (lane == 0) sknn[i][k] = bi;
            if (i0 == bi) v0 = 3.4e38f;
            if (i1 == bi) v1 = 3.4e38f;
        }
    }
    __syncthreads();

    const int s0 = srange[0], s1 = srange[1];
    const float boff = (float)(b * HH);
    for (int s = s0 + tid; s < s1; s += 256) {
        const int sh = hub_idx[s];
        const float fs = (float)s;
        const int4 kn = *(const int4*)&sknn[sh][0];
        *(float4*)&e0[(size_t)s * 4] = make_float4(fs, fs, fs, fs);
        *(float4*)&e1[(size_t)s * 4] = make_float4(kn.x + boff, kn.y + boff, kn.z + boff, kn.w + boff);
    }
}

// ---------------------------------------------------------------------------
extern "C" void kernel_launch(void* const* d_in, const int* in_sizes, int n_in,
                              void* d_out, int out_size) {
    const float* x   = (const float*)d_in[0];
    const int*   hub = (const int*)d_in[1];
    const int*   bix = (const int*)d_in[2];
    const float* W1  = (const float*)d_in[3];
    const float* b1  = (const float*)d_in[4];
    const float* W2  = (const float*)d_in[5];
    const float* b2  = (const float*)d_in[6];

    float* out  = (float*)d_out;
    float* hubf = out;
    float* e0   = out + HUBF_ELEMS;
    float* e1   = out + HUBF_ELEMS + NK;

    cudaFuncSetAttribute(ffn_mma, cudaFuncAttributeMaxDynamicSharedMemorySize, FFN_SMEM);

    prep_weights<<<64, 256>>>(W1, W2);        // idx 0
    nudge_kernel<<<1, 32>>>();                // idx 1
    nudge_kernel<<<1, 32>>>();                // idx 2
    ffn_mma<<<FFN_GRID, 512, FFN_SMEM>>>(x, b1, b2);   // idx 3 <- ncu
    scatter_gather<<<BG * SPLITS, 256>>>(hub, bix, hubf);
    knn_edge_kernel<<<BG, 256>>>(hub, bix, hubf, e0, e1);
}

// round 14
// speedup vs baseline: 6.2587x; 1.0827x over previous
#include <cuda_runtime.h>
#include <cuda_fp16.h>
#include <cstdint>

#define NS   524288
#define DIM  128
#define BG   128
#define HH   64
#define KK_  4
#define BH   (BG * HH)
#define NK   (NS * KK_)
#define HUBF_ELEMS (BH * DIM)

#define TILES_PER_HALF 2
#define FFN_GRID (NS / 256)     /* 2048 */

// FFN output scratch (fp16)
__device__ __half g_hbufh[(size_t)NS * DIM];

// Prepped fp16 weights, transposed [n][k], XOR-swizzled
__device__ __half gW1[256 * 128];
__device__ __half gW2[128 * 256];

// SMEM layout (ffn): 224KB
#define OFF_W1  0
#define OFF_W2  65536
#define OFF_X   131072     /* per-half: +half*16384 */
#define OFF_H1  163840     /* per-half: +half*32768 */
#define FFN_SMEM 229376

// ---------------------------------------------------------------------------
__device__ __forceinline__ uint32_t smem_u32(const void* p) {
    uint32_t a;
    asm("{ .reg .u64 t; cvta.to.shared.u64 t, %1; cvt.u32.u64 %0, t; }" : "=r"(a) : "l"(p));
    return a;
}
__device__ __forceinline__ void ldsm4(uint32_t addr, uint32_t r[4]) {
    asm volatile("ldmatrix.sync.aligned.m8n8.x4.shared.b16 {%0,%1,%2,%3}, [%4];"
                 : "=r"(r[0]), "=r"(r[1]), "=r"(r[2]), "=r"(r[3]) : "r"(addr));
}
__device__ __forceinline__ void mma16816(float c[4], const uint32_t a[4], uint32_t b0, uint32_t b1) {
    asm volatile("mma.sync.aligned.m16n8k16.row.col.f32.f16.f16.f32 "
                 "{%0,%1,%2,%3}, {%4,%5,%6,%7}, {%8,%9}, {%0,%1,%2,%3};"
                 : "+f"(c[0]), "+f"(c[1]), "+f"(c[2]), "+f"(c[3])
                 : "r"(a[0]), "r"(a[1]), "r"(a[2]), "r"(a[3]), "r"(b0), "r"(b1));
}
__device__ __forceinline__ uint32_t a_addr(uint32_t base, int stride, int m0, int kb, int lane) {
    int row = m0 + (lane & 15);
    int k = kb + ((lane >> 4) << 4);
    return base + row * stride + (uint32_t)(k ^ ((row & 7) << 4));
}
__device__ __forceinline__ uint32_t b_addr(uint32_t base, int stride, int n0, int kb, int lane) {
    int row = n0 + (lane & 7) + ((lane & 16) >> 1);
    int k = kb + (((lane >> 3) & 1) << 4);
    return base + row * stride + (uint32_t)(k ^ ((row & 7) << 4));
}
__device__ __forceinline__ float gelu_fast(float v) {
    float c = v * fmaf(v * v, 0.044715f, 1.0f) * 0.7978845608f;
    float t;
    asm("tanh.approx.f32 %0, %1;" : "=f"(t) : "f"(c));
    return 0.5f * v * (1.0f + t);
}
__device__ __forceinline__ uint32_t pack_h2(__half a, __half b) {
    __half2 t; t.x = a; t.y = b;
    return *(uint32_t*)&t;
}
#define HBAR(id) asm volatile("bar.sync %0, 256;" :: "r"(id) : "memory")

// ---------------------------------------------------------------------------
// K0: weight prep
// ---------------------------------------------------------------------------
__global__ void prep_weights(const float* __restrict__ W1, const float* __restrict__ W2) {
    int tid = threadIdx.x + blockIdx.x * blockDim.x;
    int stride = blockDim.x * gridDim.x;
    for (int i = tid; i < 32768; i += stride) {
        int n = i >> 7, k = i & 127;
        uint32_t off = (uint32_t)(n * 256) + (uint32_t)((k * 2) ^ ((n & 7) << 4));
        *(__half*)((char*)gW1 + off) = __float2half_rn(W1[k * 256 + n]);
    }
    for (int i = tid; i < 32768; i += stride) {
        int n = i >> 8, k = i & 255;
        uint32_t off = (uint32_t)(n * 512) + (uint32_t)((k * 2) ^ ((n & 7) << 4));
        *(__half*)((char*)gW2 + off) = __float2half_rn(W2[k * 128 + n]);
    }
}

__global__ void nudge_kernel() {}

// ---------------------------------------------------------------------------
// K1: FFN, phase-shifted halves (frozen — 289us measured)
// ---------------------------------------------------------------------------
__global__ void __launch_bounds__(512)
ffn_mma(const float* __restrict__ x,
        const float* __restrict__ b1, const float* __restrict__ b2) {
    extern __shared__ char sm[];
    const uint32_t sb = smem_u32(sm);
    const int tid = threadIdx.x;
    const int wid = tid >> 5;
    const int lane = tid & 31;
    const int half = wid >> 3;
    const int tid_h = tid & 255;
    const int hw = wid & 7;
    const int wm = hw & 1;
    const int wn = hw >> 1;

    const uint32_t offX  = OFF_X  + (uint32_t)half * 16384;
    const uint32_t offH1 = OFF_H1 + (uint32_t)half * 32768;
    const int bar = 1 + half;

    {
        const uint4* s1 = (const uint4*)gW1;
        const uint4* s2 = (const uint4*)gW2;
        uint4* d1 = (uint4*)(sm + OFF_W1);
        uint4* d2 = (uint4*)(sm + OFF_W2);
#pragma unroll 4
        for (int i = tid; i < 4096; i += 512) { d1[i] = s1[i]; d2[i] = s2[i]; }
    }
    __syncthreads();

    for (int t = 0; t < TILES_PER_HALF; t++) {
        const size_t rowbase =
            (size_t)(blockIdx.x * (2 * TILES_PER_HALF) + half * TILES_PER_HALF + t) * 64;

        {
            const float4* xg = (const float4*)(x + rowbase * DIM);
#pragma unroll
            for (int ii = 0; ii < 8; ii++) {
                int i = tid_h + ii * 256;
                float4 v = xg[i];
                int row = i >> 5, k = (i & 31) * 4;
                uint32_t off = (uint32_t)((k * 2) ^ ((row & 7) << 4)) + row * 256;
                *(uint2*)(sm + offX + off) =
                    make_uint2(pack_h2(__float2half_rn(v.x), __float2half_rn(v.y)),
                               pack_h2(__float2half_rn(v.z), __float2half_rn(v.w)));
            }
        }
        HBAR(bar);

        float acc[2][8][4];
#pragma unroll
        for (int a = 0; a < 2; a++)
#pragma unroll
            for (int b = 0; b < 8; b++)
#pragma unroll
                for (int c = 0; c < 4; c++) acc[a][b][c] = 0.f;

#pragma unroll
        for (int ks = 0; ks < 8; ks++) {
            const int kb = ks * 32;
            uint32_t aw[2][4];
#pragma unroll
            for (int mt = 0; mt < 2; mt++)
                ldsm4(a_addr(sb + offX, 256, wm * 32 + mt * 16, kb, lane), aw[mt]);
#pragma unroll
            for (int ntp = 0; ntp < 4; ntp++) {
                const int n0 = wn * 64 + ntp * 16;
                uint32_t bw[4];
                ldsm4(b_addr(sb + OFF_W1, 256, n0, kb, lane), bw);
#pragma unroll
                for (int mt = 0; mt < 2; mt++) {
                    mma16816(acc[mt][ntp * 2],     aw[mt], bw[0], bw[1]);
                    mma16816(acc[mt][ntp * 2 + 1], aw[mt], bw[2], bw[3]);
                }
            }
        }

#pragma unroll
        for (int nt = 0; nt < 8; nt++) {
            const int col = wn * 64 + nt * 8 + (lane & 3) * 2;
            const float2 bb = *(const float2*)&b1[col];
#pragma unroll
            for (int mt = 0; mt < 2; mt++) {
                const int r = wm * 32 + mt * 16 + (lane >> 2);
#pragma unroll
                for (int h = 0; h < 2; h++) {
                    const int rr = r + h * 8;
                    float v0 = gelu_fast(acc[mt][nt][h * 2]     + bb.x);
                    float v1 = gelu_fast(acc[mt][nt][h * 2 + 1] + bb.y);
                    uint32_t off = rr * 512 + (uint32_t)((col * 2) ^ ((rr & 7) << 4));
                    *(uint32_t*)(sm + offH1 + off) =
                        pack_h2(__float2half_rn(v0), __float2half_rn(v1));
                }
            }
        }
        HBAR(bar);

        float acc2[2][4][4];
#pragma unroll
        for (int a = 0; a < 2; a++)
#pragma unroll
            for (int b = 0; b < 4; b++)
#pragma unroll
                for (int c = 0; c < 4; c++) acc2[a][b][c] = 0.f;

#pragma unroll
        for (int ks = 0; ks < 16; ks++) {
            const int kb = ks * 32;
            uint32_t aw[2][4];
#pragma unroll
            for (int mt = 0; mt < 2; mt++)
                ldsm4(a_addr(sb + offH1, 512, wm * 32 + mt * 16, kb, lane), aw[mt]);
#pragma unroll
            for (int ntp = 0; ntp < 2; ntp++) {
                const int n0 = wn * 32 + ntp * 16;
                uint32_t bw[4];
                ldsm4(b_addr(sb + OFF_W2, 512, n0, kb, lane), bw);
#pragma unroll
                for (int mt = 0; mt < 2; mt++) {
                    mma16816(acc2[mt][ntp * 2],     aw[mt], bw[0], bw[1]);
                    mma16816(acc2[mt][ntp * 2 + 1], aw[mt], bw[2], bw[3]);
                }
            }
        }

#pragma unroll
        for (int nt = 0; nt < 4; nt++) {
            const int col = wn * 32 + nt * 8 + (lane & 3) * 2;
            const float2 bb = *(const float2*)&b2[col];
#pragma unroll
            for (int mt = 0; mt < 2; mt++) {
                const int r = wm * 32 + mt * 16 + (lane >> 2);
#pragma unroll
                for (int h = 0; h < 2; h++) {
                    const int rr = r + h * 8;
                    *(uint32_t*)&g_hbufh[(rowbase + rr) * DIM + col] =
                        pack_h2(__float2half_rn(acc2[mt][nt][h * 2] + bb.x),
                                __float2half_rn(acc2[mt][nt][h * 2 + 1] + bb.y));
                }
            }
        }
        HBAR(bar);
    }
}

// ---------------------------------------------------------------------------
// K2: scatter-mean v4. Gather: all 4 hubs concurrent, half2 loads, MLP 8.
// ---------------------------------------------------------------------------
#define SPLITS 16
#define WLMAX  96
#define CLMAX  768

__global__ void __launch_bounds__(256)
scatter_gather(const int* __restrict__ hub_idx,
               const int* __restrict__ batch_idx,
               float* __restrict__ hubf_out) {
    __shared__ int wlist[8][4][WLMAX];
    __shared__ int wcnt[8][4];
    __shared__ int clist[4][CLMAX];
    __shared__ int ccnt[4];
    __shared__ int coff[8][4];
    __shared__ int srange[2];

    const int b = blockIdx.x >> 4;
    const int p = blockIdx.x & 15;
    const int h0 = p * 4;
    const int tid = threadIdx.x;
    const int w = tid >> 5;
    const int lane = tid & 31;

    if (lane < 4) wcnt[w][lane] = 0;
    if (tid < 2) {
        int target = b + tid, lo = 0, hi = NS;
        while (lo < hi) { int mid = (lo + hi) >> 1; if (batch_idx[mid] < target) lo = mid + 1; else hi = mid; }
        srange[tid] = lo;
    }
    __syncthreads();

    const int s0 = srange[0];
    const int n = srange[1] - s0;
    const int chunk = (n + 7) >> 3;
    const int cs = s0 + w * chunk;
    const int ce = min(cs + chunk, s0 + n);

    // phase 1: per-warp parallel list build (preserves in-chunk order)
    const unsigned lt = (1u << lane) - 1u;
    for (int base = cs; base < ce; base += 32) {
        int i = base + lane;
        int h = (i < ce) ? __ldg(&hub_idx[i]) : -1;
        int hl = h - h0;
        bool in = (hl >= 0) && (hl < 4);
        unsigned mm = __match_any_sync(0xffffffffu, h);
        if (in) {
            int rank = __popc(mm & lt);
            int cnt = __popc(mm);
            int basec = wcnt[w][hl];
            wlist[w][hl][basec + rank] = i;
            if (rank == cnt - 1) wcnt[w][hl] = basec + cnt;
        }
        __syncwarp();
    }
    __syncthreads();

    // phase 2a: prefix offsets
    if (tid < 4) {
        int run = 0;
#pragma unroll
        for (int ww = 0; ww < 8; ww++) { coff[ww][tid] = run; run += wcnt[ww][tid]; }
        ccnt[tid] = run;
    }
    __syncthreads();

    // phase 2b: compact
#pragma unroll
    for (int hl = 0; hl < 4; hl++) {
        int c = wcnt[w][hl], o = coff[w][hl];
        for (int j = lane; j < c; j += 32) clist[hl][o + j] = wlist[w][hl][j];
    }
    __syncthreads();

    // phase 3: gather — thread = (hub, dim-pair): 4 hubs concurrent, half2 loads
    {
        const int hl = tid >> 6;           // 0..3 (warp-uniform)
        const int dd = (tid & 63) * 2;     // dim pair
        const int cnt = ccnt[hl];
        const int* lst = clist[hl];
        float sx = 0.f, sy = 0.f;
        int j = 0;
        for (; j + 8 <= cnt; j += 8) {
            __half2 v0 = *(const __half2*)&g_hbufh[(size_t)lst[j]     * DIM + dd];
            __half2 v1 = *(const __half2*)&g_hbufh[(size_t)lst[j + 1] * DIM + dd];
            __half2 v2 = *(const __half2*)&g_hbufh[(size_t)lst[j + 2] * DIM + dd];
            __half2 v3 = *(const __half2*)&g_hbufh[(size_t)lst[j + 3] * DIM + dd];
            __half2 v4 = *(const __half2*)&g_hbufh[(size_t)lst[j + 4] * DIM + dd];
            __half2 v5 = *(const __half2*)&g_hbufh[(size_t)lst[j + 5] * DIM + dd];
            __half2 v6 = *(const __half2*)&g_hbufh[(size_t)lst[j + 6] * DIM + dd];
            __half2 v7 = *(const __half2*)&g_hbufh[(size_t)lst[j + 7] * DIM + dd];
            float2 f0 = __half22float2(v0), f1 = __half22float2(v1);
            float2 f2 = __half22float2(v2), f3 = __half22float2(v3);
            float2 f4 = __half22float2(v4), f5 = __half22float2(v5);
            float2 f6 = __half22float2(v6), f7 = __half22float2(v7);
            sx += f0.x; sy += f0.y; sx += f1.x; sy += f1.y;
            sx += f2.x; sy += f2.y; sx += f3.x; sy += f3.y;
            sx += f4.x; sy += f4.y; sx += f5.x; sy += f5.y;
            sx += f6.x; sy += f6.y; sx += f7.x; sy += f7.y;
        }
        for (; j < cnt; j++) {
            float2 f = __half22float2(*(const __half2*)&g_hbufh[(size_t)lst[j] * DIM + dd]);
            sx += f.x; sy += f.y;
        }
        const float inv = 1.0f / (float)max(cnt, 1);
        *(float2*)&hubf_out[((size_t)b * HH + h0 + hl) * DIM + dd] =
            make_float2(sx * inv, sy * inv);
    }
}

// ---------------------------------------------------------------------------
// K3: per-graph 64x64 kNN + fused edge emission (256 threads)
// ---------------------------------------------------------------------------
__global__ void __launch_bounds__(256)
knn_edge_kernel(const int* __restrict__ hub_idx,
                const int* __restrict__ batch_idx,
                const float* __restrict__ hubf,
                float* __restrict__ e0, float* __restrict__ e1) {
    __shared__ float hf[HH][DIM + 1];
    __shared__ float d2row[8][HH];
    __shared__ int sknn[HH][KK_];
    __shared__ int srange[2];

    const int b = blockIdx.x;
    const int tid = threadIdx.x;
    const int warp = tid >> 5, lane = tid & 31;

    for (int i = tid; i < HH * DIM; i += 256) {
        int h = i >> 7, d = i & 127;
        hf[h][d] = hubf[((size_t)b * HH + h) * DIM + d];
    }
    if (tid < 2) {
        int target = b + tid, lo = 0, hi = NS;
        while (lo < hi) { int mid = (lo + hi) >> 1; if (batch_idx[mid] < target) lo = mid + 1; else hi = mid; }
        srange[tid] = lo;
    }
    __syncthreads();

    for (int i = warp; i < HH; i += 8) {
        for (int jj = 0; jj < HH; jj += 32) {
            int j = jj + lane;
            float s = 0.f;
#pragma unroll
            for (int d = 0; d < DIM; d++) {
                float diff = hf[i][d] - hf[j][d];
                s = fmaf(diff, diff, s);
            }
            d2row[warp][j] = s;
        }
        float v0 = d2row[warp][lane], v1 = d2row[warp][lane + 32];
        int   i0 = lane,              i1 = lane + 32;
#pragma unroll
        for (int k = 0; k < KK_; k++) {
            float bv; int bi;
            if (v0 < v1 || (v0 == v1 && i0 < i1)) { bv = v0; bi = i0; }
            else                                   { bv = v1; bi = i1; }
#pragma unroll
            for (int off = 16; off; off >>= 1) {
                float ov = __shfl_xor_sync(0xffffffffu, bv, off);
                int   oi = __shfl_xor_sync(0xffffffffu, bi, off);
                if (ov < bv || (ov == bv && oi < bi)) { bv = ov; bi = oi; }
            }
            if (lane == 0) sknn[i][k] = bi;
            if (i0 == bi) v0 = 3.4e38f;
            if (i1 == bi) v1 = 3.4e38f;
        }
    }
    __syncthreads();

    const int s0 = srange[0], s1 = srange[1];
    const float boff = (float)(b * HH);
    for (int s = s0 + tid; s < s1; s += 256) {
        const int sh = hub_idx[s];
        const float fs = (float)s;
        const int4 kn = *(const int4*)&sknn[sh][0];
        *(float4*)&e0[(size_t)s * 4] = make_float4(fs, fs, fs, fs);
        *(float4*)&e1[(size_t)s * 4] = make_float4(kn.x + boff, kn.y + boff, kn.z + boff, kn.w + boff);
    }
}

// ---------------------------------------------------------------------------
extern "C" void kernel_launch(void* const* d_in, const int* in_sizes, int n_in,
                              void* d_out, int out_size) {
    const float* x   = (const float*)d_in[0];
    const int*   hub = (const int*)d_in[1];
    const int*   bix = (const int*)d_in[2];
    const float* W1  = (const float*)d_in[3];
    const float* b1  = (const float*)d_in[4];
    const float* W2  = (const float*)d_in[5];
    const float* b2  = (const float*)d_in[6];

    float* out  = (float*)d_out;
    float* hubf = out;
    float* e0   = out + HUBF_ELEMS;
    float* e1   = out + HUBF_ELEMS + NK;

    cudaFuncSetAttribute(ffn_mma, cudaFuncAttributeMaxDynamicSharedMemorySize, FFN_SMEM);

    prep_weights<<<64, 256>>>(W1, W2);                 // idx 0
    nudge_kernel<<<1, 32>>>();                          // idx 1
    ffn_mma<<<FFN_GRID, 512, FFN_SMEM>>>(x, b1, b2);   // idx 2
    scatter_gather<<<BG * SPLITS, 256>>>(hub, bix, hubf);  // idx 3 <- ncu
    knn_edge_kernel<<<BG, 256>>>(hub, bix, hubf, e0, e1);
}